// round 1
// baseline (speedup 1.0000x reference)
#include <cuda_runtime.h>
#include <cuda_bf16.h>
#include <math.h>

// Problem constants
#define B_  2
#define N_  2048
#define C_  1024
#define H_  16
#define D_  64
#define M_  (B_ * N_)        // 4096
#define K3_ (3 * C_)         // 3072

// ---------------------------------------------------------------------------
// Scratch (device globals; no dynamic allocation allowed)
// ---------------------------------------------------------------------------
__device__ float g_q[B_ * H_ * N_ * D_];     // [B,H,N,D]
__device__ float g_k[B_ * H_ * N_ * D_];
__device__ float g_v[B_ * H_ * N_ * D_];
__device__ float g_attn[B_ * N_ * C_];       // [B,N,C] attention output

// ---------------------------------------------------------------------------
// Kernel 1: QKV GEMM.  out[m][j] = x[m,:] . qkv_w[j,:] + qkv_b[j]
// x: [M, 1024] row-major, qkv_w: [3072, 1024] row-major.
// Epilogue scatters into g_q/g_k/g_v in [B,H,N,D] layout.
// Tiling: 128x128x16, 256 threads, 8x8 per thread.
// ---------------------------------------------------------------------------
__global__ __launch_bounds__(256) void gemm_qkv(const float* __restrict__ X,
                                                const float* __restrict__ W,
                                                const float* __restrict__ bias)
{
    __shared__ float As[16][132];
    __shared__ float Bs[16][132];

    const int tid = threadIdx.x;
    const int tx = tid & 15;
    const int ty = tid >> 4;
    const int row0 = blockIdx.y * 128;
    const int col0 = blockIdx.x * 128;

    const float* Ap = X + (size_t)row0 * 1024;
    const float* Bp = W + (size_t)col0 * 1024;

    float acc[8][8];
#pragma unroll
    for (int r = 0; r < 8; r++)
#pragma unroll
        for (int c = 0; c < 8; c++) acc[r][c] = 0.0f;

    for (int k0 = 0; k0 < 1024; k0 += 16) {
#pragma unroll
        for (int i = 0; i < 2; i++) {
            int lin = tid + i * 256;          // 0..511 float4 slots
            int r = lin >> 2;                 // row within tile (0..127)
            int c = (lin & 3) << 2;           // k offset (0,4,8,12)
            float4 a = *reinterpret_cast<const float4*>(Ap + (size_t)r * 1024 + k0 + c);
            As[c + 0][r] = a.x; As[c + 1][r] = a.y; As[c + 2][r] = a.z; As[c + 3][r] = a.w;
            float4 b = *reinterpret_cast<const float4*>(Bp + (size_t)r * 1024 + k0 + c);
            Bs[c + 0][r] = b.x; Bs[c + 1][r] = b.y; Bs[c + 2][r] = b.z; Bs[c + 3][r] = b.w;
        }
        __syncthreads();
#pragma unroll
        for (int kk = 0; kk < 16; kk++) {
            float a[8], b[8];
            *reinterpret_cast<float4*>(&a[0]) = *reinterpret_cast<const float4*>(&As[kk][ty * 8]);
            *reinterpret_cast<float4*>(&a[4]) = *reinterpret_cast<const float4*>(&As[kk][ty * 8 + 4]);
            *reinterpret_cast<float4*>(&b[0]) = *reinterpret_cast<const float4*>(&Bs[kk][tx * 8]);
            *reinterpret_cast<float4*>(&b[4]) = *reinterpret_cast<const float4*>(&Bs[kk][tx * 8 + 4]);
#pragma unroll
            for (int r = 0; r < 8; r++)
#pragma unroll
                for (int c = 0; c < 8; c++)
                    acc[r][c] = fmaf(a[r], b[c], acc[r][c]);
        }
        __syncthreads();
    }

    // Epilogue: scatter into q/k/v [B,H,N,D]
#pragma unroll
    for (int r = 0; r < 8; r++) {
        int m = row0 + ty * 8 + r;
        int b = m >> 11;          // / 2048
        int n = m & 2047;
#pragma unroll
        for (int c = 0; c < 8; c++) {
            int j = col0 + tx * 8 + c;
            float v = acc[r][c] + bias[j];
            int p = j >> 10;                // 0=q, 1=k, 2=v
            int h = (j >> 6) & 15;
            int d = j & 63;
            float* dst = (p == 0) ? g_q : ((p == 1) ? g_k : g_v);
            dst[(((size_t)(b * 16 + h)) * 2048 + n) * 64 + d] = v;
        }
    }
}

// ---------------------------------------------------------------------------
// Kernel 2: RMSNorm + segmented RoPE, in place on g_q or g_k ([B,H,N,D]).
// One warp per (b,h,n) row of D=64; lane holds elems {lane, lane+32} which is
// exactly the RoPE rotate pair.
// ---------------------------------------------------------------------------
__global__ __launch_bounds__(256) void norm_rope(const float* __restrict__ w, int which)
{
    float* t = which ? g_k : g_q;
    const int gtid = blockIdx.x * blockDim.x + threadIdx.x;
    const int row = gtid >> 5;
    const int lane = threadIdx.x & 31;
    if (row >= B_ * H_ * N_) return;

    const int n = row & 2047;
    const size_t base = (size_t)row * 64;

    float x0 = t[base + lane];
    float x1 = t[base + lane + 32];
    float ss = x0 * x0 + x1 * x1;
#pragma unroll
    for (int m = 16; m >= 1; m >>= 1)
        ss += __shfl_xor_sync(0xffffffffu, ss, m);
    float rs = rsqrtf(ss * (1.0f / 64.0f) + 1e-6f);
    float y0 = x0 * rs * w[lane];
    float y1 = x1 * rs * w[lane + 32];

    // segmented RoPE: [0,1024) pos=n; [1024,1536) pos=n-1024; else identity
    int pos = (n < 1024) ? n : ((n < 1536) ? (n - 1024) : -1);
    if (pos >= 0) {
        // inv_freq = 10000 ^ (-(2*lane)/64)
        float e = (float)(2 * lane) * (1.0f / 64.0f);
        float inv = expf(-9.210340371976184f * e);   // ln(10000)
        float ang = (float)pos * inv;
        float cs = cosf(ang), sn = sinf(ang);
        float o0 = y0 * cs - y1 * sn;
        float o1 = y1 * cs + y0 * sn;
        y0 = o0; y1 = o1;
    }
    t[base + lane] = y0;
    t[base + lane + 32] = y1;
}

// ---------------------------------------------------------------------------
// Kernel 3: flash attention (fp32, streaming softmax).
// Block = 64 queries of one (b,h); 256 threads, thread computes 4x4 of the
// 64x64 score tile and 4x4 of the 64x64 output tile.
// smem: Qs[d][i], Ks[d][j] (transposed, stride 68), Vs[kc][d], Ps[i][kc].
// ---------------------------------------------------------------------------
#define AST 68   // smem stride (mult of 4 for float4 alignment)

__global__ __launch_bounds__(256) void attn_kernel()
{
    extern __shared__ float sm[];
    float* Qs = sm;                 // [64][AST]  Qs[d][i]
    float* Ks = sm + 64 * AST;      // [64][AST]  Ks[d][j]
    float* Vs = sm + 2 * 64 * AST;  // [64][AST]  Vs[kc][d]
    float* Ps = sm + 3 * 64 * AST;  // [64][AST]  Ps[i][kc]

    const int tid = threadIdx.x;
    const int tx = tid & 15;
    const int ty = tid >> 4;
    const int q0 = blockIdx.x * 64;
    const int h = blockIdx.y;
    const int b = blockIdx.z;
    const size_t headbase = ((size_t)(b * 16 + h)) * (2048 * 64);

    // Load Q tile transposed, pre-scaled by 1/sqrt(D)=0.125
    {
        const float* qp = g_q + headbase + (size_t)q0 * 64;
#pragma unroll
        for (int i = 0; i < 4; i++) {
            int lin = tid + i * 256;
            int r = lin >> 4;
            int c = (lin & 15) << 2;
            float4 v = *reinterpret_cast<const float4*>(qp + (size_t)r * 64 + c);
            Qs[(c + 0) * AST + r] = v.x * 0.125f;
            Qs[(c + 1) * AST + r] = v.y * 0.125f;
            Qs[(c + 2) * AST + r] = v.z * 0.125f;
            Qs[(c + 3) * AST + r] = v.w * 0.125f;
        }
    }

    float m_i[4], l_i[4], o[4][4];
#pragma unroll
    for (int r = 0; r < 4; r++) {
        m_i[r] = -1e30f; l_i[r] = 0.0f;
#pragma unroll
        for (int c = 0; c < 4; c++) o[r][c] = 0.0f;
    }

    for (int kt = 0; kt < 32; kt++) {
        const float* kp = g_k + headbase + (size_t)kt * (64 * 64);
        const float* vp = g_v + headbase + (size_t)kt * (64 * 64);
        __syncthreads();   // previous iter's Vs/Ps reads done before overwrite
#pragma unroll
        for (int i = 0; i < 4; i++) {
            int lin = tid + i * 256;
            int r = lin >> 4;
            int c = (lin & 15) << 2;
            float4 kv = *reinterpret_cast<const float4*>(kp + (size_t)r * 64 + c);
            Ks[(c + 0) * AST + r] = kv.x; Ks[(c + 1) * AST + r] = kv.y;
            Ks[(c + 2) * AST + r] = kv.z; Ks[(c + 3) * AST + r] = kv.w;
            float4 vv = *reinterpret_cast<const float4*>(vp + (size_t)r * 64 + c);
            *reinterpret_cast<float4*>(&Vs[r * AST + c]) = vv;
        }
        __syncthreads();

        // ---- S = Q K^T (pre-scaled) ----
        float s[4][4];
#pragma unroll
        for (int r = 0; r < 4; r++)
#pragma unroll
            for (int c = 0; c < 4; c++) s[r][c] = 0.0f;
#pragma unroll
        for (int d = 0; d < 64; d++) {
            float4 af = *reinterpret_cast<const float4*>(&Qs[d * AST + ty * 4]);
            float4 bf = *reinterpret_cast<const float4*>(&Ks[d * AST + tx * 4]);
            float a[4] = {af.x, af.y, af.z, af.w};
            float bb[4] = {bf.x, bf.y, bf.z, bf.w};
#pragma unroll
            for (int r = 0; r < 4; r++)
#pragma unroll
                for (int c = 0; c < 4; c++)
                    s[r][c] = fmaf(a[r], bb[c], s[r][c]);
        }

        // ---- online softmax update ----
#pragma unroll
        for (int r = 0; r < 4; r++) {
            float mv = fmaxf(fmaxf(s[r][0], s[r][1]), fmaxf(s[r][2], s[r][3]));
            mv = fmaxf(mv, __shfl_xor_sync(0xffffffffu, mv, 1));
            mv = fmaxf(mv, __shfl_xor_sync(0xffffffffu, mv, 2));
            mv = fmaxf(mv, __shfl_xor_sync(0xffffffffu, mv, 4));
            mv = fmaxf(mv, __shfl_xor_sync(0xffffffffu, mv, 8));
            float mn = fmaxf(m_i[r], mv);
            float alpha = __expf(m_i[r] - mn);
            m_i[r] = mn;
            float p0 = __expf(s[r][0] - mn);
            float p1 = __expf(s[r][1] - mn);
            float p2 = __expf(s[r][2] - mn);
            float p3 = __expf(s[r][3] - mn);
            float rsum = p0 + p1 + p2 + p3;
            rsum += __shfl_xor_sync(0xffffffffu, rsum, 1);
            rsum += __shfl_xor_sync(0xffffffffu, rsum, 2);
            rsum += __shfl_xor_sync(0xffffffffu, rsum, 4);
            rsum += __shfl_xor_sync(0xffffffffu, rsum, 8);
            l_i[r] = l_i[r] * alpha + rsum;
#pragma unroll
            for (int c = 0; c < 4; c++) o[r][c] *= alpha;
            float4 pv = make_float4(p0, p1, p2, p3);
            *reinterpret_cast<float4*>(&Ps[(ty * 4 + r) * AST + tx * 4]) = pv;
        }
        __syncthreads();

        // ---- O += P V ----
#pragma unroll
        for (int kc = 0; kc < 64; kc++) {
            float4 bf = *reinterpret_cast<const float4*>(&Vs[kc * AST + tx * 4]);
            float bb[4] = {bf.x, bf.y, bf.z, bf.w};
            float a0 = Ps[(ty * 4 + 0) * AST + kc];
            float a1 = Ps[(ty * 4 + 1) * AST + kc];
            float a2 = Ps[(ty * 4 + 2) * AST + kc];
            float a3 = Ps[(ty * 4 + 3) * AST + kc];
#pragma unroll
            for (int c = 0; c < 4; c++) {
                o[0][c] = fmaf(a0, bb[c], o[0][c]);
                o[1][c] = fmaf(a1, bb[c], o[1][c]);
                o[2][c] = fmaf(a2, bb[c], o[2][c]);
                o[3][c] = fmaf(a3, bb[c], o[3][c]);
            }
        }
    }

    // Epilogue: write [B,N,C] = [b][n][h*64 + d]
#pragma unroll
    for (int r = 0; r < 4; r++) {
        float inv = 1.0f / l_i[r];
        int n = q0 + ty * 4 + r;
        float4 ov = make_float4(o[r][0] * inv, o[r][1] * inv, o[r][2] * inv, o[r][3] * inv);
        *reinterpret_cast<float4*>(&g_attn[((size_t)b * 2048 + n) * 1024 + h * 64 + tx * 4]) = ov;
    }
}

// ---------------------------------------------------------------------------
// Kernel 4: output projection.  out[m][j] = attn[m,:] . proj_w[j,:] + proj_b[j]
// ---------------------------------------------------------------------------
__global__ __launch_bounds__(256) void gemm_proj(const float* __restrict__ W,
                                                 const float* __restrict__ bias,
                                                 float* __restrict__ out)
{
    __shared__ float As[16][132];
    __shared__ float Bs[16][132];

    const int tid = threadIdx.x;
    const int tx = tid & 15;
    const int ty = tid >> 4;
    const int row0 = blockIdx.y * 128;
    const int col0 = blockIdx.x * 128;

    const float* Ap = g_attn + (size_t)row0 * 1024;
    const float* Bp = W + (size_t)col0 * 1024;

    float acc[8][8];
#pragma unroll
    for (int r = 0; r < 8; r++)
#pragma unroll
        for (int c = 0; c < 8; c++) acc[r][c] = 0.0f;

    for (int k0 = 0; k0 < 1024; k0 += 16) {
#pragma unroll
        for (int i = 0; i < 2; i++) {
            int lin = tid + i * 256;
            int r = lin >> 2;
            int c = (lin & 3) << 2;
            float4 a = *reinterpret_cast<const float4*>(Ap + (size_t)r * 1024 + k0 + c);
            As[c + 0][r] = a.x; As[c + 1][r] = a.y; As[c + 2][r] = a.z; As[c + 3][r] = a.w;
            float4 b = *reinterpret_cast<const float4*>(Bp + (size_t)r * 1024 + k0 + c);
            Bs[c + 0][r] = b.x; Bs[c + 1][r] = b.y; Bs[c + 2][r] = b.z; Bs[c + 3][r] = b.w;
        }
        __syncthreads();
#pragma unroll
        for (int kk = 0; kk < 16; kk++) {
            float a[8], b[8];
            *reinterpret_cast<float4*>(&a[0]) = *reinterpret_cast<const float4*>(&As[kk][ty * 8]);
            *reinterpret_cast<float4*>(&a[4]) = *reinterpret_cast<const float4*>(&As[kk][ty * 8 + 4]);
            *reinterpret_cast<float4*>(&b[0]) = *reinterpret_cast<const float4*>(&Bs[kk][tx * 8]);
            *reinterpret_cast<float4*>(&b[4]) = *reinterpret_cast<const float4*>(&Bs[kk][tx * 8 + 4]);
#pragma unroll
            for (int r = 0; r < 8; r++)
#pragma unroll
                for (int c = 0; c < 8; c++)
                    acc[r][c] = fmaf(a[r], b[c], acc[r][c]);
        }
        __syncthreads();
    }

#pragma unroll
    for (int r = 0; r < 8; r++) {
        int m = row0 + ty * 8 + r;
#pragma unroll
        for (int c = 0; c < 8; c++) {
            int j = col0 + tx * 8 + c;
            out[(size_t)m * 1024 + j] = acc[r][c] + bias[j];
        }
    }
}

// ---------------------------------------------------------------------------
// Launch
// ---------------------------------------------------------------------------
extern "C" void kernel_launch(void* const* d_in, const int* in_sizes, int n_in,
                              void* d_out, int out_size)
{
    const float* x      = (const float*)d_in[0];
    const float* qkv_w  = (const float*)d_in[1];
    const float* qkv_b  = (const float*)d_in[2];
    const float* qn_w   = (const float*)d_in[3];
    const float* kn_w   = (const float*)d_in[4];
    const float* proj_w = (const float*)d_in[5];
    const float* proj_b = (const float*)d_in[6];
    float* out = (float*)d_out;

    const int attn_smem = 4 * 64 * AST * sizeof(float);   // 69632 bytes
    cudaFuncSetAttribute(attn_kernel, cudaFuncAttributeMaxDynamicSharedMemorySize, attn_smem);

    // 1. QKV projection -> g_q/g_k/g_v [B,H,N,D]
    gemm_qkv<<<dim3(K3_ / 128, M_ / 128), 256>>>(x, qkv_w, qkv_b);

    // 2. RMSNorm + segmented RoPE (q and k, in place)
    const int rows = B_ * H_ * N_;                 // 65536 rows, 1 warp each
    norm_rope<<<rows / 8, 256>>>(qn_w, 0);
    norm_rope<<<rows / 8, 256>>>(kn_w, 1);

    // 3. Flash attention -> g_attn [B,N,C]
    attn_kernel<<<dim3(N_ / 64, H_, B_), 256, attn_smem>>>();

    // 4. Output projection -> d_out
    gemm_proj<<<dim3(C_ / 128, M_ / 128), 256>>>(proj_w, proj_b, out);
}

// round 3
// speedup vs baseline: 1.3147x; 1.3147x over previous
#include <cuda_runtime.h>
#include <cuda_bf16.h>
#include <cstdint>
#include <math.h>

// Problem constants
#define B_  2
#define N_  2048
#define C_  1024
#define H_  16
#define D_  64
#define M_  (B_ * N_)        // 4096
#define K3_ (3 * C_)         // 3072

// ---------------------------------------------------------------------------
// Scratch (device globals)
// ---------------------------------------------------------------------------
__device__ float g_qkv[M_ * K3_];        // [M, 3072]
__device__ float g_attn[M_ * C_];        // [B,N,C]
__device__ __nv_bfloat16 g_xhi[M_ * C_],  g_xlo[M_ * C_];
__device__ __nv_bfloat16 g_w1hi[K3_ * C_], g_w1lo[K3_ * C_];
__device__ __nv_bfloat16 g_w2hi[C_ * C_],  g_w2lo[C_ * C_];
__device__ __nv_bfloat16 g_ahi[M_ * C_],  g_alo[M_ * C_];
__device__ float g_cos[1024 * 32], g_sin[1024 * 32];

// ---------------------------------------------------------------------------
// Helpers
// ---------------------------------------------------------------------------
__device__ __forceinline__ uint32_t smem_u32(const void* p) {
    uint32_t a;
    asm("{ .reg .u64 t; cvta.to.shared.u64 t, %1; cvt.u32.u64 %0, t; }" : "=r"(a) : "l"(p));
    return a;
}
__device__ __forceinline__ void ldsm4(uint32_t* r, uint32_t addr) {
    asm volatile("ldmatrix.sync.aligned.m8n8.x4.shared.b16 {%0,%1,%2,%3}, [%4];"
                 : "=r"(r[0]), "=r"(r[1]), "=r"(r[2]), "=r"(r[3]) : "r"(addr));
}
__device__ __forceinline__ void mma16816(float* c, const uint32_t* a, uint32_t b0, uint32_t b1) {
    asm volatile("mma.sync.aligned.m16n8k16.row.col.f32.bf16.bf16.f32 "
                 "{%0,%1,%2,%3}, {%4,%5,%6,%7}, {%8,%9}, {%0,%1,%2,%3};"
                 : "+f"(c[0]), "+f"(c[1]), "+f"(c[2]), "+f"(c[3])
                 : "r"(a[0]), "r"(a[1]), "r"(a[2]), "r"(a[3]), "r"(b0), "r"(b1));
}

// Fast exp via deg-6 2^f Taylor (rel err ~1.5e-5) — keeps MUFU idle.
__device__ __forceinline__ float fexp(float x) {
    x = fmaxf(x, -80.0f);
    float t = x * 1.4426950408889634f;
    float fi = floorf(t);
    float f = t - fi;
    float p = fmaf(f, 1.5403530e-4f, 1.3333558e-3f);
    p = fmaf(p, f, 9.6181291e-3f);
    p = fmaf(p, f, 5.5504109e-2f);
    p = fmaf(p, f, 2.4022651e-1f);
    p = fmaf(p, f, 6.9314718e-1f);
    p = fmaf(p, f, 1.0f);
    int i = (int)fi;
    return p * __int_as_float((i + 127) << 23);
}

// ---------------------------------------------------------------------------
// Split fp32 -> bf16 hi + bf16 lo (residual)
// ---------------------------------------------------------------------------
__global__ __launch_bounds__(256) void split_bf16(const float4* __restrict__ src,
                                                  uint2* __restrict__ hi,
                                                  uint2* __restrict__ lo, int n4)
{
    int i = blockIdx.x * 256 + threadIdx.x;
    if (i >= n4) return;
    float4 v = src[i];
    __nv_bfloat16 h0 = __float2bfloat16_rn(v.x), h1 = __float2bfloat16_rn(v.y);
    __nv_bfloat16 h2 = __float2bfloat16_rn(v.z), h3 = __float2bfloat16_rn(v.w);
    __nv_bfloat16 l0 = __float2bfloat16_rn(v.x - __bfloat162float(h0));
    __nv_bfloat16 l1 = __float2bfloat16_rn(v.y - __bfloat162float(h1));
    __nv_bfloat16 l2 = __float2bfloat16_rn(v.z - __bfloat162float(h2));
    __nv_bfloat16 l3 = __float2bfloat16_rn(v.w - __bfloat162float(h3));
    uint2 hp, lp;
    hp.x = (uint32_t)__bfloat16_as_ushort(h0) | ((uint32_t)__bfloat16_as_ushort(h1) << 16);
    hp.y = (uint32_t)__bfloat16_as_ushort(h2) | ((uint32_t)__bfloat16_as_ushort(h3) << 16);
    lp.x = (uint32_t)__bfloat16_as_ushort(l0) | ((uint32_t)__bfloat16_as_ushort(l1) << 16);
    lp.y = (uint32_t)__bfloat16_as_ushort(l2) | ((uint32_t)__bfloat16_as_ushort(l3) << 16);
    hi[i] = hp;
    lo[i] = lp;
}

// ---------------------------------------------------------------------------
// RoPE tables (pos in [0,1024), 32 freq lanes)
// ---------------------------------------------------------------------------
__global__ __launch_bounds__(256) void rope_table()
{
    int idx = blockIdx.x * 256 + threadIdx.x;          // 32768
    int pos = idx >> 5, lane = idx & 31;
    float e = (float)(2 * lane) * (1.0f / 64.0f);
    float inv = expf(-9.210340371976184f * e);
    float ang = (float)pos * inv;
    g_cos[idx] = cosf(ang);
    g_sin[idx] = sinf(ang);
}

// ---------------------------------------------------------------------------
// bf16x3 compensated GEMM via mma.sync.
// out[m][j] = Ahi/lo[m,:] . Bhi/lo[j,:] + bias[j]; K=1024.
// Block 128x128, K-chunk 32, 8 warps (4x2), warp tile 32x64, cp.async 2-stage.
// ---------------------------------------------------------------------------
#define STAGE_B 40960   // 4 matrices * 128 rows * 40 bf16 * 2B

__global__ __launch_bounds__(256, 1) void gemm_mma(
    const __nv_bfloat16* __restrict__ Ahi, const __nv_bfloat16* __restrict__ Alo,
    const __nv_bfloat16* __restrict__ Bhi, const __nv_bfloat16* __restrict__ Blo,
    const float* __restrict__ bias, float* __restrict__ out, int ostride)
{
    extern __shared__ char sm[];
    const uint32_t sbase = smem_u32(sm);
    const int tid = threadIdx.x;
    const int lane = tid & 31;
    const int wid = tid >> 5;
    const int warp_m = wid >> 1;          // 0..3
    const int warp_n = wid & 1;           // 0..1
    const int row0 = blockIdx.y * 128;
    const int col0 = blockIdx.x * 128;

    float acc[2][8][4];
#pragma unroll
    for (int a = 0; a < 2; a++)
#pragma unroll
        for (int b = 0; b < 8; b++)
#pragma unroll
            for (int c = 0; c < 4; c++) acc[a][b][c] = 0.0f;

    const __nv_bfloat16* srcs[4] = {
        Ahi + (size_t)row0 * 1024, Alo + (size_t)row0 * 1024,
        Bhi + (size_t)col0 * 1024, Blo + (size_t)col0 * 1024 };

    // --- stage loader: 2048 16B chunks, 8 per thread ---
    auto load_stage = [&](int c, int buf) {
#pragma unroll
        for (int i = 0; i < 8; i++) {
            int lin = tid + i * 256;
            int mat = lin >> 9;
            int rem = lin & 511;
            int row = rem >> 2;
            int ch = rem & 3;
            const __nv_bfloat16* s = srcs[mat] + (size_t)row * 1024 + c * 32 + ch * 8;
            uint32_t d = sbase + buf * STAGE_B + mat * 10240 + (uint32_t)(row * 40 + ch * 8) * 2;
            asm volatile("cp.async.cg.shared.global [%0], [%1], 16;" :: "r"(d), "l"(s));
        }
        asm volatile("cp.async.commit_group;");
    };

    load_stage(0, 0);

    for (int c = 0; c < 32; c++) {
        const int buf = c & 1;
        if (c + 1 < 32) {
            load_stage(c + 1, buf ^ 1);
            asm volatile("cp.async.wait_group 1;");
        } else {
            asm volatile("cp.async.wait_group 0;");
        }
        __syncthreads();

        const uint32_t base = sbase + buf * STAGE_B;
#pragma unroll
        for (int kk = 0; kk < 2; kk++) {
            uint32_t ah[2][4], al[2][4], bh[4][4], bl[4][4];
            int arow = warp_m * 32 + (lane & 15);
            int acol = kk * 16 + (lane >> 4) * 8;
            uint32_t aoff = (uint32_t)(arow * 40 + acol) * 2;
            ldsm4(ah[0], base + aoff);
            ldsm4(ah[1], base + aoff + 1280);
            ldsm4(al[0], base + 10240 + aoff);
            ldsm4(al[1], base + 10240 + aoff + 1280);
            int g = lane >> 3, l7 = lane & 7;
#pragma unroll
            for (int p = 0; p < 4; p++) {
                int brow = warp_n * 64 + (p * 2 + (g >> 1)) * 8 + l7;
                int bcol = kk * 16 + (g & 1) * 8;
                uint32_t boff = (uint32_t)(brow * 40 + bcol) * 2;
                ldsm4(bh[p], base + 20480 + boff);
                ldsm4(bl[p], base + 30720 + boff);
            }
#pragma unroll
            for (int tm = 0; tm < 2; tm++)
#pragma unroll
                for (int tn = 0; tn < 8; tn++) {
                    uint32_t bh0 = bh[tn >> 1][(tn & 1) * 2], bh1 = bh[tn >> 1][(tn & 1) * 2 + 1];
                    uint32_t bl0 = bl[tn >> 1][(tn & 1) * 2], bl1 = bl[tn >> 1][(tn & 1) * 2 + 1];
                    mma16816(acc[tm][tn], ah[tm], bh0, bh1);
                    mma16816(acc[tm][tn], ah[tm], bl0, bl1);
                    mma16816(acc[tm][tn], al[tm], bh0, bh1);
                }
        }
        __syncthreads();
    }

    // --- epilogue ---
#pragma unroll
    for (int tm = 0; tm < 2; tm++) {
        int mb = row0 + warp_m * 32 + tm * 16 + (lane >> 2);
#pragma unroll
        for (int tn = 0; tn < 8; tn++) {
            int col = col0 + warp_n * 64 + tn * 8 + (lane & 3) * 2;
            float b0 = __ldg(&bias[col]), b1 = __ldg(&bias[col + 1]);
            *reinterpret_cast<float2*>(&out[(size_t)mb * ostride + col]) =
                make_float2(acc[tm][tn][0] + b0, acc[tm][tn][1] + b1);
            *reinterpret_cast<float2*>(&out[(size_t)(mb + 8) * ostride + col]) =
                make_float2(acc[tm][tn][2] + b0, acc[tm][tn][3] + b1);
        }
    }
}

// ---------------------------------------------------------------------------
// RMSNorm + segmented RoPE (table-driven), in place on g_qkv sections.
// ---------------------------------------------------------------------------
__global__ __launch_bounds__(256) void norm_rope(const float* __restrict__ wq,
                                                 const float* __restrict__ wk)
{
    const int which = blockIdx.y;
    const float* w = which ? wk : wq;
    const int gtid = blockIdx.x * blockDim.x + threadIdx.x;
    const int row = gtid >> 5;
    const int lane = threadIdx.x & 31;
    if (row >= B_ * H_ * N_) return;

    const int b = row >> 15;
    const int h = (row >> 11) & 15;
    const int n = row & 2047;
    float* t = g_qkv + ((size_t)(b * 2048 + n)) * 3072 + which * 1024 + h * 64;

    float x0 = t[lane];
    float x1 = t[lane + 32];
    float ss = x0 * x0 + x1 * x1;
#pragma unroll
    for (int m = 16; m >= 1; m >>= 1)
        ss += __shfl_xor_sync(0xffffffffu, ss, m);
    float rs;
    if (lane == 0) rs = rsqrtf(ss * (1.0f / 64.0f) + 1e-6f);
    rs = __shfl_sync(0xffffffffu, rs, 0);
    float y0 = x0 * rs * w[lane];
    float y1 = x1 * rs * w[lane + 32];

    int pos = (n < 1024) ? n : ((n < 1536) ? (n - 1024) : -1);
    if (pos >= 0) {
        float cs = g_cos[pos * 32 + lane];
        float sn = g_sin[pos * 32 + lane];
        float o0 = y0 * cs - y1 * sn;
        float o1 = y1 * cs + y0 * sn;
        y0 = o0; y1 = o1;
    }
    t[lane] = y0;
    t[lane + 32] = y1;
}

// ---------------------------------------------------------------------------
// Flash attention (fp32 SIMT, polynomial exp). Reads g_qkv [M,3072].
// ---------------------------------------------------------------------------
#define AST 68

__global__ __launch_bounds__(256) void attn_kernel()
{
    extern __shared__ float smf[];
    float* Qs = smf;                 // [64][AST]  Qs[d][i]
    float* Ks = smf + 64 * AST;      // [64][AST]  Ks[d][j]
    float* Vs = smf + 2 * 64 * AST;  // [64][AST]  Vs[kc][d]
    float* Ps = smf + 3 * 64 * AST;  // [64][AST]  Ps[i][kc]

    const int tid = threadIdx.x;
    const int tx = tid & 15;
    const int ty = tid >> 4;
    const int q0 = blockIdx.x * 64;
    const int h = blockIdx.y;
    const int b = blockIdx.z;

    const float* qbase = g_qkv + ((size_t)(b * 2048)) * 3072 + h * 64;

    {
        const float* qp = qbase + (size_t)q0 * 3072;
#pragma unroll
        for (int i = 0; i < 4; i++) {
            int lin = tid + i * 256;
            int r = lin >> 4;
            int c = (lin & 15) << 2;
            float4 v = *reinterpret_cast<const float4*>(qp + (size_t)r * 3072 + c);
            Qs[(c + 0) * AST + r] = v.x * 0.125f;
            Qs[(c + 1) * AST + r] = v.y * 0.125f;
            Qs[(c + 2) * AST + r] = v.z * 0.125f;
            Qs[(c + 3) * AST + r] = v.w * 0.125f;
        }
    }

    float m_i[4], l_i[4], o[4][4];
#pragma unroll
    for (int r = 0; r < 4; r++) {
        m_i[r] = -1e30f; l_i[r] = 0.0f;
#pragma unroll
        for (int c = 0; c < 4; c++) o[r][c] = 0.0f;
    }

    for (int kt = 0; kt < 32; kt++) {
        const float* kp = qbase + ((size_t)kt * 64) * 3072 + 1024;
        const float* vp = qbase + ((size_t)kt * 64) * 3072 + 2048;
        __syncthreads();
#pragma unroll
        for (int i = 0; i < 4; i++) {
            int lin = tid + i * 256;
            int r = lin >> 4;
            int c = (lin & 15) << 2;
            float4 kv = *reinterpret_cast<const float4*>(kp + (size_t)r * 3072 + c);
            Ks[(c + 0) * AST + r] = kv.x; Ks[(c + 1) * AST + r] = kv.y;
            Ks[(c + 2) * AST + r] = kv.z; Ks[(c + 3) * AST + r] = kv.w;
            float4 vv = *reinterpret_cast<const float4*>(vp + (size_t)r * 3072 + c);
            *reinterpret_cast<float4*>(&Vs[r * AST + c]) = vv;
        }
        __syncthreads();

        float s[4][4];
#pragma unroll
        for (int r = 0; r < 4; r++)
#pragma unroll
            for (int c = 0; c < 4; c++) s[r][c] = 0.0f;
#pragma unroll
        for (int d = 0; d < 64; d++) {
            float4 af = *reinterpret_cast<const float4*>(&Qs[d * AST + ty * 4]);
            float4 bf = *reinterpret_cast<const float4*>(&Ks[d * AST + tx * 4]);
            float a[4] = {af.x, af.y, af.z, af.w};
            float bb[4] = {bf.x, bf.y, bf.z, bf.w};
#pragma unroll
            for (int r = 0; r < 4; r++)
#pragma unroll
                for (int c = 0; c < 4; c++)
                    s[r][c] = fmaf(a[r], bb[c], s[r][c]);
        }

#pragma unroll
        for (int r = 0; r < 4; r++) {
            float mv = fmaxf(fmaxf(s[r][0], s[r][1]), fmaxf(s[r][2], s[r][3]));
            mv = fmaxf(mv, __shfl_xor_sync(0xffffffffu, mv, 1));
            mv = fmaxf(mv, __shfl_xor_sync(0xffffffffu, mv, 2));
            mv = fmaxf(mv, __shfl_xor_sync(0xffffffffu, mv, 4));
            mv = fmaxf(mv, __shfl_xor_sync(0xffffffffu, mv, 8));
            float mn = fmaxf(m_i[r], mv);
            float alpha = fexp(m_i[r] - mn);
            m_i[r] = mn;
            float p0 = fexp(s[r][0] - mn);
            float p1 = fexp(s[r][1] - mn);
            float p2 = fexp(s[r][2] - mn);
            float p3 = fexp(s[r][3] - mn);
            float rsum = p0 + p1 + p2 + p3;
            rsum += __shfl_xor_sync(0xffffffffu, rsum, 1);
            rsum += __shfl_xor_sync(0xffffffffu, rsum, 2);
            rsum += __shfl_xor_sync(0xffffffffu, rsum, 4);
            rsum += __shfl_xor_sync(0xffffffffu, rsum, 8);
            l_i[r] = l_i[r] * alpha + rsum;
#pragma unroll
            for (int c = 0; c < 4; c++) o[r][c] *= alpha;
            *reinterpret_cast<float4*>(&Ps[(ty * 4 + r) * AST + tx * 4]) =
                make_float4(p0, p1, p2, p3);
        }
        __syncthreads();

#pragma unroll
        for (int kc = 0; kc < 64; kc++) {
            float4 bf = *reinterpret_cast<const float4*>(&Vs[kc * AST + tx * 4]);
            float bb[4] = {bf.x, bf.y, bf.z, bf.w};
            float a0 = Ps[(ty * 4 + 0) * AST + kc];
            float a1 = Ps[(ty * 4 + 1) * AST + kc];
            float a2 = Ps[(ty * 4 + 2) * AST + kc];
            float a3 = Ps[(ty * 4 + 3) * AST + kc];
#pragma unroll
            for (int c = 0; c < 4; c++) {
                o[0][c] = fmaf(a0, bb[c], o[0][c]);
                o[1][c] = fmaf(a1, bb[c], o[1][c]);
                o[2][c] = fmaf(a2, bb[c], o[2][c]);
                o[3][c] = fmaf(a3, bb[c], o[3][c]);
            }
        }
    }

#pragma unroll
    for (int r = 0; r < 4; r++) {
        float inv = 1.0f / l_i[r];
        int n = q0 + ty * 4 + r;
        *reinterpret_cast<float4*>(&g_attn[((size_t)b * 2048 + n) * 1024 + h * 64 + tx * 4]) =
            make_float4(o[r][0] * inv, o[r][1] * inv, o[r][2] * inv, o[r][3] * inv);
    }
}

// ---------------------------------------------------------------------------
// Launch
// ---------------------------------------------------------------------------
extern "C" void kernel_launch(void* const* d_in, const int* in_sizes, int n_in,
                              void* d_out, int out_size)
{
    const float* x      = (const float*)d_in[0];
    const float* qkv_w  = (const float*)d_in[1];
    const float* qkv_b  = (const float*)d_in[2];
    const float* qn_w   = (const float*)d_in[3];
    const float* kn_w   = (const float*)d_in[4];
    const float* proj_w = (const float*)d_in[5];
    const float* proj_b = (const float*)d_in[6];
    float* out = (float*)d_out;

    const int gemm_smem = 2 * STAGE_B;                    // 81920
    cudaFuncSetAttribute(gemm_mma, cudaFuncAttributeMaxDynamicSharedMemorySize, gemm_smem);
    const int attn_smem = 4 * 64 * AST * sizeof(float);   // 69632
    cudaFuncSetAttribute(attn_kernel, cudaFuncAttributeMaxDynamicSharedMemorySize, attn_smem);

    void *p_qkv, *p_attn, *p_xhi, *p_xlo, *p_w1hi, *p_w1lo, *p_w2hi, *p_w2lo, *p_ahi, *p_alo;
    cudaGetSymbolAddress(&p_qkv, g_qkv);
    cudaGetSymbolAddress(&p_attn, g_attn);
    cudaGetSymbolAddress(&p_xhi, g_xhi);   cudaGetSymbolAddress(&p_xlo, g_xlo);
    cudaGetSymbolAddress(&p_w1hi, g_w1hi); cudaGetSymbolAddress(&p_w1lo, g_w1lo);
    cudaGetSymbolAddress(&p_w2hi, g_w2hi); cudaGetSymbolAddress(&p_w2lo, g_w2lo);
    cudaGetSymbolAddress(&p_ahi, g_ahi);   cudaGetSymbolAddress(&p_alo, g_alo);

    // 0. RoPE tables
    rope_table<<<128, 256>>>();

    // 1. Splits of inputs/weights
    split_bf16<<<(M_ * C_ / 4 + 255) / 256, 256>>>((const float4*)x, (uint2*)p_xhi, (uint2*)p_xlo, M_ * C_ / 4);
    split_bf16<<<(K3_ * C_ / 4 + 255) / 256, 256>>>((const float4*)qkv_w, (uint2*)p_w1hi, (uint2*)p_w1lo, K3_ * C_ / 4);
    split_bf16<<<(C_ * C_ / 4 + 255) / 256, 256>>>((const float4*)proj_w, (uint2*)p_w2hi, (uint2*)p_w2lo, C_ * C_ / 4);

    // 2. QKV projection -> g_qkv [M, 3072]
    gemm_mma<<<dim3(K3_ / 128, M_ / 128), 256, gemm_smem>>>(
        (const __nv_bfloat16*)p_xhi, (const __nv_bfloat16*)p_xlo,
        (const __nv_bfloat16*)p_w1hi, (const __nv_bfloat16*)p_w1lo,
        qkv_b, (float*)p_qkv, K3_);

    // 3. RMSNorm + segmented RoPE
    norm_rope<<<dim3((B_ * H_ * N_) / 8, 2), 256>>>(qn_w, kn_w);

    // 4. Flash attention -> g_attn
    attn_kernel<<<dim3(N_ / 64, H_, B_), 256, attn_smem>>>();

    // 5. Split attention output, then output projection -> d_out
    split_bf16<<<(M_ * C_ / 4 + 255) / 256, 256>>>((const float4*)p_attn, (uint2*)p_ahi, (uint2*)p_alo, M_ * C_ / 4);
    gemm_mma<<<dim3(C_ / 128, M_ / 128), 256, gemm_smem>>>(
        (const __nv_bfloat16*)p_ahi, (const __nv_bfloat16*)p_alo,
        (const __nv_bfloat16*)p_w2hi, (const __nv_bfloat16*)p_w2lo,
        proj_b, out, C_);
}

// round 4
// speedup vs baseline: 2.3634x; 1.7976x over previous
#include <cuda_runtime.h>
#include <cuda_bf16.h>
#include <cstdint>
#include <math.h>

// Problem constants
#define B_  2
#define N_  2048
#define C_  1024
#define H_  16
#define D_  64
#define M_  (B_ * N_)        // 4096
#define K3_ (3 * C_)         // 3072

// ---------------------------------------------------------------------------
// Scratch (device globals)
// ---------------------------------------------------------------------------
__device__ float g_qkv[M_ * K3_];        // [M, 3072] fp32 QKV GEMM output
__device__ __nv_bfloat16 g_xhi[M_ * C_],  g_xlo[M_ * C_];
__device__ __nv_bfloat16 g_w1hi[K3_ * C_], g_w1lo[K3_ * C_];
__device__ __nv_bfloat16 g_w2hi[C_ * C_],  g_w2lo[C_ * C_];
__device__ __nv_bfloat16 g_ahi[M_ * C_],  g_alo[M_ * C_];   // attention out hi/lo
// head-major [b*16+h][n][64] bf16 hi/lo
__device__ __nv_bfloat16 g_qhi[B_*H_*N_*D_], g_qlo[B_*H_*N_*D_];
__device__ __nv_bfloat16 g_khi[B_*H_*N_*D_], g_klo[B_*H_*N_*D_];
__device__ __nv_bfloat16 g_vhi[B_*H_*N_*D_], g_vlo[B_*H_*N_*D_];
__device__ float g_cos[1024 * 32], g_sin[1024 * 32];

// ---------------------------------------------------------------------------
// Helpers
// ---------------------------------------------------------------------------
__device__ __forceinline__ uint32_t smem_u32(const void* p) {
    uint32_t a;
    asm("{ .reg .u64 t; cvta.to.shared.u64 t, %1; cvt.u32.u64 %0, t; }" : "=r"(a) : "l"(p));
    return a;
}
__device__ __forceinline__ void ldsm4(uint32_t* r, uint32_t addr) {
    asm volatile("ldmatrix.sync.aligned.m8n8.x4.shared.b16 {%0,%1,%2,%3}, [%4];"
                 : "=r"(r[0]), "=r"(r[1]), "=r"(r[2]), "=r"(r[3]) : "r"(addr));
}
__device__ __forceinline__ void ldsm4t(uint32_t* r, uint32_t addr) {
    asm volatile("ldmatrix.sync.aligned.m8n8.x4.trans.shared.b16 {%0,%1,%2,%3}, [%4];"
                 : "=r"(r[0]), "=r"(r[1]), "=r"(r[2]), "=r"(r[3]) : "r"(addr));
}
__device__ __forceinline__ void mma16816(float* c, const uint32_t* a, uint32_t b0, uint32_t b1) {
    asm volatile("mma.sync.aligned.m16n8k16.row.col.f32.bf16.bf16.f32 "
                 "{%0,%1,%2,%3}, {%4,%5,%6,%7}, {%8,%9}, {%0,%1,%2,%3};"
                 : "+f"(c[0]), "+f"(c[1]), "+f"(c[2]), "+f"(c[3])
                 : "r"(a[0]), "r"(a[1]), "r"(a[2]), "r"(a[3]), "r"(b0), "r"(b1));
}
// pack (lo=a, hi=b) into bf16x2
__device__ __forceinline__ uint32_t packbf(float a, float b) {
    uint32_t r;
    asm("cvt.rn.bf16x2.f32 %0, %1, %2;" : "=r"(r) : "f"(b), "f"(a));
    return r;
}
// split pair (a,b) into bf16x2 hi + bf16x2 residual
__device__ __forceinline__ void split2(float a, float b, uint32_t& hi, uint32_t& lo) {
    uint32_t h = packbf(a, b);
    float ra = a - __uint_as_float(h << 16);
    float rb = b - __uint_as_float(h & 0xffff0000u);
    hi = h;
    lo = packbf(ra, rb);
}
// Fast exp: deg-6 2^f poly (rel err ~1.5e-5), FMA pipe only.
__device__ __forceinline__ float fexp(float x) {
    x = fmaxf(x, -80.0f);
    float t = x * 1.4426950408889634f;
    float fi = floorf(t);
    float f = t - fi;
    float p = fmaf(f, 1.5403530e-4f, 1.3333558e-3f);
    p = fmaf(p, f, 9.6181291e-3f);
    p = fmaf(p, f, 5.5504109e-2f);
    p = fmaf(p, f, 2.4022651e-1f);
    p = fmaf(p, f, 6.9314718e-1f);
    p = fmaf(p, f, 1.0f);
    int i = (int)fi;
    return p * __int_as_float((i + 127) << 23);
}

// ---------------------------------------------------------------------------
// Split fp32 -> bf16 hi + bf16 lo
// ---------------------------------------------------------------------------
__global__ __launch_bounds__(256) void split_bf16(const float4* __restrict__ src,
                                                  uint2* __restrict__ hi,
                                                  uint2* __restrict__ lo, int n4)
{
    int i = blockIdx.x * 256 + threadIdx.x;
    if (i >= n4) return;
    float4 v = src[i];
    uint32_t h0, l0, h1, l1;
    split2(v.x, v.y, h0, l0);
    split2(v.z, v.w, h1, l1);
    hi[i] = make_uint2(h0, h1);
    lo[i] = make_uint2(l0, l1);
}

// ---------------------------------------------------------------------------
// RoPE tables
// ---------------------------------------------------------------------------
__global__ __launch_bounds__(256) void rope_table()
{
    int idx = blockIdx.x * 256 + threadIdx.x;          // 32768
    int pos = idx >> 5, lane = idx & 31;
    float e = (float)(2 * lane) * (1.0f / 64.0f);
    float inv = expf(-9.210340371976184f * e);
    float ang = (float)pos * inv;
    g_cos[idx] = cosf(ang);
    g_sin[idx] = sinf(ang);
}

// ---------------------------------------------------------------------------
// bf16x3 compensated GEMM via mma.sync (unchanged from round 3).
// ---------------------------------------------------------------------------
#define STAGE_B 40960

__global__ __launch_bounds__(256, 1) void gemm_mma(
    const __nv_bfloat16* __restrict__ Ahi, const __nv_bfloat16* __restrict__ Alo,
    const __nv_bfloat16* __restrict__ Bhi, const __nv_bfloat16* __restrict__ Blo,
    const float* __restrict__ bias, float* __restrict__ out, int ostride)
{
    extern __shared__ char sm[];
    const uint32_t sbase = smem_u32(sm);
    const int tid = threadIdx.x;
    const int lane = tid & 31;
    const int wid = tid >> 5;
    const int warp_m = wid >> 1;
    const int warp_n = wid & 1;
    const int row0 = blockIdx.y * 128;
    const int col0 = blockIdx.x * 128;

    float acc[2][8][4];
#pragma unroll
    for (int a = 0; a < 2; a++)
#pragma unroll
        for (int b = 0; b < 8; b++)
#pragma unroll
            for (int c = 0; c < 4; c++) acc[a][b][c] = 0.0f;

    const __nv_bfloat16* srcs[4] = {
        Ahi + (size_t)row0 * 1024, Alo + (size_t)row0 * 1024,
        Bhi + (size_t)col0 * 1024, Blo + (size_t)col0 * 1024 };

    auto load_stage = [&](int c, int buf) {
#pragma unroll
        for (int i = 0; i < 8; i++) {
            int lin = tid + i * 256;
            int mat = lin >> 9;
            int rem = lin & 511;
            int row = rem >> 2;
            int ch = rem & 3;
            const __nv_bfloat16* s = srcs[mat] + (size_t)row * 1024 + c * 32 + ch * 8;
            uint32_t d = sbase + buf * STAGE_B + mat * 10240 + (uint32_t)(row * 40 + ch * 8) * 2;
            asm volatile("cp.async.cg.shared.global [%0], [%1], 16;" :: "r"(d), "l"(s));
        }
        asm volatile("cp.async.commit_group;");
    };

    load_stage(0, 0);

    for (int c = 0; c < 32; c++) {
        const int buf = c & 1;
        if (c + 1 < 32) {
            load_stage(c + 1, buf ^ 1);
            asm volatile("cp.async.wait_group 1;");
        } else {
            asm volatile("cp.async.wait_group 0;");
        }
        __syncthreads();

        const uint32_t base = sbase + buf * STAGE_B;
#pragma unroll
        for (int kk = 0; kk < 2; kk++) {
            uint32_t ah[2][4], al[2][4], bh[4][4], bl[4][4];
            int arow = warp_m * 32 + (lane & 15);
            int acol = kk * 16 + (lane >> 4) * 8;
            uint32_t aoff = (uint32_t)(arow * 40 + acol) * 2;
            ldsm4(ah[0], base + aoff);
            ldsm4(ah[1], base + aoff + 1280);
            ldsm4(al[0], base + 10240 + aoff);
            ldsm4(al[1], base + 10240 + aoff + 1280);
            int g = lane >> 3, l7 = lane & 7;
#pragma unroll
            for (int p = 0; p < 4; p++) {
                int brow = warp_n * 64 + (p * 2 + (g >> 1)) * 8 + l7;
                int bcol = kk * 16 + (g & 1) * 8;
                uint32_t boff = (uint32_t)(brow * 40 + bcol) * 2;
                ldsm4(bh[p], base + 20480 + boff);
                ldsm4(bl[p], base + 30720 + boff);
            }
#pragma unroll
            for (int tm = 0; tm < 2; tm++)
#pragma unroll
                for (int tn = 0; tn < 8; tn++) {
                    uint32_t bh0 = bh[tn >> 1][(tn & 1) * 2], bh1 = bh[tn >> 1][(tn & 1) * 2 + 1];
                    uint32_t bl0 = bl[tn >> 1][(tn & 1) * 2], bl1 = bl[tn >> 1][(tn & 1) * 2 + 1];
                    mma16816(acc[tm][tn], ah[tm], bh0, bh1);
                    mma16816(acc[tm][tn], ah[tm], bl0, bl1);
                    mma16816(acc[tm][tn], al[tm], bh0, bh1);
                }
        }
        __syncthreads();
    }

#pragma unroll
    for (int tm = 0; tm < 2; tm++) {
        int mb = row0 + warp_m * 32 + tm * 16 + (lane >> 2);
#pragma unroll
        for (int tn = 0; tn < 8; tn++) {
            int col = col0 + warp_n * 64 + tn * 8 + (lane & 3) * 2;
            float b0 = __ldg(&bias[col]), b1 = __ldg(&bias[col + 1]);
            *reinterpret_cast<float2*>(&out[(size_t)mb * ostride + col]) =
                make_float2(acc[tm][tn][0] + b0, acc[tm][tn][1] + b1);
            *reinterpret_cast<float2*>(&out[(size_t)(mb + 8) * ostride + col]) =
                make_float2(acc[tm][tn][2] + b0, acc[tm][tn][3] + b1);
        }
    }
}

// ---------------------------------------------------------------------------
// RMSNorm + segmented RoPE + bf16 hi/lo emit, head-major layout.
// blockIdx.y: 0 = q (scaled 0.125), 1 = k, 2 = v passthrough split.
// ---------------------------------------------------------------------------
__global__ __launch_bounds__(256) void norm_rope(const float* __restrict__ wq,
                                                 const float* __restrict__ wk)
{
    const int which = blockIdx.y;
    const int gtid = blockIdx.x * blockDim.x + threadIdx.x;
    const int row = gtid >> 5;
    const int lane = threadIdx.x & 31;
    if (row >= B_ * H_ * N_) return;

    const int b = row >> 15;
    const int h = (row >> 11) & 15;
    const int n = row & 2047;
    const float* src = g_qkv + ((size_t)(b * 2048 + n)) * 3072 + which * 1024 + h * 64;

    float y0 = src[lane];
    float y1 = src[lane + 32];

    if (which < 2) {
        const float* w = which ? wk : wq;
        float ss = y0 * y0 + y1 * y1;
#pragma unroll
        for (int m = 16; m >= 1; m >>= 1)
            ss += __shfl_xor_sync(0xffffffffu, ss, m);
        float rs;
        if (lane == 0) rs = rsqrtf(ss * (1.0f / 64.0f) + 1e-6f);
        rs = __shfl_sync(0xffffffffu, rs, 0);
        y0 = y0 * rs * w[lane];
        y1 = y1 * rs * w[lane + 32];

        int pos = (n < 1024) ? n : ((n < 1536) ? (n - 1024) : -1);
        if (pos >= 0) {
            float cs = g_cos[pos * 32 + lane];
            float sn = g_sin[pos * 32 + lane];
            float o0 = y0 * cs - y1 * sn;
            float o1 = y1 * cs + y0 * sn;
            y0 = o0; y1 = o1;
        }
        if (which == 0) { y0 *= 0.125f; y1 *= 0.125f; }
    }

    __nv_bfloat16 *dhi, *dlo;
    const size_t o = (((size_t)(b * 16 + h)) * 2048 + n) * 64;
    if (which == 0)      { dhi = g_qhi + o; dlo = g_qlo + o; }
    else if (which == 1) { dhi = g_khi + o; dlo = g_klo + o; }
    else                 { dhi = g_vhi + o; dlo = g_vlo + o; }

    __nv_bfloat16 h0 = __float2bfloat16_rn(y0);
    __nv_bfloat16 h1 = __float2bfloat16_rn(y1);
    dhi[lane]      = h0;
    dhi[lane + 32] = h1;
    dlo[lane]      = __float2bfloat16_rn(y0 - __bfloat162float(h0));
    dlo[lane + 32] = __float2bfloat16_rn(y1 - __bfloat162float(h1));
}

// ---------------------------------------------------------------------------
// Flash attention via mma.sync (bf16x3 compensated QK^T and P.V).
// CTA: 128 queries of one (b,h); 8 warps x 16 rows. K/V tiles of 64 keys,
// cp.async double-buffered. Epilogue emits bf16 hi/lo into [M,1024].
// ---------------------------------------------------------------------------
#define RS   144                  // smem row stride bytes (72 bf16)
#define SQHI 0
#define SQLO 18432
#define SBUF 36864                // start of K/V buffers
#define BUFB 36864                // bytes per buffer (4 x 64 x 144)
#define OKHI 0
#define OKLO 9216
#define OVHI 18432
#define OVLO 27648
#define ATTN_SMEM (SBUF + 2 * BUFB)   // 110592

__global__ __launch_bounds__(256, 1) void attn_mma()
{
    extern __shared__ char sm[];
    const uint32_t sbase = smem_u32(sm);
    const int tid = threadIdx.x;
    const int lane = tid & 31;
    const int wid = tid >> 5;
    const int q0 = blockIdx.x * 128;
    const int h = blockIdx.y;
    const int b = blockIdx.z;
    const size_t hb = ((size_t)(b * 16 + h)) * 2048 * 64;   // head base (elements)

    const __nv_bfloat16* qhi_g = g_qhi + hb + (size_t)q0 * 64;
    const __nv_bfloat16* qlo_g = g_qlo + hb + (size_t)q0 * 64;
    const __nv_bfloat16* khi_g = g_khi + hb;
    const __nv_bfloat16* klo_g = g_klo + hb;
    const __nv_bfloat16* vhi_g = g_vhi + hb;
    const __nv_bfloat16* vlo_g = g_vlo + hb;

    // ---- loaders ----
    auto load_q = [&]() {
#pragma unroll
        for (int i = 0; i < 8; i++) {
            int lin = tid + i * 256;          // 0..2047
            int mat = lin >> 10;              // 0=hi, 1=lo
            int rem = lin & 1023;
            int row = rem >> 3;
            int ch = rem & 7;
            const __nv_bfloat16* s = (mat ? qlo_g : qhi_g) + (size_t)row * 64 + ch * 8;
            uint32_t d = sbase + (mat ? SQLO : SQHI) + (uint32_t)(row * RS + ch * 16);
            asm volatile("cp.async.cg.shared.global [%0], [%1], 16;" :: "r"(d), "l"(s));
        }
    };
    auto load_kv = [&](int t, int buf) {
        const __nv_bfloat16* srcs[4] = {
            khi_g + (size_t)t * 64 * 64, klo_g + (size_t)t * 64 * 64,
            vhi_g + (size_t)t * 64 * 64, vlo_g + (size_t)t * 64 * 64 };
        const uint32_t dbase = sbase + SBUF + buf * BUFB;
#pragma unroll
        for (int i = 0; i < 8; i++) {
            int lin = tid + i * 256;          // 0..2047
            int mat = lin >> 9;               // 0..3
            int rem = lin & 511;
            int row = rem >> 3;
            int ch = rem & 7;
            const __nv_bfloat16* s = srcs[mat] + (size_t)row * 64 + ch * 8;
            uint32_t d = dbase + mat * 9216 + (uint32_t)(row * RS + ch * 16);
            asm volatile("cp.async.cg.shared.global [%0], [%1], 16;" :: "r"(d), "l"(s));
        }
        asm volatile("cp.async.commit_group;");
    };

    load_q();
    load_kv(0, 0);     // Q + KV0 are split over two commit groups (load_kv commits
                       // the joint set: Q issued before, same group boundary)
    load_kv(1, 1);
    asm volatile("cp.async.wait_group 1;");  // Q + KV0 complete
    __syncthreads();

    // ---- hoist Q fragments (constant across k-tiles) ----
    uint32_t ahi[4][4], alo[4][4];
    {
        const int arow = wid * 16 + (lane & 15);
        const int acolb = (lane >> 4) * 16;   // bytes: (lane>>4)*8 elements
#pragma unroll
        for (int kc = 0; kc < 4; kc++) {
            uint32_t off = (uint32_t)(arow * RS + kc * 32 + acolb);
            ldsm4(ahi[kc], sbase + SQHI + off);
            ldsm4(alo[kc], sbase + SQLO + off);
        }
    }

    float m0 = -1e30f, m1 = -1e30f, l0 = 0.0f, l1 = 0.0f;
    float o[8][4];
#pragma unroll
    for (int nd = 0; nd < 8; nd++)
#pragma unroll
        for (int j = 0; j < 4; j++) o[nd][j] = 0.0f;

    const int g = lane >> 3, l7 = lane & 7;

    for (int t = 0; t < 32; t++) {
        const uint32_t kbuf = sbase + SBUF + (t & 1) * BUFB;

        // ---- S = Q K^T (3-pass hi/lo) ----
        float c[8][4];
#pragma unroll
        for (int tn = 0; tn < 8; tn++)
#pragma unroll
            for (int j = 0; j < 4; j++) c[tn][j] = 0.0f;

#pragma unroll
        for (int kc = 0; kc < 4; kc++) {
            uint32_t bh[4][4], bl[4][4];
#pragma unroll
            for (int p = 0; p < 4; p++) {
                int brow = (p * 2 + (g >> 1)) * 8 + l7;
                int bcolb = kc * 32 + (g & 1) * 16;
                uint32_t off = (uint32_t)(brow * RS + bcolb);
                ldsm4(bh[p], kbuf + OKHI + off);
                ldsm4(bl[p], kbuf + OKLO + off);
            }
#pragma unroll
            for (int tn = 0; tn < 8; tn++) {
                uint32_t bh0 = bh[tn >> 1][(tn & 1) * 2], bh1 = bh[tn >> 1][(tn & 1) * 2 + 1];
                uint32_t bl0 = bl[tn >> 1][(tn & 1) * 2], bl1 = bl[tn >> 1][(tn & 1) * 2 + 1];
                mma16816(c[tn], ahi[kc], bh0, bh1);
                mma16816(c[tn], ahi[kc], bl0, bl1);
                mma16816(c[tn], alo[kc], bh0, bh1);
            }
        }

        // ---- online softmax ----
        float mx0 = c[0][0], mx1 = c[0][2];
#pragma unroll
        for (int tn = 0; tn < 8; tn++) {
            mx0 = fmaxf(mx0, fmaxf(c[tn][0], c[tn][1]));
            mx1 = fmaxf(mx1, fmaxf(c[tn][2], c[tn][3]));
        }
        mx0 = fmaxf(mx0, __shfl_xor_sync(0xffffffffu, mx0, 1));
        mx0 = fmaxf(mx0, __shfl_xor_sync(0xffffffffu, mx0, 2));
        mx1 = fmaxf(mx1, __shfl_xor_sync(0xffffffffu, mx1, 1));
        mx1 = fmaxf(mx1, __shfl_xor_sync(0xffffffffu, mx1, 2));
        float mn0 = fmaxf(m0, mx0), mn1 = fmaxf(m1, mx1);
        float al0 = fexp(m0 - mn0), al1 = fexp(m1 - mn1);
        m0 = mn0; m1 = mn1;

        float s0 = 0.0f, s1 = 0.0f;
#pragma unroll
        for (int tn = 0; tn < 8; tn++) {
            c[tn][0] = fexp(c[tn][0] - mn0);
            c[tn][1] = fexp(c[tn][1] - mn0);
            c[tn][2] = fexp(c[tn][2] - mn1);
            c[tn][3] = fexp(c[tn][3] - mn1);
            s0 += c[tn][0] + c[tn][1];
            s1 += c[tn][2] + c[tn][3];
        }
        s0 += __shfl_xor_sync(0xffffffffu, s0, 1);
        s0 += __shfl_xor_sync(0xffffffffu, s0, 2);
        s1 += __shfl_xor_sync(0xffffffffu, s1, 1);
        s1 += __shfl_xor_sync(0xffffffffu, s1, 2);
        l0 = l0 * al0 + s0;
        l1 = l1 * al1 + s1;
#pragma unroll
        for (int nd = 0; nd < 8; nd++) {
            o[nd][0] *= al0; o[nd][1] *= al0;
            o[nd][2] *= al1; o[nd][3] *= al1;
        }

        // ---- O += P V (3-pass hi/lo), P repacked in registers ----
#pragma unroll
        for (int kc = 0; kc < 4; kc++) {
            uint32_t phi[4], plo[4];
            split2(c[2 * kc][0],     c[2 * kc][1],     phi[0], plo[0]);
            split2(c[2 * kc][2],     c[2 * kc][3],     phi[1], plo[1]);
            split2(c[2 * kc + 1][0], c[2 * kc + 1][1], phi[2], plo[2]);
            split2(c[2 * kc + 1][2], c[2 * kc + 1][3], phi[3], plo[3]);
#pragma unroll
            for (int dp = 0; dp < 4; dp++) {
                int vrow = kc * 16 + (g & 1) * 8 + l7;
                int vcolb = dp * 32 + (g >> 1) * 16;
                uint32_t off = (uint32_t)(vrow * RS + vcolb);
                uint32_t vh[4], vl[4];
                ldsm4t(vh, kbuf + OVHI + off);
                ldsm4t(vl, kbuf + OVLO + off);
                mma16816(o[dp * 2],     phi, vh[0], vh[1]);
                mma16816(o[dp * 2 + 1], phi, vh[2], vh[3]);
                mma16816(o[dp * 2],     phi, vl[0], vl[1]);
                mma16816(o[dp * 2 + 1], phi, vl[2], vl[3]);
                mma16816(o[dp * 2],     plo, vh[0], vh[1]);
                mma16816(o[dp * 2 + 1], plo, vh[2], vh[3]);
            }
        }

        __syncthreads();   // all reads of this buffer done
        if (t + 2 < 32) load_kv(t + 2, t & 1);
        if (t + 1 < 32) {
            if (t + 2 < 32) { asm volatile("cp.async.wait_group 1;"); }
            else            { asm volatile("cp.async.wait_group 0;"); }
            __syncthreads();
        }
    }

    // ---- epilogue: normalize + write bf16 hi/lo into [M,1024] ----
    const float inv0 = 1.0f / l0, inv1 = 1.0f / l1;
    const int r0 = q0 + wid * 16 + (lane >> 2);
    const size_t m0i = (size_t)(b * 2048) + r0;
    const int colb = h * 64 + (lane & 3) * 2;
#pragma unroll
    for (int nd = 0; nd < 8; nd++) {
        uint32_t hi, lo;
        split2(o[nd][0] * inv0, o[nd][1] * inv0, hi, lo);
        *reinterpret_cast<uint32_t*>(&g_ahi[m0i * 1024 + colb + nd * 8]) = hi;
        *reinterpret_cast<uint32_t*>(&g_alo[m0i * 1024 + colb + nd * 8]) = lo;
        split2(o[nd][2] * inv1, o[nd][3] * inv1, hi, lo);
        *reinterpret_cast<uint32_t*>(&g_ahi[(m0i + 8) * 1024 + colb + nd * 8]) = hi;
        *reinterpret_cast<uint32_t*>(&g_alo[(m0i + 8) * 1024 + colb + nd * 8]) = lo;
    }
}

// ---------------------------------------------------------------------------
// Launch
// ---------------------------------------------------------------------------
extern "C" void kernel_launch(void* const* d_in, const int* in_sizes, int n_in,
                              void* d_out, int out_size)
{
    const float* x      = (const float*)d_in[0];
    const float* qkv_w  = (const float*)d_in[1];
    const float* qkv_b  = (const float*)d_in[2];
    const float* qn_w   = (const float*)d_in[3];
    const float* kn_w   = (const float*)d_in[4];
    const float* proj_w = (const float*)d_in[5];
    const float* proj_b = (const float*)d_in[6];
    float* out = (float*)d_out;

    const int gemm_smem = 2 * STAGE_B;
    cudaFuncSetAttribute(gemm_mma, cudaFuncAttributeMaxDynamicSharedMemorySize, gemm_smem);
    cudaFuncSetAttribute(attn_mma, cudaFuncAttributeMaxDynamicSharedMemorySize, ATTN_SMEM);

    void *p_qkv, *p_xhi, *p_xlo, *p_w1hi, *p_w1lo, *p_w2hi, *p_w2lo, *p_ahi, *p_alo;
    cudaGetSymbolAddress(&p_qkv, g_qkv);
    cudaGetSymbolAddress(&p_xhi, g_xhi);   cudaGetSymbolAddress(&p_xlo, g_xlo);
    cudaGetSymbolAddress(&p_w1hi, g_w1hi); cudaGetSymbolAddress(&p_w1lo, g_w1lo);
    cudaGetSymbolAddress(&p_w2hi, g_w2hi); cudaGetSymbolAddress(&p_w2lo, g_w2lo);
    cudaGetSymbolAddress(&p_ahi, g_ahi);   cudaGetSymbolAddress(&p_alo, g_alo);

    rope_table<<<128, 256>>>();

    split_bf16<<<(M_ * C_ / 4 + 255) / 256, 256>>>((const float4*)x, (uint2*)p_xhi, (uint2*)p_xlo, M_ * C_ / 4);
    split_bf16<<<(K3_ * C_ / 4 + 255) / 256, 256>>>((const float4*)qkv_w, (uint2*)p_w1hi, (uint2*)p_w1lo, K3_ * C_ / 4);
    split_bf16<<<(C_ * C_ / 4 + 255) / 256, 256>>>((const float4*)proj_w, (uint2*)p_w2hi, (uint2*)p_w2lo, C_ * C_ / 4);

    // 1. QKV projection -> g_qkv [M, 3072]
    gemm_mma<<<dim3(K3_ / 128, M_ / 128), 256, gemm_smem>>>(
        (const __nv_bfloat16*)p_xhi, (const __nv_bfloat16*)p_xlo,
        (const __nv_bfloat16*)p_w1hi, (const __nv_bfloat16*)p_w1lo,
        qkv_b, (float*)p_qkv, K3_);

    // 2. RMSNorm + RoPE + bf16 split (q scaled), head-major
    norm_rope<<<dim3((B_ * H_ * N_) / 8, 3), 256>>>(qn_w, kn_w);

    // 3. Tensor-core flash attention -> g_ahi/g_alo [M,1024]
    attn_mma<<<dim3(N_ / 128, H_, B_), 256, ATTN_SMEM>>>();

    // 4. Output projection -> d_out
    gemm_mma<<<dim3(C_ / 128, M_ / 128), 256, gemm_smem>>>(
        (const __nv_bfloat16*)p_ahi, (const __nv_bfloat16*)p_alo,
        (const __nv_bfloat16*)p_w2hi, (const __nv_bfloat16*)p_w2lo,
        proj_b, out, C_);
}

// round 5
// speedup vs baseline: 3.5066x; 1.4837x over previous
#include <cuda_runtime.h>
#include <cuda_bf16.h>
#include <cuda_fp16.h>
#include <cstdint>
#include <math.h>

// Problem constants
#define B_  2
#define N_  2048
#define C_  1024
#define H_  16
#define D_  64
#define M_  (B_ * N_)        // 4096
#define K3_ (3 * C_)         // 3072

// ---------------------------------------------------------------------------
// Scratch (device globals)
// ---------------------------------------------------------------------------
__device__ float g_qkv[M_ * K3_];          // [M, 3072] fp32 QKV GEMM output
__device__ __half g_xhi[M_ * C_],  g_xlo[M_ * C_];     // x split
__device__ __half g_w1h[K3_ * C_];                     // qkv_w single fp16
__device__ __half g_w2h[C_ * C_];                      // proj_w single fp16
__device__ __half g_ahi[M_ * C_],  g_alo[M_ * C_];     // attention out split
// head-major [b*16+h][n][64]
__device__ __half g_qhi[B_*H_*N_*D_], g_qlo[B_*H_*N_*D_];   // Q split
__device__ __half g_k[B_*H_*N_*D_];                         // K single
__device__ __half g_v[B_*H_*N_*D_];                         // V single
__device__ float g_cos[1024 * 32], g_sin[1024 * 32];

// ---------------------------------------------------------------------------
// Helpers
// ---------------------------------------------------------------------------
__device__ __forceinline__ uint32_t smem_u32(const void* p) {
    uint32_t a;
    asm("{ .reg .u64 t; cvta.to.shared.u64 t, %1; cvt.u32.u64 %0, t; }" : "=r"(a) : "l"(p));
    return a;
}
__device__ __forceinline__ void ldsm4(uint32_t* r, uint32_t addr) {
    asm volatile("ldmatrix.sync.aligned.m8n8.x4.shared.b16 {%0,%1,%2,%3}, [%4];"
                 : "=r"(r[0]), "=r"(r[1]), "=r"(r[2]), "=r"(r[3]) : "r"(addr));
}
__device__ __forceinline__ void ldsm4t(uint32_t* r, uint32_t addr) {
    asm volatile("ldmatrix.sync.aligned.m8n8.x4.trans.shared.b16 {%0,%1,%2,%3}, [%4];"
                 : "=r"(r[0]), "=r"(r[1]), "=r"(r[2]), "=r"(r[3]) : "r"(addr));
}
__device__ __forceinline__ void mma16816(float* c, const uint32_t* a, uint32_t b0, uint32_t b1) {
    asm volatile("mma.sync.aligned.m16n8k16.row.col.f32.f16.f16.f32 "
                 "{%0,%1,%2,%3}, {%4,%5,%6,%7}, {%8,%9}, {%0,%1,%2,%3};"
                 : "+f"(c[0]), "+f"(c[1]), "+f"(c[2]), "+f"(c[3])
                 : "r"(a[0]), "r"(a[1]), "r"(a[2]), "r"(a[3]), "r"(b0), "r"(b1));
}
// pack (low=a, high=b) into f16x2
__device__ __forceinline__ uint32_t packh(float a, float b) {
    uint32_t r;
    asm("cvt.rn.f16x2.f32 %0, %1, %2;" : "=r"(r) : "f"(b), "f"(a));
    return r;
}
// split pair (a,b) into f16x2 hi + f16x2 residual
__device__ __forceinline__ void split2h(float a, float b, uint32_t& hi, uint32_t& lo) {
    uint32_t h = packh(a, b);
    __half2 hh = *reinterpret_cast<__half2*>(&h);
    float2 hf = __half22float2(hh);
    hi = h;
    lo = packh(a - hf.x, b - hf.y);
}
// Fast exp: deg-6 2^f poly (rel err ~1.5e-5), FMA pipe only.
__device__ __forceinline__ float fexp(float x) {
    x = fmaxf(x, -80.0f);
    float t = x * 1.4426950408889634f;
    float fi = floorf(t);
    float f = t - fi;
    float p = fmaf(f, 1.5403530e-4f, 1.3333558e-3f);
    p = fmaf(p, f, 9.6181291e-3f);
    p = fmaf(p, f, 5.5504109e-2f);
    p = fmaf(p, f, 2.4022651e-1f);
    p = fmaf(p, f, 6.9314718e-1f);
    p = fmaf(p, f, 1.0f);
    int i = (int)fi;
    return p * __int_as_float((i + 127) << 23);
}

// ---------------------------------------------------------------------------
// fp32 -> fp16 hi + lo split
// ---------------------------------------------------------------------------
__global__ __launch_bounds__(256) void split_fp16(const float4* __restrict__ src,
                                                  uint2* __restrict__ hi,
                                                  uint2* __restrict__ lo, int n4)
{
    int i = blockIdx.x * 256 + threadIdx.x;
    if (i >= n4) return;
    float4 v = src[i];
    uint32_t h0, l0, h1, l1;
    split2h(v.x, v.y, h0, l0);
    split2h(v.z, v.w, h1, l1);
    hi[i] = make_uint2(h0, h1);
    lo[i] = make_uint2(l0, l1);
}
// fp32 -> fp16 single
__global__ __launch_bounds__(256) void cvt_fp16(const float4* __restrict__ src,
                                                uint2* __restrict__ dst, int n4)
{
    int i = blockIdx.x * 256 + threadIdx.x;
    if (i >= n4) return;
    float4 v = src[i];
    dst[i] = make_uint2(packh(v.x, v.y), packh(v.z, v.w));
}

// ---------------------------------------------------------------------------
// RoPE tables
// ---------------------------------------------------------------------------
__global__ __launch_bounds__(256) void rope_table()
{
    int idx = blockIdx.x * 256 + threadIdx.x;          // 32768
    int pos = idx >> 5, lane = idx & 31;
    float e = (float)(2 * lane) * (1.0f / 64.0f);
    float inv = expf(-9.210340371976184f * e);
    float ang = (float)pos * inv;
    g_cos[idx] = cosf(ang);
    g_sin[idx] = sinf(ang);
}

// ---------------------------------------------------------------------------
// fp16 2-pass compensated GEMM: out[m][j] = (Ahi+Alo)[m,:] . Bh[j,:] + bias[j]
// Block 128x128, K-chunk 32, 8 warps (4x2), warp tile 32x64, cp.async 2-stage.
// Stage: 3 matrices (Ahi, Alo, B), 30720 B; double buffered.
// ---------------------------------------------------------------------------
#define STAGE_B 30720

__global__ __launch_bounds__(256, 2) void gemm_mma(
    const __half* __restrict__ Ahi, const __half* __restrict__ Alo,
    const __half* __restrict__ Bh,
    const float* __restrict__ bias, float* __restrict__ out, int ostride)
{
    extern __shared__ char sm[];
    const uint32_t sbase = smem_u32(sm);
    const int tid = threadIdx.x;
    const int lane = tid & 31;
    const int wid = tid >> 5;
    const int warp_m = wid >> 1;
    const int warp_n = wid & 1;
    const int row0 = blockIdx.y * 128;
    const int col0 = blockIdx.x * 128;

    float acc[2][8][4];
#pragma unroll
    for (int a = 0; a < 2; a++)
#pragma unroll
        for (int b = 0; b < 8; b++)
#pragma unroll
            for (int c = 0; c < 4; c++) acc[a][b][c] = 0.0f;

    const __half* srcs[3] = {
        Ahi + (size_t)row0 * 1024, Alo + (size_t)row0 * 1024,
        Bh + (size_t)col0 * 1024 };

    auto load_stage = [&](int c, int buf) {
#pragma unroll
        for (int i = 0; i < 6; i++) {
            int lin = tid + i * 256;          // 0..1535
            int mat = lin >> 9;               // 0..2
            int rem = lin & 511;
            int row = rem >> 2;
            int ch = rem & 3;
            const __half* s = srcs[mat] + (size_t)row * 1024 + c * 32 + ch * 8;
            uint32_t d = sbase + buf * STAGE_B + mat * 10240 + (uint32_t)(row * 40 + ch * 8) * 2;
            asm volatile("cp.async.cg.shared.global [%0], [%1], 16;" :: "r"(d), "l"(s));
        }
        asm volatile("cp.async.commit_group;");
    };

    load_stage(0, 0);

    for (int c = 0; c < 32; c++) {
        const int buf = c & 1;
        if (c + 1 < 32) {
            load_stage(c + 1, buf ^ 1);
            asm volatile("cp.async.wait_group 1;");
        } else {
            asm volatile("cp.async.wait_group 0;");
        }
        __syncthreads();

        const uint32_t base = sbase + buf * STAGE_B;
#pragma unroll
        for (int kk = 0; kk < 2; kk++) {
            uint32_t ah[2][4], al[2][4], bh[4][4];
            int arow = warp_m * 32 + (lane & 15);
            int acol = kk * 16 + (lane >> 4) * 8;
            uint32_t aoff = (uint32_t)(arow * 40 + acol) * 2;
            ldsm4(ah[0], base + aoff);
            ldsm4(ah[1], base + aoff + 1280);
            ldsm4(al[0], base + 10240 + aoff);
            ldsm4(al[1], base + 10240 + aoff + 1280);
            int g = lane >> 3, l7 = lane & 7;
#pragma unroll
            for (int p = 0; p < 4; p++) {
                int brow = warp_n * 64 + (p * 2 + (g >> 1)) * 8 + l7;
                int bcol = kk * 16 + (g & 1) * 8;
                uint32_t boff = (uint32_t)(brow * 40 + bcol) * 2;
                ldsm4(bh[p], base + 20480 + boff);
            }
#pragma unroll
            for (int tm = 0; tm < 2; tm++)
#pragma unroll
                for (int tn = 0; tn < 8; tn++) {
                    uint32_t b0 = bh[tn >> 1][(tn & 1) * 2], b1 = bh[tn >> 1][(tn & 1) * 2 + 1];
                    mma16816(acc[tm][tn], ah[tm], b0, b1);
                    mma16816(acc[tm][tn], al[tm], b0, b1);
                }
        }
        __syncthreads();
    }

#pragma unroll
    for (int tm = 0; tm < 2; tm++) {
        int mb = row0 + warp_m * 32 + tm * 16 + (lane >> 2);
#pragma unroll
        for (int tn = 0; tn < 8; tn++) {
            int col = col0 + warp_n * 64 + tn * 8 + (lane & 3) * 2;
            float b0 = __ldg(&bias[col]), b1 = __ldg(&bias[col + 1]);
            *reinterpret_cast<float2*>(&out[(size_t)mb * ostride + col]) =
                make_float2(acc[tm][tn][0] + b0, acc[tm][tn][1] + b1);
            *reinterpret_cast<float2*>(&out[(size_t)(mb + 8) * ostride + col]) =
                make_float2(acc[tm][tn][2] + b0, acc[tm][tn][3] + b1);
        }
    }
}

// ---------------------------------------------------------------------------
// RMSNorm + segmented RoPE + fp16 emit, head-major layout.
// blockIdx.y: 0 = q (split hi/lo), 1 = k (single), 2 = v (single).
// ---------------------------------------------------------------------------
__global__ __launch_bounds__(256) void norm_rope(const float* __restrict__ wq,
                                                 const float* __restrict__ wk)
{
    const int which = blockIdx.y;
    const int gtid = blockIdx.x * blockDim.x + threadIdx.x;
    const int row = gtid >> 5;
    const int lane = threadIdx.x & 31;
    if (row >= B_ * H_ * N_) return;

    const int b = row >> 15;
    const int h = (row >> 11) & 15;
    const int n = row & 2047;
    const float* src = g_qkv + ((size_t)(b * 2048 + n)) * 3072 + which * 1024 + h * 64;

    float y0 = src[lane];
    float y1 = src[lane + 32];

    if (which < 2) {
        const float* w = which ? wk : wq;
        float ss = y0 * y0 + y1 * y1;
#pragma unroll
        for (int m = 16; m >= 1; m >>= 1)
            ss += __shfl_xor_sync(0xffffffffu, ss, m);
        float rs;
        if (lane == 0) rs = rsqrtf(ss * (1.0f / 64.0f) + 1e-6f);
        rs = __shfl_sync(0xffffffffu, rs, 0);
        y0 = y0 * rs * w[lane];
        y1 = y1 * rs * w[lane + 32];

        int pos = (n < 1024) ? n : ((n < 1536) ? (n - 1024) : -1);
        if (pos >= 0) {
            float cs = g_cos[pos * 32 + lane];
            float sn = g_sin[pos * 32 + lane];
            float o0 = y0 * cs - y1 * sn;
            float o1 = y1 * cs + y0 * sn;
            y0 = o0; y1 = o1;
        }
    }

    const size_t o = (((size_t)(b * 16 + h)) * 2048 + n) * 64;
    if (which == 0) {
        __half h0 = __float2half_rn(y0);
        __half h1 = __float2half_rn(y1);
        g_qhi[o + lane]      = h0;
        g_qhi[o + lane + 32] = h1;
        g_qlo[o + lane]      = __float2half_rn(y0 - __half2float(h0));
        g_qlo[o + lane + 32] = __float2half_rn(y1 - __half2float(h1));
    } else if (which == 1) {
        g_k[o + lane]      = __float2half_rn(y0);
        g_k[o + lane + 32] = __float2half_rn(y1);
    } else {
        g_v[o + lane]      = __float2half_rn(y0);
        g_v[o + lane + 32] = __float2half_rn(y1);
    }
}

// ---------------------------------------------------------------------------
// Flash attention via mma.sync fp16 (Q split 2-pass, K/V single).
// CTA: 128 queries of one (b,h); 8 warps x 16 rows. 64-key tiles,
// cp.async double-buffered. 1/sqrt(D) folded into logits post-MMA.
// ---------------------------------------------------------------------------
#define RS   144                  // smem row stride bytes (72 fp16)
#define SQHI 0
#define SQLO 18432
#define SBUF 36864                // start of K/V buffers
#define BUFB 18432                // per buffer: K 9216 + V 9216
#define OV   9216
#define ATTN_SMEM (SBUF + 2 * BUFB)   // 73728

__global__ __launch_bounds__(256, 1) void attn_mma()
{
    extern __shared__ char sm[];
    const uint32_t sbase = smem_u32(sm);
    const int tid = threadIdx.x;
    const int lane = tid & 31;
    const int wid = tid >> 5;
    const int q0 = blockIdx.x * 128;
    const int h = blockIdx.y;
    const int b = blockIdx.z;
    const size_t hb = ((size_t)(b * 16 + h)) * 2048 * 64;

    const __half* qhi_g = g_qhi + hb + (size_t)q0 * 64;
    const __half* qlo_g = g_qlo + hb + (size_t)q0 * 64;
    const __half* k_g = g_k + hb;
    const __half* v_g = g_v + hb;

    auto load_q = [&]() {
#pragma unroll
        for (int i = 0; i < 8; i++) {
            int lin = tid + i * 256;          // 0..2047
            int mat = lin >> 10;              // 0=hi, 1=lo
            int rem = lin & 1023;
            int row = rem >> 3;
            int ch = rem & 7;
            const __half* s = (mat ? qlo_g : qhi_g) + (size_t)row * 64 + ch * 8;
            uint32_t d = sbase + (mat ? SQLO : SQHI) + (uint32_t)(row * RS + ch * 16);
            asm volatile("cp.async.cg.shared.global [%0], [%1], 16;" :: "r"(d), "l"(s));
        }
    };
    auto load_kv = [&](int t, int buf) {
        const uint32_t dbase = sbase + SBUF + buf * BUFB;
#pragma unroll
        for (int i = 0; i < 4; i++) {
            int lin = tid + i * 256;          // 0..1023
            int mat = lin >> 9;               // 0=K, 1=V
            int rem = lin & 511;
            int row = rem >> 3;
            int ch = rem & 7;
            const __half* s = (mat ? v_g : k_g) + (size_t)t * 64 * 64 + (size_t)row * 64 + ch * 8;
            uint32_t d = dbase + mat * OV + (uint32_t)(row * RS + ch * 16);
            asm volatile("cp.async.cg.shared.global [%0], [%1], 16;" :: "r"(d), "l"(s));
        }
        asm volatile("cp.async.commit_group;");
    };

    load_q();
    load_kv(0, 0);     // Q + KV0 share commit group 0
    load_kv(1, 1);
    asm volatile("cp.async.wait_group 1;");
    __syncthreads();

    // hoist Q fragments
    uint32_t ahi[4][4], alo[4][4];
    {
        const int arow = wid * 16 + (lane & 15);
        const int acolb = (lane >> 4) * 16;
#pragma unroll
        for (int kc = 0; kc < 4; kc++) {
            uint32_t off = (uint32_t)(arow * RS + kc * 32 + acolb);
            ldsm4(ahi[kc], sbase + SQHI + off);
            ldsm4(alo[kc], sbase + SQLO + off);
        }
    }

    float m0 = -1e30f, m1 = -1e30f, l0 = 0.0f, l1 = 0.0f;
    float o[8][4];
#pragma unroll
    for (int nd = 0; nd < 8; nd++)
#pragma unroll
        for (int j = 0; j < 4; j++) o[nd][j] = 0.0f;

    const int g = lane >> 3, l7 = lane & 7;

    for (int t = 0; t < 32; t++) {
        const uint32_t kbuf = sbase + SBUF + (t & 1) * BUFB;

        // ---- S = Q K^T (2-pass) ----
        float c[8][4];
#pragma unroll
        for (int tn = 0; tn < 8; tn++)
#pragma unroll
            for (int j = 0; j < 4; j++) c[tn][j] = 0.0f;

#pragma unroll
        for (int kc = 0; kc < 4; kc++) {
            uint32_t bh[4][4];
#pragma unroll
            for (int p = 0; p < 4; p++) {
                int brow = (p * 2 + (g >> 1)) * 8 + l7;
                int bcolb = kc * 32 + (g & 1) * 16;
                ldsm4(bh[p], kbuf + (uint32_t)(brow * RS + bcolb));
            }
#pragma unroll
            for (int tn = 0; tn < 8; tn++) {
                uint32_t b0 = bh[tn >> 1][(tn & 1) * 2], b1 = bh[tn >> 1][(tn & 1) * 2 + 1];
                mma16816(c[tn], ahi[kc], b0, b1);
                mma16816(c[tn], alo[kc], b0, b1);
            }
        }

        // ---- scale + online softmax ----
        float mx0 = -1e30f, mx1 = -1e30f;
#pragma unroll
        for (int tn = 0; tn < 8; tn++) {
            c[tn][0] *= 0.125f; c[tn][1] *= 0.125f;
            c[tn][2] *= 0.125f; c[tn][3] *= 0.125f;
            mx0 = fmaxf(mx0, fmaxf(c[tn][0], c[tn][1]));
            mx1 = fmaxf(mx1, fmaxf(c[tn][2], c[tn][3]));
        }
        mx0 = fmaxf(mx0, __shfl_xor_sync(0xffffffffu, mx0, 1));
        mx0 = fmaxf(mx0, __shfl_xor_sync(0xffffffffu, mx0, 2));
        mx1 = fmaxf(mx1, __shfl_xor_sync(0xffffffffu, mx1, 1));
        mx1 = fmaxf(mx1, __shfl_xor_sync(0xffffffffu, mx1, 2));
        float mn0 = fmaxf(m0, mx0), mn1 = fmaxf(m1, mx1);
        float al0 = fexp(m0 - mn0), al1 = fexp(m1 - mn1);
        m0 = mn0; m1 = mn1;

        float s0 = 0.0f, s1 = 0.0f;
#pragma unroll
        for (int tn = 0; tn < 8; tn++) {
            c[tn][0] = fexp(c[tn][0] - mn0);
            c[tn][1] = fexp(c[tn][1] - mn0);
            c[tn][2] = fexp(c[tn][2] - mn1);
            c[tn][3] = fexp(c[tn][3] - mn1);
            s0 += c[tn][0] + c[tn][1];
            s1 += c[tn][2] + c[tn][3];
        }
        s0 += __shfl_xor_sync(0xffffffffu, s0, 1);
        s0 += __shfl_xor_sync(0xffffffffu, s0, 2);
        s1 += __shfl_xor_sync(0xffffffffu, s1, 1);
        s1 += __shfl_xor_sync(0xffffffffu, s1, 2);
        l0 = l0 * al0 + s0;
        l1 = l1 * al1 + s1;
#pragma unroll
        for (int nd = 0; nd < 8; nd++) {
            o[nd][0] *= al0; o[nd][1] *= al0;
            o[nd][2] *= al1; o[nd][3] *= al1;
        }

        // ---- O += P V (P split 2-pass, V single) ----
#pragma unroll
        for (int kc = 0; kc < 4; kc++) {
            uint32_t phi[4], plo[4];
            split2h(c[2 * kc][0],     c[2 * kc][1],     phi[0], plo[0]);
            split2h(c[2 * kc][2],     c[2 * kc][3],     phi[1], plo[1]);
            split2h(c[2 * kc + 1][0], c[2 * kc + 1][1], phi[2], plo[2]);
            split2h(c[2 * kc + 1][2], c[2 * kc + 1][3], phi[3], plo[3]);
#pragma unroll
            for (int dp = 0; dp < 4; dp++) {
                int vrow = kc * 16 + (g & 1) * 8 + l7;
                int vcolb = dp * 32 + (g >> 1) * 16;
                uint32_t vh[4];
                ldsm4t(vh, kbuf + OV + (uint32_t)(vrow * RS + vcolb));
                mma16816(o[dp * 2],     phi, vh[0], vh[1]);
                mma16816(o[dp * 2 + 1], phi, vh[2], vh[3]);
                mma16816(o[dp * 2],     plo, vh[0], vh[1]);
                mma16816(o[dp * 2 + 1], plo, vh[2], vh[3]);
            }
        }

        __syncthreads();
        if (t + 2 < 32) load_kv(t + 2, t & 1);
        if (t + 1 < 32) {
            if (t + 2 < 32) { asm volatile("cp.async.wait_group 1;"); }
            else            { asm volatile("cp.async.wait_group 0;"); }
            __syncthreads();
        }
    }

    // ---- epilogue: normalize + fp16 hi/lo into [M,1024] ----
    const float inv0 = 1.0f / l0, inv1 = 1.0f / l1;
    const int r0 = q0 + wid * 16 + (lane >> 2);
    const size_t m0i = (size_t)(b * 2048) + r0;
    const int colb = h * 64 + (lane & 3) * 2;
#pragma unroll
    for (int nd = 0; nd < 8; nd++) {
        uint32_t hi, lo;
        split2h(o[nd][0] * inv0, o[nd][1] * inv0, hi, lo);
        *reinterpret_cast<uint32_t*>(&g_ahi[m0i * 1024 + colb + nd * 8]) = hi;
        *reinterpret_cast<uint32_t*>(&g_alo[m0i * 1024 + colb + nd * 8]) = lo;
        split2h(o[nd][2] * inv1, o[nd][3] * inv1, hi, lo);
        *reinterpret_cast<uint32_t*>(&g_ahi[(m0i + 8) * 1024 + colb + nd * 8]) = hi;
        *reinterpret_cast<uint32_t*>(&g_alo[(m0i + 8) * 1024 + colb + nd * 8]) = lo;
    }
}

// ---------------------------------------------------------------------------
// Launch
// ---------------------------------------------------------------------------
extern "C" void kernel_launch(void* const* d_in, const int* in_sizes, int n_in,
                              void* d_out, int out_size)
{
    const float* x      = (const float*)d_in[0];
    const float* qkv_w  = (const float*)d_in[1];
    const float* qkv_b  = (const float*)d_in[2];
    const float* qn_w   = (const float*)d_in[3];
    const float* kn_w   = (const float*)d_in[4];
    const float* proj_w = (const float*)d_in[5];
    const float* proj_b = (const float*)d_in[6];
    float* out = (float*)d_out;

    const int gemm_smem = 2 * STAGE_B;   // 61440
    cudaFuncSetAttribute(gemm_mma, cudaFuncAttributeMaxDynamicSharedMemorySize, gemm_smem);
    cudaFuncSetAttribute(attn_mma, cudaFuncAttributeMaxDynamicSharedMemorySize, ATTN_SMEM);

    void *p_qkv, *p_xhi, *p_xlo, *p_w1h, *p_w2h, *p_ahi, *p_alo;
    cudaGetSymbolAddress(&p_qkv, g_qkv);
    cudaGetSymbolAddress(&p_xhi, g_xhi);   cudaGetSymbolAddress(&p_xlo, g_xlo);
    cudaGetSymbolAddress(&p_w1h, g_w1h);   cudaGetSymbolAddress(&p_w2h, g_w2h);
    cudaGetSymbolAddress(&p_ahi, g_ahi);   cudaGetSymbolAddress(&p_alo, g_alo);

    rope_table<<<128, 256>>>();

    split_fp16<<<(M_ * C_ / 4 + 255) / 256, 256>>>((const float4*)x, (uint2*)p_xhi, (uint2*)p_xlo, M_ * C_ / 4);
    cvt_fp16<<<(K3_ * C_ / 4 + 255) / 256, 256>>>((const float4*)qkv_w, (uint2*)p_w1h, K3_ * C_ / 4);
    cvt_fp16<<<(C_ * C_ / 4 + 255) / 256, 256>>>((const float4*)proj_w, (uint2*)p_w2h, C_ * C_ / 4);

    // 1. QKV projection -> g_qkv [M, 3072]
    gemm_mma<<<dim3(K3_ / 128, M_ / 128), 256, gemm_smem>>>(
        (const __half*)p_xhi, (const __half*)p_xlo, (const __half*)p_w1h,
        qkv_b, (float*)p_qkv, K3_);

    // 2. RMSNorm + RoPE + fp16 emit, head-major
    norm_rope<<<dim3((B_ * H_ * N_) / 8, 3), 256>>>(qn_w, kn_w);

    // 3. Tensor-core flash attention -> g_ahi/g_alo [M,1024]
    attn_mma<<<dim3(N_ / 128, H_, B_), 256, ATTN_SMEM>>>();

    // 4. Output projection -> d_out
    gemm_mma<<<dim3(C_ / 128, M_ / 128), 256, gemm_smem>>>(
        (const __half*)p_ahi, (const __half*)p_alo, (const __half*)p_w2h,
        proj_b, out, C_);
}

// round 6
// speedup vs baseline: 4.2451x; 1.2106x over previous
#include <cuda_runtime.h>
#include <cuda_bf16.h>
#include <cuda_fp16.h>
#include <cstdint>
#include <math.h>

// Problem constants
#define B_  2
#define N_  2048
#define C_  1024
#define H_  16
#define D_  64
#define M_  (B_ * N_)        // 4096
#define K3_ (3 * C_)         // 3072

// ---------------------------------------------------------------------------
// Scratch (device globals)
// ---------------------------------------------------------------------------
__device__ float g_qkv[M_ * K3_];          // [M, 3072] fp32 QKV GEMM output
__device__ __half g_xhi[M_ * C_],  g_xlo[M_ * C_];     // x split
__device__ __half g_w1h[K3_ * C_];                     // qkv_w single fp16
__device__ __half g_w2h[C_ * C_];                      // proj_w single fp16
__device__ __half g_ahi[M_ * C_],  g_alo[M_ * C_];     // attention out split
// head-major [b*16+h][n][64]
__device__ __half g_qhi[B_*H_*N_*D_], g_qlo[B_*H_*N_*D_];   // Q split (pre-scaled)
__device__ __half g_k[B_*H_*N_*D_];                         // K single
__device__ __half g_v[B_*H_*N_*D_];                         // V single
__device__ float g_cos[1024 * 32], g_sin[1024 * 32];

// ---------------------------------------------------------------------------
// Helpers
// ---------------------------------------------------------------------------
__device__ __forceinline__ uint32_t smem_u32(const void* p) {
    uint32_t a;
    asm("{ .reg .u64 t; cvta.to.shared.u64 t, %1; cvt.u32.u64 %0, t; }" : "=r"(a) : "l"(p));
    return a;
}
__device__ __forceinline__ void ldsm4(uint32_t* r, uint32_t addr) {
    asm volatile("ldmatrix.sync.aligned.m8n8.x4.shared.b16 {%0,%1,%2,%3}, [%4];"
                 : "=r"(r[0]), "=r"(r[1]), "=r"(r[2]), "=r"(r[3]) : "r"(addr));
}
__device__ __forceinline__ void ldsm4t(uint32_t* r, uint32_t addr) {
    asm volatile("ldmatrix.sync.aligned.m8n8.x4.trans.shared.b16 {%0,%1,%2,%3}, [%4];"
                 : "=r"(r[0]), "=r"(r[1]), "=r"(r[2]), "=r"(r[3]) : "r"(addr));
}
__device__ __forceinline__ void mma16816(float* c, const uint32_t* a, uint32_t b0, uint32_t b1) {
    asm volatile("mma.sync.aligned.m16n8k16.row.col.f32.f16.f16.f32 "
                 "{%0,%1,%2,%3}, {%4,%5,%6,%7}, {%8,%9}, {%0,%1,%2,%3};"
                 : "+f"(c[0]), "+f"(c[1]), "+f"(c[2]), "+f"(c[3])
                 : "r"(a[0]), "r"(a[1]), "r"(a[2]), "r"(a[3]), "r"(b0), "r"(b1));
}
// pack (low=a, high=b) into f16x2
__device__ __forceinline__ uint32_t packh(float a, float b) {
    uint32_t r;
    asm("cvt.rn.f16x2.f32 %0, %1, %2;" : "=r"(r) : "f"(b), "f"(a));
    return r;
}
// split pair (a,b) into f16x2 hi + f16x2 residual
__device__ __forceinline__ void split2h(float a, float b, uint32_t& hi, uint32_t& lo) {
    uint32_t h = packh(a, b);
    __half2 hh = *reinterpret_cast<__half2*>(&h);
    float2 hf = __half22float2(hh);
    hi = h;
    lo = packh(a - hf.x, b - hf.y);
}
// MUFU exp2 (logits pre-scaled by log2e)
__device__ __forceinline__ float fexp2(float x) {
    float r;
    asm("ex2.approx.f32 %0, %1;" : "=f"(r) : "f"(x));
    return r;
}

// ---------------------------------------------------------------------------
// fp32 -> fp16 hi + lo split
// ---------------------------------------------------------------------------
__global__ __launch_bounds__(256) void split_fp16(const float4* __restrict__ src,
                                                  uint2* __restrict__ hi,
                                                  uint2* __restrict__ lo, int n4)
{
    int i = blockIdx.x * 256 + threadIdx.x;
    if (i >= n4) return;
    float4 v = src[i];
    uint32_t h0, l0, h1, l1;
    split2h(v.x, v.y, h0, l0);
    split2h(v.z, v.w, h1, l1);
    hi[i] = make_uint2(h0, h1);
    lo[i] = make_uint2(l0, l1);
}
// fp32 -> fp16 single
__global__ __launch_bounds__(256) void cvt_fp16(const float4* __restrict__ src,
                                                uint2* __restrict__ dst, int n4)
{
    int i = blockIdx.x * 256 + threadIdx.x;
    if (i >= n4) return;
    float4 v = src[i];
    dst[i] = make_uint2(packh(v.x, v.y), packh(v.z, v.w));
}

// ---------------------------------------------------------------------------
// RoPE tables
// ---------------------------------------------------------------------------
__global__ __launch_bounds__(256) void rope_table()
{
    int idx = blockIdx.x * 256 + threadIdx.x;          // 32768
    int pos = idx >> 5, lane = idx & 31;
    float e = (float)(2 * lane) * (1.0f / 64.0f);
    float inv = expf(-9.210340371976184f * e);
    float ang = (float)pos * inv;
    g_cos[idx] = cosf(ang);
    g_sin[idx] = sinf(ang);
}

// ---------------------------------------------------------------------------
// fp16 2-pass compensated GEMM: out[m][j] = (Ahi+Alo)[m,:] . Bh[j,:] + bias[j]
// Block 128x128, K-chunk 32, 8 warps (4x2), warp tile 32x64, cp.async 2-stage.
// ---------------------------------------------------------------------------
#define STAGE_B 30720

__global__ __launch_bounds__(256, 2) void gemm_mma(
    const __half* __restrict__ Ahi, const __half* __restrict__ Alo,
    const __half* __restrict__ Bh,
    const float* __restrict__ bias, float* __restrict__ out, int ostride)
{
    extern __shared__ char sm[];
    const uint32_t sbase = smem_u32(sm);
    const int tid = threadIdx.x;
    const int lane = tid & 31;
    const int wid = tid >> 5;
    const int warp_m = wid >> 1;
    const int warp_n = wid & 1;
    const int row0 = blockIdx.y * 128;
    const int col0 = blockIdx.x * 128;

    float acc[2][8][4];
#pragma unroll
    for (int a = 0; a < 2; a++)
#pragma unroll
        for (int b = 0; b < 8; b++)
#pragma unroll
            for (int c = 0; c < 4; c++) acc[a][b][c] = 0.0f;

    const __half* srcs[3] = {
        Ahi + (size_t)row0 * 1024, Alo + (size_t)row0 * 1024,
        Bh + (size_t)col0 * 1024 };

    auto load_stage = [&](int c, int buf) {
#pragma unroll
        for (int i = 0; i < 6; i++) {
            int lin = tid + i * 256;          // 0..1535
            int mat = lin >> 9;               // 0..2
            int rem = lin & 511;
            int row = rem >> 2;
            int ch = rem & 3;
            const __half* s = srcs[mat] + (size_t)row * 1024 + c * 32 + ch * 8;
            uint32_t d = sbase + buf * STAGE_B + mat * 10240 + (uint32_t)(row * 40 + ch * 8) * 2;
            asm volatile("cp.async.cg.shared.global [%0], [%1], 16;" :: "r"(d), "l"(s));
        }
        asm volatile("cp.async.commit_group;");
    };

    load_stage(0, 0);

    for (int c = 0; c < 32; c++) {
        const int buf = c & 1;
        if (c + 1 < 32) {
            load_stage(c + 1, buf ^ 1);
            asm volatile("cp.async.wait_group 1;");
        } else {
            asm volatile("cp.async.wait_group 0;");
        }
        __syncthreads();

        const uint32_t base = sbase + buf * STAGE_B;
#pragma unroll
        for (int kk = 0; kk < 2; kk++) {
            uint32_t ah[2][4], al[2][4], bh[4][4];
            int arow = warp_m * 32 + (lane & 15);
            int acol = kk * 16 + (lane >> 4) * 8;
            uint32_t aoff = (uint32_t)(arow * 40 + acol) * 2;
            ldsm4(ah[0], base + aoff);
            ldsm4(ah[1], base + aoff + 1280);
            ldsm4(al[0], base + 10240 + aoff);
            ldsm4(al[1], base + 10240 + aoff + 1280);
            int g = lane >> 3, l7 = lane & 7;
#pragma unroll
            for (int p = 0; p < 4; p++) {
                int brow = warp_n * 64 + (p * 2 + (g >> 1)) * 8 + l7;
                int bcol = kk * 16 + (g & 1) * 8;
                uint32_t boff = (uint32_t)(brow * 40 + bcol) * 2;
                ldsm4(bh[p], base + 20480 + boff);
            }
#pragma unroll
            for (int tm = 0; tm < 2; tm++)
#pragma unroll
                for (int tn = 0; tn < 8; tn++) {
                    uint32_t b0 = bh[tn >> 1][(tn & 1) * 2], b1 = bh[tn >> 1][(tn & 1) * 2 + 1];
                    mma16816(acc[tm][tn], ah[tm], b0, b1);
                    mma16816(acc[tm][tn], al[tm], b0, b1);
                }
        }
        __syncthreads();
    }

#pragma unroll
    for (int tm = 0; tm < 2; tm++) {
        int mb = row0 + warp_m * 32 + tm * 16 + (lane >> 2);
#pragma unroll
        for (int tn = 0; tn < 8; tn++) {
            int col = col0 + warp_n * 64 + tn * 8 + (lane & 3) * 2;
            float b0 = __ldg(&bias[col]), b1 = __ldg(&bias[col + 1]);
            *reinterpret_cast<float2*>(&out[(size_t)mb * ostride + col]) =
                make_float2(acc[tm][tn][0] + b0, acc[tm][tn][1] + b1);
            *reinterpret_cast<float2*>(&out[(size_t)(mb + 8) * ostride + col]) =
                make_float2(acc[tm][tn][2] + b0, acc[tm][tn][3] + b1);
        }
    }
}

// ---------------------------------------------------------------------------
// RMSNorm + segmented RoPE + fp16 emit, head-major layout.
// blockIdx.y: 0 = q (split hi/lo, scaled by 0.125*log2e), 1 = k, 2 = v.
// ---------------------------------------------------------------------------
#define QSCALE 0.1803368801111137f   // 0.125 * log2(e)

__global__ __launch_bounds__(256) void norm_rope(const float* __restrict__ wq,
                                                 const float* __restrict__ wk)
{
    const int which = blockIdx.y;
    const int gtid = blockIdx.x * blockDim.x + threadIdx.x;
    const int row = gtid >> 5;
    const int lane = threadIdx.x & 31;
    if (row >= B_ * H_ * N_) return;

    const int b = row >> 15;
    const int h = (row >> 11) & 15;
    const int n = row & 2047;
    const float* src = g_qkv + ((size_t)(b * 2048 + n)) * 3072 + which * 1024 + h * 64;

    float y0 = src[lane];
    float y1 = src[lane + 32];

    if (which < 2) {
        const float* w = which ? wk : wq;
        float ss = y0 * y0 + y1 * y1;
#pragma unroll
        for (int m = 16; m >= 1; m >>= 1)
            ss += __shfl_xor_sync(0xffffffffu, ss, m);
        float rs;
        if (lane == 0) rs = rsqrtf(ss * (1.0f / 64.0f) + 1e-6f);
        rs = __shfl_sync(0xffffffffu, rs, 0);
        y0 = y0 * rs * w[lane];
        y1 = y1 * rs * w[lane + 32];

        int pos = (n < 1024) ? n : ((n < 1536) ? (n - 1024) : -1);
        if (pos >= 0) {
            float cs = g_cos[pos * 32 + lane];
            float sn = g_sin[pos * 32 + lane];
            float o0 = y0 * cs - y1 * sn;
            float o1 = y1 * cs + y0 * sn;
            y0 = o0; y1 = o1;
        }
        if (which == 0) { y0 *= QSCALE; y1 *= QSCALE; }
    }

    const size_t o = (((size_t)(b * 16 + h)) * 2048 + n) * 64;
    if (which == 0) {
        __half h0 = __float2half_rn(y0);
        __half h1 = __float2half_rn(y1);
        g_qhi[o + lane]      = h0;
        g_qhi[o + lane + 32] = h1;
        g_qlo[o + lane]      = __float2half_rn(y0 - __half2float(h0));
        g_qlo[o + lane + 32] = __float2half_rn(y1 - __half2float(h1));
    } else if (which == 1) {
        g_k[o + lane]      = __float2half_rn(y0);
        g_k[o + lane + 32] = __float2half_rn(y1);
    } else {
        g_v[o + lane]      = __float2half_rn(y0);
        g_v[o + lane + 32] = __float2half_rn(y1);
    }
}

// ---------------------------------------------------------------------------
// Flash attention via mma.sync fp16. Q split 2-pass (pre-scaled to log2
// domain); softmax = MUFU ex2; P single-pass fp16; V single fp16.
// CTA: 128 queries of one (b,h); 8 warps x 16 rows; 64-key tiles double-buffered.
// ---------------------------------------------------------------------------
#define RS   144                  // smem row stride bytes (72 fp16)
#define SQHI 0
#define SQLO 18432
#define SBUF 36864
#define BUFB 18432                // per buffer: K 9216 + V 9216
#define OV   9216
#define ATTN_SMEM (SBUF + 2 * BUFB)   // 73728

__global__ __launch_bounds__(256, 1) void attn_mma()
{
    extern __shared__ char sm[];
    const uint32_t sbase = smem_u32(sm);
    const int tid = threadIdx.x;
    const int lane = tid & 31;
    const int wid = tid >> 5;
    const int q0 = blockIdx.x * 128;
    const int h = blockIdx.y;
    const int b = blockIdx.z;
    const size_t hb = ((size_t)(b * 16 + h)) * 2048 * 64;

    const __half* qhi_g = g_qhi + hb + (size_t)q0 * 64;
    const __half* qlo_g = g_qlo + hb + (size_t)q0 * 64;
    const __half* k_g = g_k + hb;
    const __half* v_g = g_v + hb;

    auto load_q = [&]() {
#pragma unroll
        for (int i = 0; i < 8; i++) {
            int lin = tid + i * 256;
            int mat = lin >> 10;
            int rem = lin & 1023;
            int row = rem >> 3;
            int ch = rem & 7;
            const __half* s = (mat ? qlo_g : qhi_g) + (size_t)row * 64 + ch * 8;
            uint32_t d = sbase + (mat ? SQLO : SQHI) + (uint32_t)(row * RS + ch * 16);
            asm volatile("cp.async.cg.shared.global [%0], [%1], 16;" :: "r"(d), "l"(s));
        }
    };
    auto load_kv = [&](int t, int buf) {
        const uint32_t dbase = sbase + SBUF + buf * BUFB;
#pragma unroll
        for (int i = 0; i < 4; i++) {
            int lin = tid + i * 256;
            int mat = lin >> 9;
            int rem = lin & 511;
            int row = rem >> 3;
            int ch = rem & 7;
            const __half* s = (mat ? v_g : k_g) + (size_t)t * 64 * 64 + (size_t)row * 64 + ch * 8;
            uint32_t d = dbase + mat * OV + (uint32_t)(row * RS + ch * 16);
            asm volatile("cp.async.cg.shared.global [%0], [%1], 16;" :: "r"(d), "l"(s));
        }
        asm volatile("cp.async.commit_group;");
    };

    load_q();
    load_kv(0, 0);
    load_kv(1, 1);
    asm volatile("cp.async.wait_group 1;");
    __syncthreads();

    // hoist Q fragments
    uint32_t ahi[4][4], alo[4][4];
    {
        const int arow = wid * 16 + (lane & 15);
        const int acolb = (lane >> 4) * 16;
#pragma unroll
        for (int kc = 0; kc < 4; kc++) {
            uint32_t off = (uint32_t)(arow * RS + kc * 32 + acolb);
            ldsm4(ahi[kc], sbase + SQHI + off);
            ldsm4(alo[kc], sbase + SQLO + off);
        }
    }

    float m0 = -1e30f, m1 = -1e30f, l0 = 0.0f, l1 = 0.0f;
    float o[8][4];
#pragma unroll
    for (int nd = 0; nd < 8; nd++)
#pragma unroll
        for (int j = 0; j < 4; j++) o[nd][j] = 0.0f;

    const int g = lane >> 3, l7 = lane & 7;

    for (int t = 0; t < 32; t++) {
        const uint32_t kbuf = sbase + SBUF + (t & 1) * BUFB;

        // ---- S = Q K^T (2-pass), logits already in log2 domain ----
        float c[8][4];
#pragma unroll
        for (int tn = 0; tn < 8; tn++)
#pragma unroll
            for (int j = 0; j < 4; j++) c[tn][j] = 0.0f;

#pragma unroll
        for (int kc = 0; kc < 4; kc++) {
            uint32_t bh[4][4];
#pragma unroll
            for (int p = 0; p < 4; p++) {
                int brow = (p * 2 + (g >> 1)) * 8 + l7;
                int bcolb = kc * 32 + (g & 1) * 16;
                ldsm4(bh[p], kbuf + (uint32_t)(brow * RS + bcolb));
            }
#pragma unroll
            for (int tn = 0; tn < 8; tn++) {
                uint32_t b0 = bh[tn >> 1][(tn & 1) * 2], b1 = bh[tn >> 1][(tn & 1) * 2 + 1];
                mma16816(c[tn], ahi[kc], b0, b1);
                mma16816(c[tn], alo[kc], b0, b1);
            }
        }

        // ---- online softmax (exp2, MUFU) ----
        float mx0 = -1e30f, mx1 = -1e30f;
#pragma unroll
        for (int tn = 0; tn < 8; tn++) {
            mx0 = fmaxf(mx0, fmaxf(c[tn][0], c[tn][1]));
            mx1 = fmaxf(mx1, fmaxf(c[tn][2], c[tn][3]));
        }
        mx0 = fmaxf(mx0, __shfl_xor_sync(0xffffffffu, mx0, 1));
        mx0 = fmaxf(mx0, __shfl_xor_sync(0xffffffffu, mx0, 2));
        mx1 = fmaxf(mx1, __shfl_xor_sync(0xffffffffu, mx1, 1));
        mx1 = fmaxf(mx1, __shfl_xor_sync(0xffffffffu, mx1, 2));
        float mn0 = fmaxf(m0, mx0), mn1 = fmaxf(m1, mx1);
        float al0 = fexp2(m0 - mn0), al1 = fexp2(m1 - mn1);
        m0 = mn0; m1 = mn1;

        float s0 = 0.0f, s1 = 0.0f;
#pragma unroll
        for (int tn = 0; tn < 8; tn++) {
            c[tn][0] = fexp2(c[tn][0] - mn0);
            c[tn][1] = fexp2(c[tn][1] - mn0);
            c[tn][2] = fexp2(c[tn][2] - mn1);
            c[tn][3] = fexp2(c[tn][3] - mn1);
            s0 += c[tn][0] + c[tn][1];
            s1 += c[tn][2] + c[tn][3];
        }
        s0 += __shfl_xor_sync(0xffffffffu, s0, 1);
        s0 += __shfl_xor_sync(0xffffffffu, s0, 2);
        s1 += __shfl_xor_sync(0xffffffffu, s1, 1);
        s1 += __shfl_xor_sync(0xffffffffu, s1, 2);
        l0 = l0 * al0 + s0;
        l1 = l1 * al1 + s1;
#pragma unroll
        for (int nd = 0; nd < 8; nd++) {
            o[nd][0] *= al0; o[nd][1] *= al0;
            o[nd][2] *= al1; o[nd][3] *= al1;
        }

        // ---- O += P V (P single-pass fp16, V single) ----
#pragma unroll
        for (int kc = 0; kc < 4; kc++) {
            uint32_t phi[4];
            phi[0] = packh(c[2 * kc][0],     c[2 * kc][1]);
            phi[1] = packh(c[2 * kc][2],     c[2 * kc][3]);
            phi[2] = packh(c[2 * kc + 1][0], c[2 * kc + 1][1]);
            phi[3] = packh(c[2 * kc + 1][2], c[2 * kc + 1][3]);
#pragma unroll
            for (int dp = 0; dp < 4; dp++) {
                int vrow = kc * 16 + (g & 1) * 8 + l7;
                int vcolb = dp * 32 + (g >> 1) * 16;
                uint32_t vh[4];
                ldsm4t(vh, kbuf + OV + (uint32_t)(vrow * RS + vcolb));
                mma16816(o[dp * 2],     phi, vh[0], vh[1]);
                mma16816(o[dp * 2 + 1], phi, vh[2], vh[3]);
            }
        }

        __syncthreads();
        if (t + 2 < 32) load_kv(t + 2, t & 1);
        if (t + 1 < 32) {
            if (t + 2 < 32) { asm volatile("cp.async.wait_group 1;"); }
            else            { asm volatile("cp.async.wait_group 0;"); }
            __syncthreads();
        }
    }

    // ---- epilogue: normalize + fp16 hi/lo into [M,1024] ----
    const float inv0 = 1.0f / l0, inv1 = 1.0f / l1;
    const int r0 = q0 + wid * 16 + (lane >> 2);
    const size_t m0i = (size_t)(b * 2048) + r0;
    const int colb = h * 64 + (lane & 3) * 2;
#pragma unroll
    for (int nd = 0; nd < 8; nd++) {
        uint32_t hi, lo;
        split2h(o[nd][0] * inv0, o[nd][1] * inv0, hi, lo);
        *reinterpret_cast<uint32_t*>(&g_ahi[m0i * 1024 + colb + nd * 8]) = hi;
        *reinterpret_cast<uint32_t*>(&g_alo[m0i * 1024 + colb + nd * 8]) = lo;
        split2h(o[nd][2] * inv1, o[nd][3] * inv1, hi, lo);
        *reinterpret_cast<uint32_t*>(&g_ahi[(m0i + 8) * 1024 + colb + nd * 8]) = hi;
        *reinterpret_cast<uint32_t*>(&g_alo[(m0i + 8) * 1024 + colb + nd * 8]) = lo;
    }
}

// ---------------------------------------------------------------------------
// Launch
// ---------------------------------------------------------------------------
extern "C" void kernel_launch(void* const* d_in, const int* in_sizes, int n_in,
                              void* d_out, int out_size)
{
    const float* x      = (const float*)d_in[0];
    const float* qkv_w  = (const float*)d_in[1];
    const float* qkv_b  = (const float*)d_in[2];
    const float* qn_w   = (const float*)d_in[3];
    const float* kn_w   = (const float*)d_in[4];
    const float* proj_w = (const float*)d_in[5];
    const float* proj_b = (const float*)d_in[6];
    float* out = (float*)d_out;

    const int gemm_smem = 2 * STAGE_B;   // 61440
    cudaFuncSetAttribute(gemm_mma, cudaFuncAttributeMaxDynamicSharedMemorySize, gemm_smem);
    cudaFuncSetAttribute(attn_mma, cudaFuncAttributeMaxDynamicSharedMemorySize, ATTN_SMEM);

    void *p_qkv, *p_xhi, *p_xlo, *p_w1h, *p_w2h, *p_ahi, *p_alo;
    cudaGetSymbolAddress(&p_qkv, g_qkv);
    cudaGetSymbolAddress(&p_xhi, g_xhi);   cudaGetSymbolAddress(&p_xlo, g_xlo);
    cudaGetSymbolAddress(&p_w1h, g_w1h);   cudaGetSymbolAddress(&p_w2h, g_w2h);
    cudaGetSymbolAddress(&p_ahi, g_ahi);   cudaGetSymbolAddress(&p_alo, g_alo);

    rope_table<<<128, 256>>>();

    split_fp16<<<(M_ * C_ / 4 + 255) / 256, 256>>>((const float4*)x, (uint2*)p_xhi, (uint2*)p_xlo, M_ * C_ / 4);
    cvt_fp16<<<(K3_ * C_ / 4 + 255) / 256, 256>>>((const float4*)qkv_w, (uint2*)p_w1h, K3_ * C_ / 4);
    cvt_fp16<<<(C_ * C_ / 4 + 255) / 256, 256>>>((const float4*)proj_w, (uint2*)p_w2h, C_ * C_ / 4);

    // 1. QKV projection -> g_qkv [M, 3072]
    gemm_mma<<<dim3(K3_ / 128, M_ / 128), 256, gemm_smem>>>(
        (const __half*)p_xhi, (const __half*)p_xlo, (const __half*)p_w1h,
        qkv_b, (float*)p_qkv, K3_);

    // 2. RMSNorm + RoPE + fp16 emit (Q pre-scaled to log2 domain), head-major
    norm_rope<<<dim3((B_ * H_ * N_) / 8, 3), 256>>>(qn_w, kn_w);

    // 3. Tensor-core flash attention -> g_ahi/g_alo [M,1024]
    attn_mma<<<dim3(N_ / 128, H_, B_), 256, ATTN_SMEM>>>();

    // 4. Output projection -> d_out
    gemm_mma<<<dim3(C_ / 128, M_ / 128), 256, gemm_smem>>>(
        (const __half*)p_ahi, (const __half*)p_alo, (const __half*)p_w2h,
        proj_b, out, C_);
}

// round 8
// speedup vs baseline: 4.4574x; 1.0500x over previous
#include <cuda_runtime.h>
#include <cuda_bf16.h>
#include <cuda_fp16.h>
#include <cstdint>
#include <math.h>

// Problem constants
#define B_  2
#define N_  2048
#define C_  1024
#define H_  16
#define D_  64
#define M_  (B_ * N_)        // 4096
#define K3_ (3 * C_)         // 3072

// ---------------------------------------------------------------------------
// Scratch (device globals)
// ---------------------------------------------------------------------------
__device__ __half g_xhi[M_ * C_],  g_xlo[M_ * C_];     // x split
__device__ __half g_w1h[K3_ * C_];                     // qkv_w single fp16
__device__ __half g_w2h[C_ * C_];                      // proj_w single fp16
__device__ __half g_ahi[M_ * C_],  g_alo[M_ * C_];     // attention out split
// head-major [b*16+h][n][64]
__device__ __half g_qhi[B_*H_*N_*D_], g_qlo[B_*H_*N_*D_];   // Q split (pre-scaled)
__device__ __half g_k[B_*H_*N_*D_];                         // K single
__device__ __half g_v[B_*H_*N_*D_];                         // V single
__device__ float g_cos[1024 * 32], g_sin[1024 * 32];

// ---------------------------------------------------------------------------
// Helpers
// ---------------------------------------------------------------------------
__device__ __forceinline__ uint32_t smem_u32(const void* p) {
    uint32_t a;
    asm("{ .reg .u64 t; cvta.to.shared.u64 t, %1; cvt.u32.u64 %0, t; }" : "=r"(a) : "l"(p));
    return a;
}
__device__ __forceinline__ void ldsm4(uint32_t* r, uint32_t addr) {
    asm volatile("ldmatrix.sync.aligned.m8n8.x4.shared.b16 {%0,%1,%2,%3}, [%4];"
                 : "=r"(r[0]), "=r"(r[1]), "=r"(r[2]), "=r"(r[3]) : "r"(addr));
}
__device__ __forceinline__ void ldsm4t(uint32_t* r, uint32_t addr) {
    asm volatile("ldmatrix.sync.aligned.m8n8.x4.trans.shared.b16 {%0,%1,%2,%3}, [%4];"
                 : "=r"(r[0]), "=r"(r[1]), "=r"(r[2]), "=r"(r[3]) : "r"(addr));
}
__device__ __forceinline__ void mma16816(float* c, const uint32_t* a, uint32_t b0, uint32_t b1) {
    asm volatile("mma.sync.aligned.m16n8k16.row.col.f32.f16.f16.f32 "
                 "{%0,%1,%2,%3}, {%4,%5,%6,%7}, {%8,%9}, {%0,%1,%2,%3};"
                 : "+f"(c[0]), "+f"(c[1]), "+f"(c[2]), "+f"(c[3])
                 : "r"(a[0]), "r"(a[1]), "r"(a[2]), "r"(a[3]), "r"(b0), "r"(b1));
}
__device__ __forceinline__ uint32_t packh(float a, float b) {
    uint32_t r;
    asm("cvt.rn.f16x2.f32 %0, %1, %2;" : "=r"(r) : "f"(b), "f"(a));
    return r;
}
__device__ __forceinline__ void split2h(float a, float b, uint32_t& hi, uint32_t& lo) {
    uint32_t h = packh(a, b);
    __half2 hh = *reinterpret_cast<__half2*>(&h);
    float2 hf = __half22float2(hh);
    hi = h;
    lo = packh(a - hf.x, b - hf.y);
}
__device__ __forceinline__ float fexp2(float x) {
    float r;
    asm("ex2.approx.f32 %0, %1;" : "=f"(r) : "f"(x));
    return r;
}

#define QSCALE 0.1803368801111137f   // 0.125 * log2(e)

// ---------------------------------------------------------------------------
// fp32 -> fp16 hi + lo split / single convert
// ---------------------------------------------------------------------------
__global__ __launch_bounds__(256) void split_fp16(const float4* __restrict__ src,
                                                  uint2* __restrict__ hi,
                                                  uint2* __restrict__ lo, int n4)
{
    int i = blockIdx.x * 256 + threadIdx.x;
    if (i >= n4) return;
    float4 v = src[i];
    uint32_t h0, l0, h1, l1;
    split2h(v.x, v.y, h0, l0);
    split2h(v.z, v.w, h1, l1);
    hi[i] = make_uint2(h0, h1);
    lo[i] = make_uint2(l0, l1);
}
__global__ __launch_bounds__(256) void cvt_fp16(const float4* __restrict__ src,
                                                uint2* __restrict__ dst, int n4)
{
    int i = blockIdx.x * 256 + threadIdx.x;
    if (i >= n4) return;
    float4 v = src[i];
    dst[i] = make_uint2(packh(v.x, v.y), packh(v.z, v.w));
}

// ---------------------------------------------------------------------------
// RoPE tables
// ---------------------------------------------------------------------------
__global__ __launch_bounds__(256) void rope_table()
{
    int idx = blockIdx.x * 256 + threadIdx.x;          // 32768
    int pos = idx >> 5, lane = idx & 31;
    float e = (float)(2 * lane) * (1.0f / 64.0f);
    float inv = expf(-9.210340371976184f * e);
    float ang = (float)pos * inv;
    g_cos[idx] = cosf(ang);
    g_sin[idx] = sinf(ang);
}

// ---------------------------------------------------------------------------
// Shared GEMM config (block 128x128, K=1024, chunk 32, 8 warps 4x2)
// ---------------------------------------------------------------------------
#define STAGE_B 30720

// ---------------------------------------------------------------------------
// QKV GEMM with FUSED RMSNorm + RoPE + fp16 head-major emit.
// ---------------------------------------------------------------------------
__global__ __launch_bounds__(256, 2) void gemm_qkv_fused(
    const __half* __restrict__ Ahi, const __half* __restrict__ Alo,
    const __half* __restrict__ Bh, const float* __restrict__ bias,
    const float* __restrict__ qn_w, const float* __restrict__ kn_w)
{
    extern __shared__ char sm[];
    const uint32_t sbase = smem_u32(sm);
    const int tid = threadIdx.x;
    const int lane = tid & 31;
    const int wid = tid >> 5;
    const int warp_m = wid >> 1;
    const int warp_n = wid & 1;
    const int row0 = blockIdx.y * 128;
    const int col0 = blockIdx.x * 128;

    float acc[2][8][4];
#pragma unroll
    for (int a = 0; a < 2; a++)
#pragma unroll
        for (int b = 0; b < 8; b++)
#pragma unroll
            for (int c = 0; c < 4; c++) acc[a][b][c] = 0.0f;

    const __half* srcs[3] = {
        Ahi + (size_t)row0 * 1024, Alo + (size_t)row0 * 1024,
        Bh + (size_t)col0 * 1024 };

    auto load_stage = [&](int c, int buf) {
#pragma unroll
        for (int i = 0; i < 6; i++) {
            int lin = tid + i * 256;
            int mat = lin >> 9;
            int rem = lin & 511;
            int row = rem >> 2;
            int ch = rem & 3;
            const __half* s = srcs[mat] + (size_t)row * 1024 + c * 32 + ch * 8;
            uint32_t d = sbase + buf * STAGE_B + mat * 10240 + (uint32_t)(row * 40 + ch * 8) * 2;
            asm volatile("cp.async.cg.shared.global [%0], [%1], 16;" :: "r"(d), "l"(s));
        }
        asm volatile("cp.async.commit_group;");
    };

    load_stage(0, 0);
    for (int c = 0; c < 32; c++) {
        const int buf = c & 1;
        if (c + 1 < 32) { load_stage(c + 1, buf ^ 1); asm volatile("cp.async.wait_group 1;"); }
        else            { asm volatile("cp.async.wait_group 0;"); }
        __syncthreads();
        const uint32_t base = sbase + buf * STAGE_B;
#pragma unroll
        for (int kk = 0; kk < 2; kk++) {
            uint32_t ah[2][4], al[2][4], bh[4][4];
            int arow = warp_m * 32 + (lane & 15);
            int acol = kk * 16 + (lane >> 4) * 8;
            uint32_t aoff = (uint32_t)(arow * 40 + acol) * 2;
            ldsm4(ah[0], base + aoff);
            ldsm4(ah[1], base + aoff + 1280);
            ldsm4(al[0], base + 10240 + aoff);
            ldsm4(al[1], base + 10240 + aoff + 1280);
            int g = lane >> 3, l7 = lane & 7;
#pragma unroll
            for (int p = 0; p < 4; p++) {
                int brow = warp_n * 64 + (p * 2 + (g >> 1)) * 8 + l7;
                int bcol = kk * 16 + (g & 1) * 8;
                ldsm4(bh[p], base + 20480 + (uint32_t)(brow * 40 + bcol) * 2);
            }
#pragma unroll
            for (int tm = 0; tm < 2; tm++)
#pragma unroll
                for (int tn = 0; tn < 8; tn++) {
                    uint32_t b0 = bh[tn >> 1][(tn & 1) * 2], b1 = bh[tn >> 1][(tn & 1) * 2 + 1];
                    mma16816(acc[tm][tn], ah[tm], b0, b1);
                    mma16816(acc[tm][tn], al[tm], b0, b1);
                }
        }
        __syncthreads();
    }

    // ---- fused epilogue ----
    const int sec = col0 >> 10;                         // 0=q, 1=k, 2=v
    const int head = ((col0 & 1023) >> 6) + warp_n;
    const int d0 = (lane & 3) * 2;

    float bs[8][2], wv[8][2];
    const float* w = (sec == 1) ? kn_w : qn_w;
#pragma unroll
    for (int tn = 0; tn < 8; tn++) {
        int d = tn * 8 + d0;
        int col = col0 + warp_n * 64 + d;
        bs[tn][0] = __ldg(&bias[col]);
        bs[tn][1] = __ldg(&bias[col + 1]);
        if (sec < 2) { wv[tn][0] = __ldg(&w[d]); wv[tn][1] = __ldg(&w[d + 1]); }
    }

    auto process_row = [&](float v[8][2], int m) {
        const int n = m & 2047;
        const int bb = m >> 11;
        const size_t obase = (((size_t)(bb * 16 + head)) * 2048 + n) * 64;
        if (sec == 2) {
#pragma unroll
            for (int tn = 0; tn < 8; tn++)
                *reinterpret_cast<uint32_t*>(&g_v[obase + tn * 8 + d0]) = packh(v[tn][0], v[tn][1]);
            return;
        }
        float ss = 0.0f;
#pragma unroll
        for (int tn = 0; tn < 8; tn++) ss += v[tn][0] * v[tn][0] + v[tn][1] * v[tn][1];
        ss += __shfl_xor_sync(0xffffffffu, ss, 1);
        ss += __shfl_xor_sync(0xffffffffu, ss, 2);
        float rs = rsqrtf(ss * (1.0f / 64.0f) + 1e-6f);
#pragma unroll
        for (int tn = 0; tn < 8; tn++) {
            v[tn][0] *= rs * wv[tn][0];
            v[tn][1] *= rs * wv[tn][1];
        }
        int pos = (n < 1024) ? n : ((n < 1536) ? (n - 1024) : -1);
        if (pos >= 0) {
#pragma unroll
            for (int tn = 0; tn < 4; tn++) {
                int idx = pos * 32 + tn * 8 + d0;
#pragma unroll
                for (int j = 0; j < 2; j++) {
                    float cs = g_cos[idx + j], sn = g_sin[idx + j];
                    float t1 = v[tn][j], t2 = v[tn + 4][j];
                    v[tn][j]     = t1 * cs - t2 * sn;
                    v[tn + 4][j] = t2 * cs + t1 * sn;
                }
            }
        }
        if (sec == 0) {
#pragma unroll
            for (int tn = 0; tn < 8; tn++) {
                uint32_t hi, lo;
                split2h(v[tn][0] * QSCALE, v[tn][1] * QSCALE, hi, lo);
                *reinterpret_cast<uint32_t*>(&g_qhi[obase + tn * 8 + d0]) = hi;
                *reinterpret_cast<uint32_t*>(&g_qlo[obase + tn * 8 + d0]) = lo;
            }
        } else {
#pragma unroll
            for (int tn = 0; tn < 8; tn++)
                *reinterpret_cast<uint32_t*>(&g_k[obase + tn * 8 + d0]) = packh(v[tn][0], v[tn][1]);
        }
    };

#pragma unroll
    for (int tm = 0; tm < 2; tm++) {
        const int mA = row0 + warp_m * 32 + tm * 16 + (lane >> 2);
        float vA[8][2], vB[8][2];
#pragma unroll
        for (int tn = 0; tn < 8; tn++) {
            vA[tn][0] = acc[tm][tn][0] + bs[tn][0];
            vA[tn][1] = acc[tm][tn][1] + bs[tn][1];
            vB[tn][0] = acc[tm][tn][2] + bs[tn][0];
            vB[tn][1] = acc[tm][tn][3] + bs[tn][1];
        }
        process_row(vA, mA);
        process_row(vB, mA + 8);
    }
}

// ---------------------------------------------------------------------------
// Generic fp16 2-pass GEMM (proj): out = (Ahi+Alo).B^T + bias
// ---------------------------------------------------------------------------
__global__ __launch_bounds__(256, 2) void gemm_mma(
    const __half* __restrict__ Ahi, const __half* __restrict__ Alo,
    const __half* __restrict__ Bh,
    const float* __restrict__ bias, float* __restrict__ out, int ostride)
{
    extern __shared__ char sm[];
    const uint32_t sbase = smem_u32(sm);
    const int tid = threadIdx.x;
    const int lane = tid & 31;
    const int wid = tid >> 5;
    const int warp_m = wid >> 1;
    const int warp_n = wid & 1;
    const int row0 = blockIdx.y * 128;
    const int col0 = blockIdx.x * 128;

    float acc[2][8][4];
#pragma unroll
    for (int a = 0; a < 2; a++)
#pragma unroll
        for (int b = 0; b < 8; b++)
#pragma unroll
            for (int c = 0; c < 4; c++) acc[a][b][c] = 0.0f;

    const __half* srcs[3] = {
        Ahi + (size_t)row0 * 1024, Alo + (size_t)row0 * 1024,
        Bh + (size_t)col0 * 1024 };

    auto load_stage = [&](int c, int buf) {
#pragma unroll
        for (int i = 0; i < 6; i++) {
            int lin = tid + i * 256;
            int mat = lin >> 9;
            int rem = lin & 511;
            int row = rem >> 2;
            int ch = rem & 3;
            const __half* s = srcs[mat] + (size_t)row * 1024 + c * 32 + ch * 8;
            uint32_t d = sbase + buf * STAGE_B + mat * 10240 + (uint32_t)(row * 40 + ch * 8) * 2;
            asm volatile("cp.async.cg.shared.global [%0], [%1], 16;" :: "r"(d), "l"(s));
        }
        asm volatile("cp.async.commit_group;");
    };

    load_stage(0, 0);
    for (int c = 0; c < 32; c++) {
        const int buf = c & 1;
        if (c + 1 < 32) { load_stage(c + 1, buf ^ 1); asm volatile("cp.async.wait_group 1;"); }
        else            { asm volatile("cp.async.wait_group 0;"); }
        __syncthreads();
        const uint32_t base = sbase + buf * STAGE_B;
#pragma unroll
        for (int kk = 0; kk < 2; kk++) {
            uint32_t ah[2][4], al[2][4], bh[4][4];
            int arow = warp_m * 32 + (lane & 15);
            int acol = kk * 16 + (lane >> 4) * 8;
            uint32_t aoff = (uint32_t)(arow * 40 + acol) * 2;
            ldsm4(ah[0], base + aoff);
            ldsm4(ah[1], base + aoff + 1280);
            ldsm4(al[0], base + 10240 + aoff);
            ldsm4(al[1], base + 10240 + aoff + 1280);
            int g = lane >> 3, l7 = lane & 7;
#pragma unroll
            for (int p = 0; p < 4; p++) {
                int brow = warp_n * 64 + (p * 2 + (g >> 1)) * 8 + l7;
                int bcol = kk * 16 + (g & 1) * 8;
                ldsm4(bh[p], base + 20480 + (uint32_t)(brow * 40 + bcol) * 2);
            }
#pragma unroll
            for (int tm = 0; tm < 2; tm++)
#pragma unroll
                for (int tn = 0; tn < 8; tn++) {
                    uint32_t b0 = bh[tn >> 1][(tn & 1) * 2], b1 = bh[tn >> 1][(tn & 1) * 2 + 1];
                    mma16816(acc[tm][tn], ah[tm], b0, b1);
                    mma16816(acc[tm][tn], al[tm], b0, b1);
                }
        }
        __syncthreads();
    }

#pragma unroll
    for (int tm = 0; tm < 2; tm++) {
        int mb = row0 + warp_m * 32 + tm * 16 + (lane >> 2);
#pragma unroll
        for (int tn = 0; tn < 8; tn++) {
            int col = col0 + warp_n * 64 + tn * 8 + (lane & 3) * 2;
            float b0 = __ldg(&bias[col]), b1 = __ldg(&bias[col + 1]);
            *reinterpret_cast<float2*>(&out[(size_t)mb * ostride + col]) =
                make_float2(acc[tm][tn][0] + b0, acc[tm][tn][1] + b1);
            *reinterpret_cast<float2*>(&out[(size_t)(mb + 8) * ostride + col]) =
                make_float2(acc[tm][tn][2] + b0, acc[tm][tn][3] + b1);
        }
    }
}

// ---------------------------------------------------------------------------
// Flash attention (mma.sync fp16). Q staged through the KV buffers (smem
// reuse -> 36.9KB -> 2 CTAs/SM). Q 2-pass, P/V single-pass, MUFU exp2.
// ---------------------------------------------------------------------------
#define RS   144
#define BUFB 18432                // per KV buffer: K 9216 + V 9216
#define OV   9216
#define ATTN_SMEM (2 * BUFB)      // 36864

__global__ __launch_bounds__(256, 2) void attn_mma()
{
    extern __shared__ char sm[];
    const uint32_t sbase = smem_u32(sm);
    const int tid = threadIdx.x;
    const int lane = tid & 31;
    const int wid = tid >> 5;
    const int q0 = blockIdx.x * 128;
    const int h = blockIdx.y;
    const int b = blockIdx.z;
    const size_t hb = ((size_t)(b * 16 + h)) * 2048 * 64;

    const __half* qhi_g = g_qhi + hb + (size_t)q0 * 64;
    const __half* qlo_g = g_qlo + hb + (size_t)q0 * 64;
    const __half* k_g = g_k + hb;
    const __half* v_g = g_v + hb;

    // ---- stage Q through the (future) KV buffers, hoist to registers ----
    {
#pragma unroll
        for (int i = 0; i < 8; i++) {
            int lin = tid + i * 256;
            int mat = lin >> 10;              // 0=hi -> buf0, 1=lo -> buf1
            int rem = lin & 1023;
            int row = rem >> 3;
            int ch = rem & 7;
            const __half* s = (mat ? qlo_g : qhi_g) + (size_t)row * 64 + ch * 8;
            uint32_t d = sbase + mat * BUFB + (uint32_t)(row * RS + ch * 16);
            asm volatile("cp.async.cg.shared.global [%0], [%1], 16;" :: "r"(d), "l"(s));
        }
        asm volatile("cp.async.commit_group;");
        asm volatile("cp.async.wait_group 0;");
        __syncthreads();
    }

    uint32_t ahi[4][4], alo[4][4];
    {
        const int arow = wid * 16 + (lane & 15);
        const int acolb = (lane >> 4) * 16;
#pragma unroll
        for (int kc = 0; kc < 4; kc++) {
            uint32_t off = (uint32_t)(arow * RS + kc * 32 + acolb);
            ldsm4(ahi[kc], sbase + off);
            ldsm4(alo[kc], sbase + BUFB + off);
        }
    }
    __syncthreads();   // all warps hoisted before KV overwrites Q

    auto load_kv = [&](int t, int buf) {
        const uint32_t dbase = sbase + buf * BUFB;
#pragma unroll
        for (int i = 0; i < 4; i++) {
            int lin = tid + i * 256;
            int mat = lin >> 9;
            int rem = lin & 511;
            int row = rem >> 3;
            int ch = rem & 7;
            const __half* s = (mat ? v_g : k_g) + (size_t)t * 64 * 64 + (size_t)row * 64 + ch * 8;
            uint32_t d = dbase + mat * OV + (uint32_t)(row * RS + ch * 16);
            asm volatile("cp.async.cg.shared.global [%0], [%1], 16;" :: "r"(d), "l"(s));
        }
        asm volatile("cp.async.commit_group;");
    };

    load_kv(0, 0);
    load_kv(1, 1);
    asm volatile("cp.async.wait_group 1;");
    __syncthreads();

    float m0 = -1e30f, m1 = -1e30f, l0 = 0.0f, l1 = 0.0f;
    float o[8][4];
#pragma unroll
    for (int nd = 0; nd < 8; nd++)
#pragma unroll
        for (int j = 0; j < 4; j++) o[nd][j] = 0.0f;

    const int g = lane >> 3, l7 = lane & 7;

    for (int t = 0; t < 32; t++) {
        const uint32_t kbuf = sbase + (t & 1) * BUFB;

        // ---- S = Q K^T (2-pass), logits in log2 domain ----
        float c[8][4];
#pragma unroll
        for (int tn = 0; tn < 8; tn++)
#pragma unroll
            for (int j = 0; j < 4; j++) c[tn][j] = 0.0f;

#pragma unroll
        for (int kc = 0; kc < 4; kc++) {
            uint32_t bh[4][4];
#pragma unroll
            for (int p = 0; p < 4; p++) {
                int brow = (p * 2 + (g >> 1)) * 8 + l7;
                int bcolb = kc * 32 + (g & 1) * 16;
                ldsm4(bh[p], kbuf + (uint32_t)(brow * RS + bcolb));
            }
#pragma unroll
            for (int tn = 0; tn < 8; tn++) {
                uint32_t b0 = bh[tn >> 1][(tn & 1) * 2], b1 = bh[tn >> 1][(tn & 1) * 2 + 1];
                mma16816(c[tn], ahi[kc], b0, b1);
                mma16816(c[tn], alo[kc], b0, b1);
            }
        }

        // ---- online softmax (MUFU exp2) ----
        float mx0 = -1e30f, mx1 = -1e30f;
#pragma unroll
        for (int tn = 0; tn < 8; tn++) {
            mx0 = fmaxf(mx0, fmaxf(c[tn][0], c[tn][1]));
            mx1 = fmaxf(mx1, fmaxf(c[tn][2], c[tn][3]));
        }
        mx0 = fmaxf(mx0, __shfl_xor_sync(0xffffffffu, mx0, 1));
        mx0 = fmaxf(mx0, __shfl_xor_sync(0xffffffffu, mx0, 2));
        mx1 = fmaxf(mx1, __shfl_xor_sync(0xffffffffu, mx1, 1));
        mx1 = fmaxf(mx1, __shfl_xor_sync(0xffffffffu, mx1, 2));
        float mn0 = fmaxf(m0, mx0), mn1 = fmaxf(m1, mx1);
        float al0 = fexp2(m0 - mn0), al1 = fexp2(m1 - mn1);
        m0 = mn0; m1 = mn1;

        float s0 = 0.0f, s1 = 0.0f;
#pragma unroll
        for (int tn = 0; tn < 8; tn++) {
            c[tn][0] = fexp2(c[tn][0] - mn0);
            c[tn][1] = fexp2(c[tn][1] - mn0);
            c[tn][2] = fexp2(c[tn][2] - mn1);
            c[tn][3] = fexp2(c[tn][3] - mn1);
            s0 += c[tn][0] + c[tn][1];
            s1 += c[tn][2] + c[tn][3];
        }
        s0 += __shfl_xor_sync(0xffffffffu, s0, 1);
        s0 += __shfl_xor_sync(0xffffffffu, s0, 2);
        s1 += __shfl_xor_sync(0xffffffffu, s1, 1);
        s1 += __shfl_xor_sync(0xffffffffu, s1, 2);
        l0 = l0 * al0 + s0;
        l1 = l1 * al1 + s1;
#pragma unroll
        for (int nd = 0; nd < 8; nd++) {
            o[nd][0] *= al0; o[nd][1] *= al0;
            o[nd][2] *= al1; o[nd][3] *= al1;
        }

        // ---- O += P V ----
#pragma unroll
        for (int kc = 0; kc < 4; kc++) {
            uint32_t phi[4];
            phi[0] = packh(c[2 * kc][0],     c[2 * kc][1]);
            phi[1] = packh(c[2 * kc][2],     c[2 * kc][3]);
            phi[2] = packh(c[2 * kc + 1][0], c[2 * kc + 1][1]);
            phi[3] = packh(c[2 * kc + 1][2], c[2 * kc + 1][3]);
#pragma unroll
            for (int dp = 0; dp < 4; dp++) {
                int vrow = kc * 16 + (g & 1) * 8 + l7;
                int vcolb = dp * 32 + (g >> 1) * 16;
                uint32_t vh[4];
                ldsm4t(vh, kbuf + OV + (uint32_t)(vrow * RS + vcolb));
                mma16816(o[dp * 2],     phi, vh[0], vh[1]);
                mma16816(o[dp * 2 + 1], phi, vh[2], vh[3]);
            }
        }

        __syncthreads();
        if (t + 2 < 32) load_kv(t + 2, t & 1);
        if (t + 1 < 32) {
            if (t + 2 < 32) { asm volatile("cp.async.wait_group 1;"); }
            else            { asm volatile("cp.async.wait_group 0;"); }
            __syncthreads();
        }
    }

    // ---- epilogue: normalize + fp16 hi/lo into [M,1024] ----
    const float inv0 = 1.0f / l0, inv1 = 1.0f / l1;
    const int r0 = q0 + wid * 16 + (lane >> 2);
    const size_t m0i = (size_t)(b * 2048) + r0;
    const int colb = h * 64 + (lane & 3) * 2;
#pragma unroll
    for (int nd = 0; nd < 8; nd++) {
        uint32_t hi, lo;
        split2h(o[nd][0] * inv0, o[nd][1] * inv0, hi, lo);
        *reinterpret_cast<uint32_t*>(&g_ahi[m0i * 1024 + colb + nd * 8]) = hi;
        *reinterpret_cast<uint32_t*>(&g_alo[m0i * 1024 + colb + nd * 8]) = lo;
        split2h(o[nd][2] * inv1, o[nd][3] * inv1, hi, lo);
        *reinterpret_cast<uint32_t*>(&g_ahi[(m0i + 8) * 1024 + colb + nd * 8]) = hi;
        *reinterpret_cast<uint32_t*>(&g_alo[(m0i + 8) * 1024 + colb + nd * 8]) = lo;
    }
}

// ---------------------------------------------------------------------------
// Launch
// ---------------------------------------------------------------------------
extern "C" void kernel_launch(void* const* d_in, const int* in_sizes, int n_in,
                              void* d_out, int out_size)
{
    const float* x      = (const float*)d_in[0];
    const float* qkv_w  = (const float*)d_in[1];
    const float* qkv_b  = (const float*)d_in[2];
    const float* qn_w   = (const float*)d_in[3];
    const float* kn_w   = (const float*)d_in[4];
    const float* proj_w = (const float*)d_in[5];
    const float* proj_b = (const float*)d_in[6];
    float* out = (float*)d_out;

    const int gemm_smem = 2 * STAGE_B;   // 61440
    cudaFuncSetAttribute(gemm_qkv_fused, cudaFuncAttributeMaxDynamicSharedMemorySize, gemm_smem);
    cudaFuncSetAttribute(gemm_mma, cudaFuncAttributeMaxDynamicSharedMemorySize, gemm_smem);
    cudaFuncSetAttribute(attn_mma, cudaFuncAttributeMaxDynamicSharedMemorySize, ATTN_SMEM);

    void *p_xhi, *p_xlo, *p_w1h, *p_w2h, *p_ahi, *p_alo;
    cudaGetSymbolAddress(&p_xhi, g_xhi);   cudaGetSymbolAddress(&p_xlo, g_xlo);
    cudaGetSymbolAddress(&p_w1h, g_w1h);   cudaGetSymbolAddress(&p_w2h, g_w2h);
    cudaGetSymbolAddress(&p_ahi, g_ahi);   cudaGetSymbolAddress(&p_alo, g_alo);

    rope_table<<<128, 256>>>();

    split_fp16<<<(M_ * C_ / 4 + 255) / 256, 256>>>((const float4*)x, (uint2*)p_xhi, (uint2*)p_xlo, M_ * C_ / 4);
    cvt_fp16<<<(K3_ * C_ / 4 + 255) / 256, 256>>>((const float4*)qkv_w, (uint2*)p_w1h, K3_ * C_ / 4);
    cvt_fp16<<<(C_ * C_ / 4 + 255) / 256, 256>>>((const float4*)proj_w, (uint2*)p_w2h, C_ * C_ / 4);

    // 1. QKV projection + fused RMSNorm/RoPE/fp16 emit (head-major q/k/v)
    gemm_qkv_fused<<<dim3(K3_ / 128, M_ / 128), 256, gemm_smem>>>(
        (const __half*)p_xhi, (const __half*)p_xlo, (const __half*)p_w1h,
        qkv_b, qn_w, kn_w);

    // 2. Tensor-core flash attention -> g_ahi/g_alo [M,1024]
    attn_mma<<<dim3(N_ / 128, H_, B_), 256, ATTN_SMEM>>>();

    // 3. Output projection -> d_out
    gemm_mma<<<dim3(C_ / 128, M_ / 128), 256, gemm_smem>>>(
        (const __half*)p_ahi, (const __half*)p_alo, (const __half*)p_w2h,
        proj_b, out, C_);
}

// round 9
// speedup vs baseline: 4.9738x; 1.1158x over previous
#include <cuda_runtime.h>
#include <cuda_bf16.h>
#include <cuda_fp16.h>
#include <cstdint>
#include <math.h>

// Problem constants
#define B_  2
#define N_  2048
#define C_  1024
#define H_  16
#define D_  64
#define M_  (B_ * N_)        // 4096
#define K3_ (3 * C_)         // 3072

// ---------------------------------------------------------------------------
// Scratch (device globals)
// ---------------------------------------------------------------------------
__device__ __half g_xhi[M_ * C_],  g_xlo[M_ * C_];     // x split
__device__ __half g_w1h[K3_ * C_];                     // qkv_w single fp16
__device__ __half g_w2h[C_ * C_];                      // proj_w single fp16
__device__ __half g_ahi[M_ * C_],  g_alo[M_ * C_];     // attention out split
// head-major [b*16+h][n][64]
__device__ __half g_q[B_*H_*N_*D_];                    // Q single (pre-scaled)
__device__ __half g_k[B_*H_*N_*D_];                    // K single
__device__ __half g_v[B_*H_*N_*D_];                    // V single
__device__ float g_cos[1024 * 32], g_sin[1024 * 32];

// ---------------------------------------------------------------------------
// Helpers
// ---------------------------------------------------------------------------
__device__ __forceinline__ uint32_t smem_u32(const void* p) {
    uint32_t a;
    asm("{ .reg .u64 t; cvta.to.shared.u64 t, %1; cvt.u32.u64 %0, t; }" : "=r"(a) : "l"(p));
    return a;
}
__device__ __forceinline__ void ldsm4(uint32_t* r, uint32_t addr) {
    asm volatile("ldmatrix.sync.aligned.m8n8.x4.shared.b16 {%0,%1,%2,%3}, [%4];"
                 : "=r"(r[0]), "=r"(r[1]), "=r"(r[2]), "=r"(r[3]) : "r"(addr));
}
__device__ __forceinline__ void ldsm4t(uint32_t* r, uint32_t addr) {
    asm volatile("ldmatrix.sync.aligned.m8n8.x4.trans.shared.b16 {%0,%1,%2,%3}, [%4];"
                 : "=r"(r[0]), "=r"(r[1]), "=r"(r[2]), "=r"(r[3]) : "r"(addr));
}
__device__ __forceinline__ void mma16816(float* c, const uint32_t* a, uint32_t b0, uint32_t b1) {
    asm volatile("mma.sync.aligned.m16n8k16.row.col.f32.f16.f16.f32 "
                 "{%0,%1,%2,%3}, {%4,%5,%6,%7}, {%8,%9}, {%0,%1,%2,%3};"
                 : "+f"(c[0]), "+f"(c[1]), "+f"(c[2]), "+f"(c[3])
                 : "r"(a[0]), "r"(a[1]), "r"(a[2]), "r"(a[3]), "r"(b0), "r"(b1));
}
__device__ __forceinline__ uint32_t packh(float a, float b) {
    uint32_t r;
    asm("cvt.rn.f16x2.f32 %0, %1, %2;" : "=r"(r) : "f"(b), "f"(a));
    return r;
}
__device__ __forceinline__ void split2h(float a, float b, uint32_t& hi, uint32_t& lo) {
    uint32_t h = packh(a, b);
    __half2 hh = *reinterpret_cast<__half2*>(&h);
    float2 hf = __half22float2(hh);
    hi = h;
    lo = packh(a - hf.x, b - hf.y);
}
__device__ __forceinline__ float fexp2(float x) {
    float r;
    asm("ex2.approx.f32 %0, %1;" : "=f"(r) : "f"(x));
    return r;
}

#define QSCALE 0.1803368801111137f   // 0.125 * log2(e)

// ---------------------------------------------------------------------------
// fp32 -> fp16 hi + lo split / single convert
// ---------------------------------------------------------------------------
__global__ __launch_bounds__(256) void split_fp16(const float4* __restrict__ src,
                                                  uint2* __restrict__ hi,
                                                  uint2* __restrict__ lo, int n4)
{
    int i = blockIdx.x * 256 + threadIdx.x;
    if (i >= n4) return;
    float4 v = src[i];
    uint32_t h0, l0, h1, l1;
    split2h(v.x, v.y, h0, l0);
    split2h(v.z, v.w, h1, l1);
    hi[i] = make_uint2(h0, h1);
    lo[i] = make_uint2(l0, l1);
}
__global__ __launch_bounds__(256) void cvt_fp16(const float4* __restrict__ src,
                                                uint2* __restrict__ dst, int n4)
{
    int i = blockIdx.x * 256 + threadIdx.x;
    if (i >= n4) return;
    float4 v = src[i];
    dst[i] = make_uint2(packh(v.x, v.y), packh(v.z, v.w));
}

// ---------------------------------------------------------------------------
// RoPE tables
// ---------------------------------------------------------------------------
__global__ __launch_bounds__(256) void rope_table()
{
    int idx = blockIdx.x * 256 + threadIdx.x;          // 32768
    int pos = idx >> 5, lane = idx & 31;
    float e = (float)(2 * lane) * (1.0f / 64.0f);
    float inv = expf(-9.210340371976184f * e);
    float ang = (float)pos * inv;
    g_cos[idx] = cosf(ang);
    g_sin[idx] = sinf(ang);
}

// ---------------------------------------------------------------------------
// Shared GEMM config (block 128x128, K=1024, chunk 32, 8 warps 4x2)
// ---------------------------------------------------------------------------
#define STAGE_B 30720

// ---------------------------------------------------------------------------
// QKV GEMM with FUSED RMSNorm + RoPE + fp16 head-major emit.
// Q emitted single-pass fp16 (pre-scaled by 0.125*log2e).
// ---------------------------------------------------------------------------
__global__ __launch_bounds__(256, 2) void gemm_qkv_fused(
    const __half* __restrict__ Ahi, const __half* __restrict__ Alo,
    const __half* __restrict__ Bh, const float* __restrict__ bias,
    const float* __restrict__ qn_w, const float* __restrict__ kn_w)
{
    extern __shared__ char sm[];
    const uint32_t sbase = smem_u32(sm);
    const int tid = threadIdx.x;
    const int lane = tid & 31;
    const int wid = tid >> 5;
    const int warp_m = wid >> 1;
    const int warp_n = wid & 1;
    const int row0 = blockIdx.y * 128;
    const int col0 = blockIdx.x * 128;

    float acc[2][8][4];
#pragma unroll
    for (int a = 0; a < 2; a++)
#pragma unroll
        for (int b = 0; b < 8; b++)
#pragma unroll
            for (int c = 0; c < 4; c++) acc[a][b][c] = 0.0f;

    const __half* srcs[3] = {
        Ahi + (size_t)row0 * 1024, Alo + (size_t)row0 * 1024,
        Bh + (size_t)col0 * 1024 };

    auto load_stage = [&](int c, int buf) {
#pragma unroll
        for (int i = 0; i < 6; i++) {
            int lin = tid + i * 256;
            int mat = lin >> 9;
            int rem = lin & 511;
            int row = rem >> 2;
            int ch = rem & 3;
            const __half* s = srcs[mat] + (size_t)row * 1024 + c * 32 + ch * 8;
            uint32_t d = sbase + buf * STAGE_B + mat * 10240 + (uint32_t)(row * 40 + ch * 8) * 2;
            asm volatile("cp.async.cg.shared.global [%0], [%1], 16;" :: "r"(d), "l"(s));
        }
        asm volatile("cp.async.commit_group;");
    };

    load_stage(0, 0);
    for (int c = 0; c < 32; c++) {
        const int buf = c & 1;
        if (c + 1 < 32) { load_stage(c + 1, buf ^ 1); asm volatile("cp.async.wait_group 1;"); }
        else            { asm volatile("cp.async.wait_group 0;"); }
        __syncthreads();
        const uint32_t base = sbase + buf * STAGE_B;
#pragma unroll
        for (int kk = 0; kk < 2; kk++) {
            uint32_t ah[2][4], al[2][4], bh[4][4];
            int arow = warp_m * 32 + (lane & 15);
            int acol = kk * 16 + (lane >> 4) * 8;
            uint32_t aoff = (uint32_t)(arow * 40 + acol) * 2;
            ldsm4(ah[0], base + aoff);
            ldsm4(ah[1], base + aoff + 1280);
            ldsm4(al[0], base + 10240 + aoff);
            ldsm4(al[1], base + 10240 + aoff + 1280);
            int g = lane >> 3, l7 = lane & 7;
#pragma unroll
            for (int p = 0; p < 4; p++) {
                int brow = warp_n * 64 + (p * 2 + (g >> 1)) * 8 + l7;
                int bcol = kk * 16 + (g & 1) * 8;
                ldsm4(bh[p], base + 20480 + (uint32_t)(brow * 40 + bcol) * 2);
            }
#pragma unroll
            for (int tm = 0; tm < 2; tm++)
#pragma unroll
                for (int tn = 0; tn < 8; tn++) {
                    uint32_t b0 = bh[tn >> 1][(tn & 1) * 2], b1 = bh[tn >> 1][(tn & 1) * 2 + 1];
                    mma16816(acc[tm][tn], ah[tm], b0, b1);
                    mma16816(acc[tm][tn], al[tm], b0, b1);
                }
        }
        __syncthreads();
    }

    // ---- fused epilogue ----
    const int sec = col0 >> 10;                         // 0=q, 1=k, 2=v
    const int head = ((col0 & 1023) >> 6) + warp_n;
    const int d0 = (lane & 3) * 2;

    float bs[8][2], wv[8][2];
    const float* w = (sec == 1) ? kn_w : qn_w;
#pragma unroll
    for (int tn = 0; tn < 8; tn++) {
        int d = tn * 8 + d0;
        int col = col0 + warp_n * 64 + d;
        bs[tn][0] = __ldg(&bias[col]);
        bs[tn][1] = __ldg(&bias[col + 1]);
        if (sec < 2) { wv[tn][0] = __ldg(&w[d]); wv[tn][1] = __ldg(&w[d + 1]); }
    }

    auto process_row = [&](float v[8][2], int m) {
        const int n = m & 2047;
        const int bb = m >> 11;
        const size_t obase = (((size_t)(bb * 16 + head)) * 2048 + n) * 64;
        if (sec == 2) {
#pragma unroll
            for (int tn = 0; tn < 8; tn++)
                *reinterpret_cast<uint32_t*>(&g_v[obase + tn * 8 + d0]) = packh(v[tn][0], v[tn][1]);
            return;
        }
        float ss = 0.0f;
#pragma unroll
        for (int tn = 0; tn < 8; tn++) ss += v[tn][0] * v[tn][0] + v[tn][1] * v[tn][1];
        ss += __shfl_xor_sync(0xffffffffu, ss, 1);
        ss += __shfl_xor_sync(0xffffffffu, ss, 2);
        float rs = rsqrtf(ss * (1.0f / 64.0f) + 1e-6f);
#pragma unroll
        for (int tn = 0; tn < 8; tn++) {
            v[tn][0] *= rs * wv[tn][0];
            v[tn][1] *= rs * wv[tn][1];
        }
        int pos = (n < 1024) ? n : ((n < 1536) ? (n - 1024) : -1);
        if (pos >= 0) {
#pragma unroll
            for (int tn = 0; tn < 4; tn++) {
                int idx = pos * 32 + tn * 8 + d0;
#pragma unroll
                for (int j = 0; j < 2; j++) {
                    float cs = g_cos[idx + j], sn = g_sin[idx + j];
                    float t1 = v[tn][j], t2 = v[tn + 4][j];
                    v[tn][j]     = t1 * cs - t2 * sn;
                    v[tn + 4][j] = t2 * cs + t1 * sn;
                }
            }
        }
        if (sec == 0) {
#pragma unroll
            for (int tn = 0; tn < 8; tn++)
                *reinterpret_cast<uint32_t*>(&g_q[obase + tn * 8 + d0]) =
                    packh(v[tn][0] * QSCALE, v[tn][1] * QSCALE);
        } else {
#pragma unroll
            for (int tn = 0; tn < 8; tn++)
                *reinterpret_cast<uint32_t*>(&g_k[obase + tn * 8 + d0]) = packh(v[tn][0], v[tn][1]);
        }
    };

#pragma unroll
    for (int tm = 0; tm < 2; tm++) {
        const int mA = row0 + warp_m * 32 + tm * 16 + (lane >> 2);
        float vA[8][2], vB[8][2];
#pragma unroll
        for (int tn = 0; tn < 8; tn++) {
            vA[tn][0] = acc[tm][tn][0] + bs[tn][0];
            vA[tn][1] = acc[tm][tn][1] + bs[tn][1];
            vB[tn][0] = acc[tm][tn][2] + bs[tn][0];
            vB[tn][1] = acc[tm][tn][3] + bs[tn][1];
        }
        process_row(vA, mA);
        process_row(vB, mA + 8);
    }
}

// ---------------------------------------------------------------------------
// Generic fp16 2-pass GEMM (proj): out = (Ahi+Alo).B^T + bias
// ---------------------------------------------------------------------------
__global__ __launch_bounds__(256, 2) void gemm_mma(
    const __half* __restrict__ Ahi, const __half* __restrict__ Alo,
    const __half* __restrict__ Bh,
    const float* __restrict__ bias, float* __restrict__ out, int ostride)
{
    extern __shared__ char sm[];
    const uint32_t sbase = smem_u32(sm);
    const int tid = threadIdx.x;
    const int lane = tid & 31;
    const int wid = tid >> 5;
    const int warp_m = wid >> 1;
    const int warp_n = wid & 1;
    const int row0 = blockIdx.y * 128;
    const int col0 = blockIdx.x * 128;

    float acc[2][8][4];
#pragma unroll
    for (int a = 0; a < 2; a++)
#pragma unroll
        for (int b = 0; b < 8; b++)
#pragma unroll
            for (int c = 0; c < 4; c++) acc[a][b][c] = 0.0f;

    const __half* srcs[3] = {
        Ahi + (size_t)row0 * 1024, Alo + (size_t)row0 * 1024,
        Bh + (size_t)col0 * 1024 };

    auto load_stage = [&](int c, int buf) {
#pragma unroll
        for (int i = 0; i < 6; i++) {
            int lin = tid + i * 256;
            int mat = lin >> 9;
            int rem = lin & 511;
            int row = rem >> 2;
            int ch = rem & 3;
            const __half* s = srcs[mat] + (size_t)row * 1024 + c * 32 + ch * 8;
            uint32_t d = sbase + buf * STAGE_B + mat * 10240 + (uint32_t)(row * 40 + ch * 8) * 2;
            asm volatile("cp.async.cg.shared.global [%0], [%1], 16;" :: "r"(d), "l"(s));
        }
        asm volatile("cp.async.commit_group;");
    };

    load_stage(0, 0);
    for (int c = 0; c < 32; c++) {
        const int buf = c & 1;
        if (c + 1 < 32) { load_stage(c + 1, buf ^ 1); asm volatile("cp.async.wait_group 1;"); }
        else            { asm volatile("cp.async.wait_group 0;"); }
        __syncthreads();
        const uint32_t base = sbase + buf * STAGE_B;
#pragma unroll
        for (int kk = 0; kk < 2; kk++) {
            uint32_t ah[2][4], al[2][4], bh[4][4];
            int arow = warp_m * 32 + (lane & 15);
            int acol = kk * 16 + (lane >> 4) * 8;
            uint32_t aoff = (uint32_t)(arow * 40 + acol) * 2;
            ldsm4(ah[0], base + aoff);
            ldsm4(ah[1], base + aoff + 1280);
            ldsm4(al[0], base + 10240 + aoff);
            ldsm4(al[1], base + 10240 + aoff + 1280);
            int g = lane >> 3, l7 = lane & 7;
#pragma unroll
            for (int p = 0; p < 4; p++) {
                int brow = warp_n * 64 + (p * 2 + (g >> 1)) * 8 + l7;
                int bcol = kk * 16 + (g & 1) * 8;
                ldsm4(bh[p], base + 20480 + (uint32_t)(brow * 40 + bcol) * 2);
            }
#pragma unroll
            for (int tm = 0; tm < 2; tm++)
#pragma unroll
                for (int tn = 0; tn < 8; tn++) {
                    uint32_t b0 = bh[tn >> 1][(tn & 1) * 2], b1 = bh[tn >> 1][(tn & 1) * 2 + 1];
                    mma16816(acc[tm][tn], ah[tm], b0, b1);
                    mma16816(acc[tm][tn], al[tm], b0, b1);
                }
        }
        __syncthreads();
    }

#pragma unroll
    for (int tm = 0; tm < 2; tm++) {
        int mb = row0 + warp_m * 32 + tm * 16 + (lane >> 2);
#pragma unroll
        for (int tn = 0; tn < 8; tn++) {
            int col = col0 + warp_n * 64 + tn * 8 + (lane & 3) * 2;
            float b0 = __ldg(&bias[col]), b1 = __ldg(&bias[col + 1]);
            *reinterpret_cast<float2*>(&out[(size_t)mb * ostride + col]) =
                make_float2(acc[tm][tn][0] + b0, acc[tm][tn][1] + b1);
            *reinterpret_cast<float2*>(&out[(size_t)(mb + 8) * ostride + col]) =
                make_float2(acc[tm][tn][2] + b0, acc[tm][tn][3] + b1);
        }
    }
}

// ---------------------------------------------------------------------------
// Flash attention (mma.sync fp16, fully single-pass: Q, K, P, V all fp16).
// Q staged through KV buf0 then hoisted; smem 36.9KB, ~110 regs -> 2 CTAs/SM.
// ---------------------------------------------------------------------------
#define RS   144
#define BUFB 18432                // per KV buffer: K 9216 + V 9216
#define OV   9216
#define ATTN_SMEM (2 * BUFB)      // 36864

__global__ __launch_bounds__(256, 2) void attn_mma()
{
    extern __shared__ char sm[];
    const uint32_t sbase = smem_u32(sm);
    const int tid = threadIdx.x;
    const int lane = tid & 31;
    const int wid = tid >> 5;
    const int q0 = blockIdx.x * 128;
    const int h = blockIdx.y;
    const int b = blockIdx.z;
    const size_t hb = ((size_t)(b * 16 + h)) * 2048 * 64;

    const __half* q_g = g_q + hb + (size_t)q0 * 64;
    const __half* k_g = g_k + hb;
    const __half* v_g = g_v + hb;

    // ---- stage Q through buf0, hoist to registers ----
    {
#pragma unroll
        for (int i = 0; i < 4; i++) {
            int lin = tid + i * 256;          // 0..1023 (128 rows x 8 chunks)
            int row = lin >> 3;
            int ch = lin & 7;
            const __half* s = q_g + (size_t)row * 64 + ch * 8;
            uint32_t d = sbase + (uint32_t)(row * RS + ch * 16);
            asm volatile("cp.async.cg.shared.global [%0], [%1], 16;" :: "r"(d), "l"(s));
        }
        asm volatile("cp.async.commit_group;");
        asm volatile("cp.async.wait_group 0;");
        __syncthreads();
    }

    uint32_t aq[4][4];
    {
        const int arow = wid * 16 + (lane & 15);
        const int acolb = (lane >> 4) * 16;
#pragma unroll
        for (int kc = 0; kc < 4; kc++)
            ldsm4(aq[kc], sbase + (uint32_t)(arow * RS + kc * 32 + acolb));
    }
    __syncthreads();   // all warps hoisted before KV overwrites Q

    auto load_kv = [&](int t, int buf) {
        const uint32_t dbase = sbase + buf * BUFB;
#pragma unroll
        for (int i = 0; i < 4; i++) {
            int lin = tid + i * 256;
            int mat = lin >> 9;
            int rem = lin & 511;
            int row = rem >> 3;
            int ch = rem & 7;
            const __half* s = (mat ? v_g : k_g) + (size_t)t * 64 * 64 + (size_t)row * 64 + ch * 8;
            uint32_t d = dbase + mat * OV + (uint32_t)(row * RS + ch * 16);
            asm volatile("cp.async.cg.shared.global [%0], [%1], 16;" :: "r"(d), "l"(s));
        }
        asm volatile("cp.async.commit_group;");
    };

    load_kv(0, 0);
    load_kv(1, 1);
    asm volatile("cp.async.wait_group 1;");
    __syncthreads();

    float m0 = -1e30f, m1 = -1e30f, l0 = 0.0f, l1 = 0.0f;
    float o[8][4];
#pragma unroll
    for (int nd = 0; nd < 8; nd++)
#pragma unroll
        for (int j = 0; j < 4; j++) o[nd][j] = 0.0f;

    const int g = lane >> 3, l7 = lane & 7;

    for (int t = 0; t < 32; t++) {
        const uint32_t kbuf = sbase + (t & 1) * BUFB;

        // ---- S = Q K^T (single pass), logits in log2 domain ----
        float c[8][4];
#pragma unroll
        for (int tn = 0; tn < 8; tn++)
#pragma unroll
            for (int j = 0; j < 4; j++) c[tn][j] = 0.0f;

#pragma unroll
        for (int kc = 0; kc < 4; kc++) {
            uint32_t bh[4][4];
#pragma unroll
            for (int p = 0; p < 4; p++) {
                int brow = (p * 2 + (g >> 1)) * 8 + l7;
                int bcolb = kc * 32 + (g & 1) * 16;
                ldsm4(bh[p], kbuf + (uint32_t)(brow * RS + bcolb));
            }
#pragma unroll
            for (int tn = 0; tn < 8; tn++) {
                uint32_t b0 = bh[tn >> 1][(tn & 1) * 2], b1 = bh[tn >> 1][(tn & 1) * 2 + 1];
                mma16816(c[tn], aq[kc], b0, b1);
            }
        }

        // ---- online softmax (MUFU exp2) ----
        float mx0 = -1e30f, mx1 = -1e30f;
#pragma unroll
        for (int tn = 0; tn < 8; tn++) {
            mx0 = fmaxf(mx0, fmaxf(c[tn][0], c[tn][1]));
            mx1 = fmaxf(mx1, fmaxf(c[tn][2], c[tn][3]));
        }
        mx0 = fmaxf(mx0, __shfl_xor_sync(0xffffffffu, mx0, 1));
        mx0 = fmaxf(mx0, __shfl_xor_sync(0xffffffffu, mx0, 2));
        mx1 = fmaxf(mx1, __shfl_xor_sync(0xffffffffu, mx1, 1));
        mx1 = fmaxf(mx1, __shfl_xor_sync(0xffffffffu, mx1, 2));
        float mn0 = fmaxf(m0, mx0), mn1 = fmaxf(m1, mx1);
        float al0 = fexp2(m0 - mn0), al1 = fexp2(m1 - mn1);
        m0 = mn0; m1 = mn1;

        float s0 = 0.0f, s1 = 0.0f;
#pragma unroll
        for (int tn = 0; tn < 8; tn++) {
            c[tn][0] = fexp2(c[tn][0] - mn0);
            c[tn][1] = fexp2(c[tn][1] - mn0);
            c[tn][2] = fexp2(c[tn][2] - mn1);
            c[tn][3] = fexp2(c[tn][3] - mn1);
            s0 += c[tn][0] + c[tn][1];
            s1 += c[tn][2] + c[tn][3];
        }
        s0 += __shfl_xor_sync(0xffffffffu, s0, 1);
        s0 += __shfl_xor_sync(0xffffffffu, s0, 2);
        s1 += __shfl_xor_sync(0xffffffffu, s1, 1);
        s1 += __shfl_xor_sync(0xffffffffu, s1, 2);
        l0 = l0 * al0 + s0;
        l1 = l1 * al1 + s1;
#pragma unroll
        for (int nd = 0; nd < 8; nd++) {
            o[nd][0] *= al0; o[nd][1] *= al0;
            o[nd][2] *= al1; o[nd][3] *= al1;
        }

        // ---- O += P V ----
#pragma unroll
        for (int kc = 0; kc < 4; kc++) {
            uint32_t phi[4];
            phi[0] = packh(c[2 * kc][0],     c[2 * kc][1]);
            phi[1] = packh(c[2 * kc][2],     c[2 * kc][3]);
            phi[2] = packh(c[2 * kc + 1][0], c[2 * kc + 1][1]);
            phi[3] = packh(c[2 * kc + 1][2], c[2 * kc + 1][3]);
#pragma unroll
            for (int dp = 0; dp < 4; dp++) {
                int vrow = kc * 16 + (g & 1) * 8 + l7;
                int vcolb = dp * 32 + (g >> 1) * 16;
                uint32_t vh[4];
                ldsm4t(vh, kbuf + OV + (uint32_t)(vrow * RS + vcolb));
                mma16816(o[dp * 2],     phi, vh[0], vh[1]);
                mma16816(o[dp * 2 + 1], phi, vh[2], vh[3]);
            }
        }

        __syncthreads();
        if (t + 2 < 32) load_kv(t + 2, t & 1);
        if (t + 1 < 32) {
            if (t + 2 < 32) { asm volatile("cp.async.wait_group 1;"); }
            else            { asm volatile("cp.async.wait_group 0;"); }
            __syncthreads();
        }
    }

    // ---- epilogue: normalize + fp16 hi/lo into [M,1024] ----
    const float inv0 = 1.0f / l0, inv1 = 1.0f / l1;
    const int r0 = q0 + wid * 16 + (lane >> 2);
    const size_t m0i = (size_t)(b * 2048) + r0;
    const int colb = h * 64 + (lane & 3) * 2;
#pragma unroll
    for (int nd = 0; nd < 8; nd++) {
        uint32_t hi, lo;
        split2h(o[nd][0] * inv0, o[nd][1] * inv0, hi, lo);
        *reinterpret_cast<uint32_t*>(&g_ahi[m0i * 1024 + colb + nd * 8]) = hi;
        *reinterpret_cast<uint32_t*>(&g_alo[m0i * 1024 + colb + nd * 8]) = lo;
        split2h(o[nd][2] * inv1, o[nd][3] * inv1, hi, lo);
        *reinterpret_cast<uint32_t*>(&g_ahi[(m0i + 8) * 1024 + colb + nd * 8]) = hi;
        *reinterpret_cast<uint32_t*>(&g_alo[(m0i + 8) * 1024 + colb + nd * 8]) = lo;
    }
}

// ---------------------------------------------------------------------------
// Launch
// ---------------------------------------------------------------------------
extern "C" void kernel_launch(void* const* d_in, const int* in_sizes, int n_in,
                              void* d_out, int out_size)
{
    const float* x      = (const float*)d_in[0];
    const float* qkv_w  = (const float*)d_in[1];
    const float* qkv_b  = (const float*)d_in[2];
    const float* qn_w   = (const float*)d_in[3];
    const float* kn_w   = (const float*)d_in[4];
    const float* proj_w = (const float*)d_in[5];
    const float* proj_b = (const float*)d_in[6];
    float* out = (float*)d_out;

    const int gemm_smem = 2 * STAGE_B;   // 61440
    cudaFuncSetAttribute(gemm_qkv_fused, cudaFuncAttributeMaxDynamicSharedMemorySize, gemm_smem);
    cudaFuncSetAttribute(gemm_mma, cudaFuncAttributeMaxDynamicSharedMemorySize, gemm_smem);
    cudaFuncSetAttribute(attn_mma, cudaFuncAttributeMaxDynamicSharedMemorySize, ATTN_SMEM);

    void *p_xhi, *p_xlo, *p_w1h, *p_w2h, *p_ahi, *p_alo;
    cudaGetSymbolAddress(&p_xhi, g_xhi);   cudaGetSymbolAddress(&p_xlo, g_xlo);
    cudaGetSymbolAddress(&p_w1h, g_w1h);   cudaGetSymbolAddress(&p_w2h, g_w2h);
    cudaGetSymbolAddress(&p_ahi, g_ahi);   cudaGetSymbolAddress(&p_alo, g_alo);

    rope_table<<<128, 256>>>();

    split_fp16<<<(M_ * C_ / 4 + 255) / 256, 256>>>((const float4*)x, (uint2*)p_xhi, (uint2*)p_xlo, M_ * C_ / 4);
    cvt_fp16<<<(K3_ * C_ / 4 + 255) / 256, 256>>>((const float4*)qkv_w, (uint2*)p_w1h, K3_ * C_ / 4);
    cvt_fp16<<<(C_ * C_ / 4 + 255) / 256, 256>>>((const float4*)proj_w, (uint2*)p_w2h, C_ * C_ / 4);

    // 1. QKV projection + fused RMSNorm/RoPE/fp16 emit (head-major q/k/v)
    gemm_qkv_fused<<<dim3(K3_ / 128, M_ / 128), 256, gemm_smem>>>(
        (const __half*)p_xhi, (const __half*)p_xlo, (const __half*)p_w1h,
        qkv_b, qn_w, kn_w);

    // 2. Tensor-core flash attention -> g_ahi/g_alo [M,1024]
    attn_mma<<<dim3(N_ / 128, H_, B_), 256, ATTN_SMEM>>>();

    // 3. Output projection -> d_out
    gemm_mma<<<dim3(C_ / 128, M_ / 128), 256, gemm_smem>>>(
        (const __half*)p_ahi, (const __half*)p_alo, (const __half*)p_w2h,
        proj_b, out, C_);
}

// round 10
// speedup vs baseline: 6.4503x; 1.2969x over previous
#include <cuda_runtime.h>
#include <cuda_bf16.h>
#include <cuda_fp16.h>
#include <cstdint>
#include <math.h>

// Problem constants
#define B_  2
#define N_  2048
#define C_  1024
#define H_  16
#define D_  64
#define M_  (B_ * N_)        // 4096
#define K3_ (3 * C_)         // 3072

// ---------------------------------------------------------------------------
// Scratch (device globals)
// ---------------------------------------------------------------------------
__device__ __half g_xh[M_ * C_];                       // x single fp16
__device__ __half g_w1h[K3_ * C_];                     // qkv_w single fp16
__device__ __half g_w2h[C_ * C_];                      // proj_w single fp16
__device__ __half g_a[M_ * C_];                        // attention out single fp16
// head-major [b*16+h][n][64]
__device__ __half g_q[B_*H_*N_*D_];                    // Q single (pre-scaled)
__device__ __half g_k[B_*H_*N_*D_];                    // K single
__device__ __half g_v[B_*H_*N_*D_];                    // V single
__device__ float g_cos[1024 * 32], g_sin[1024 * 32];

// ---------------------------------------------------------------------------
// Helpers
// ---------------------------------------------------------------------------
__device__ __forceinline__ uint32_t smem_u32(const void* p) {
    uint32_t a;
    asm("{ .reg .u64 t; cvta.to.shared.u64 t, %1; cvt.u32.u64 %0, t; }" : "=r"(a) : "l"(p));
    return a;
}
__device__ __forceinline__ void ldsm4(uint32_t* r, uint32_t addr) {
    asm volatile("ldmatrix.sync.aligned.m8n8.x4.shared.b16 {%0,%1,%2,%3}, [%4];"
                 : "=r"(r[0]), "=r"(r[1]), "=r"(r[2]), "=r"(r[3]) : "r"(addr));
}
__device__ __forceinline__ void ldsm4t(uint32_t* r, uint32_t addr) {
    asm volatile("ldmatrix.sync.aligned.m8n8.x4.trans.shared.b16 {%0,%1,%2,%3}, [%4];"
                 : "=r"(r[0]), "=r"(r[1]), "=r"(r[2]), "=r"(r[3]) : "r"(addr));
}
__device__ __forceinline__ void mma16816(float* c, const uint32_t* a, uint32_t b0, uint32_t b1) {
    asm volatile("mma.sync.aligned.m16n8k16.row.col.f32.f16.f16.f32 "
                 "{%0,%1,%2,%3}, {%4,%5,%6,%7}, {%8,%9}, {%0,%1,%2,%3};"
                 : "+f"(c[0]), "+f"(c[1]), "+f"(c[2]), "+f"(c[3])
                 : "r"(a[0]), "r"(a[1]), "r"(a[2]), "r"(a[3]), "r"(b0), "r"(b1));
}
__device__ __forceinline__ uint32_t packh(float a, float b) {
    uint32_t r;
    asm("cvt.rn.f16x2.f32 %0, %1, %2;" : "=r"(r) : "f"(b), "f"(a));
    return r;
}
__device__ __forceinline__ float fexp2(float x) {
    float r;
    asm("ex2.approx.f32 %0, %1;" : "=f"(r) : "f"(x));
    return r;
}

#define QSCALE 0.1803368801111137f   // 0.125 * log2(e)

// ---------------------------------------------------------------------------
// fp32 -> fp16 single convert
// ---------------------------------------------------------------------------
__global__ __launch_bounds__(256) void cvt_fp16(const float4* __restrict__ src,
                                                uint2* __restrict__ dst, int n4)
{
    int i = blockIdx.x * 256 + threadIdx.x;
    if (i >= n4) return;
    float4 v = src[i];
    dst[i] = make_uint2(packh(v.x, v.y), packh(v.z, v.w));
}

// ---------------------------------------------------------------------------
// RoPE tables
// ---------------------------------------------------------------------------
__global__ __launch_bounds__(256) void rope_table()
{
    int idx = blockIdx.x * 256 + threadIdx.x;          // 32768
    int pos = idx >> 5, lane = idx & 31;
    float e = (float)(2 * lane) * (1.0f / 64.0f);
    float inv = expf(-9.210340371976184f * e);
    float ang = (float)pos * inv;
    g_cos[idx] = cosf(ang);
    g_sin[idx] = sinf(ang);
}

// ---------------------------------------------------------------------------
// Shared GEMM config (block 128x128, K=1024, chunk 32, 8 warps 4x2)
// Stage: 2 matrices (A, B), 20480 B; double buffered.
// ---------------------------------------------------------------------------
#define STAGE_B 20480

// ---------------------------------------------------------------------------
// QKV GEMM (single-pass fp16) with FUSED RMSNorm + RoPE + fp16 emit.
// ---------------------------------------------------------------------------
__global__ __launch_bounds__(256, 2) void gemm_qkv_fused(
    const __half* __restrict__ Ah, const __half* __restrict__ Bh,
    const float* __restrict__ bias,
    const float* __restrict__ qn_w, const float* __restrict__ kn_w)
{
    extern __shared__ char sm[];
    const uint32_t sbase = smem_u32(sm);
    const int tid = threadIdx.x;
    const int lane = tid & 31;
    const int wid = tid >> 5;
    const int warp_m = wid >> 1;
    const int warp_n = wid & 1;
    const int row0 = blockIdx.y * 128;
    const int col0 = blockIdx.x * 128;

    float acc[2][8][4];
#pragma unroll
    for (int a = 0; a < 2; a++)
#pragma unroll
        for (int b = 0; b < 8; b++)
#pragma unroll
            for (int c = 0; c < 4; c++) acc[a][b][c] = 0.0f;

    const __half* srcs[2] = { Ah + (size_t)row0 * 1024, Bh + (size_t)col0 * 1024 };

    auto load_stage = [&](int c, int buf) {
#pragma unroll
        for (int i = 0; i < 4; i++) {
            int lin = tid + i * 256;          // 0..1023
            int mat = lin >> 9;               // 0=A, 1=B
            int rem = lin & 511;
            int row = rem >> 2;
            int ch = rem & 3;
            const __half* s = srcs[mat] + (size_t)row * 1024 + c * 32 + ch * 8;
            uint32_t d = sbase + buf * STAGE_B + mat * 10240 + (uint32_t)(row * 40 + ch * 8) * 2;
            asm volatile("cp.async.cg.shared.global [%0], [%1], 16;" :: "r"(d), "l"(s));
        }
        asm volatile("cp.async.commit_group;");
    };

    load_stage(0, 0);
    for (int c = 0; c < 32; c++) {
        const int buf = c & 1;
        if (c + 1 < 32) { load_stage(c + 1, buf ^ 1); asm volatile("cp.async.wait_group 1;"); }
        else            { asm volatile("cp.async.wait_group 0;"); }
        __syncthreads();
        const uint32_t base = sbase + buf * STAGE_B;
#pragma unroll
        for (int kk = 0; kk < 2; kk++) {
            uint32_t ah[2][4], bh[4][4];
            int arow = warp_m * 32 + (lane & 15);
            int acol = kk * 16 + (lane >> 4) * 8;
            uint32_t aoff = (uint32_t)(arow * 40 + acol) * 2;
            ldsm4(ah[0], base + aoff);
            ldsm4(ah[1], base + aoff + 1280);
            int g = lane >> 3, l7 = lane & 7;
#pragma unroll
            for (int p = 0; p < 4; p++) {
                int brow = warp_n * 64 + (p * 2 + (g >> 1)) * 8 + l7;
                int bcol = kk * 16 + (g & 1) * 8;
                ldsm4(bh[p], base + 10240 + (uint32_t)(brow * 40 + bcol) * 2);
            }
#pragma unroll
            for (int tm = 0; tm < 2; tm++)
#pragma unroll
                for (int tn = 0; tn < 8; tn++)
                    mma16816(acc[tm][tn], ah[tm],
                             bh[tn >> 1][(tn & 1) * 2], bh[tn >> 1][(tn & 1) * 2 + 1]);
        }
        __syncthreads();
    }

    // ---- fused epilogue ----
    const int sec = col0 >> 10;                         // 0=q, 1=k, 2=v
    const int head = ((col0 & 1023) >> 6) + warp_n;
    const int d0 = (lane & 3) * 2;

    float bs[8][2], wv[8][2];
    const float* w = (sec == 1) ? kn_w : qn_w;
#pragma unroll
    for (int tn = 0; tn < 8; tn++) {
        int d = tn * 8 + d0;
        int col = col0 + warp_n * 64 + d;
        bs[tn][0] = __ldg(&bias[col]);
        bs[tn][1] = __ldg(&bias[col + 1]);
        if (sec < 2) { wv[tn][0] = __ldg(&w[d]); wv[tn][1] = __ldg(&w[d + 1]); }
    }

    auto process_row = [&](float v[8][2], int m) {
        const int n = m & 2047;
        const int bb = m >> 11;
        const size_t obase = (((size_t)(bb * 16 + head)) * 2048 + n) * 64;
        if (sec == 2) {
#pragma unroll
            for (int tn = 0; tn < 8; tn++)
                *reinterpret_cast<uint32_t*>(&g_v[obase + tn * 8 + d0]) = packh(v[tn][0], v[tn][1]);
            return;
        }
        float ss = 0.0f;
#pragma unroll
        for (int tn = 0; tn < 8; tn++) ss += v[tn][0] * v[tn][0] + v[tn][1] * v[tn][1];
        ss += __shfl_xor_sync(0xffffffffu, ss, 1);
        ss += __shfl_xor_sync(0xffffffffu, ss, 2);
        float rs = rsqrtf(ss * (1.0f / 64.0f) + 1e-6f);
#pragma unroll
        for (int tn = 0; tn < 8; tn++) {
            v[tn][0] *= rs * wv[tn][0];
            v[tn][1] *= rs * wv[tn][1];
        }
        int pos = (n < 1024) ? n : ((n < 1536) ? (n - 1024) : -1);
        if (pos >= 0) {
#pragma unroll
            for (int tn = 0; tn < 4; tn++) {
                int idx = pos * 32 + tn * 8 + d0;
#pragma unroll
                for (int j = 0; j < 2; j++) {
                    float cs = g_cos[idx + j], sn = g_sin[idx + j];
                    float t1 = v[tn][j], t2 = v[tn + 4][j];
                    v[tn][j]     = t1 * cs - t2 * sn;
                    v[tn + 4][j] = t2 * cs + t1 * sn;
                }
            }
        }
        if (sec == 0) {
#pragma unroll
            for (int tn = 0; tn < 8; tn++)
                *reinterpret_cast<uint32_t*>(&g_q[obase + tn * 8 + d0]) =
                    packh(v[tn][0] * QSCALE, v[tn][1] * QSCALE);
        } else {
#pragma unroll
            for (int tn = 0; tn < 8; tn++)
                *reinterpret_cast<uint32_t*>(&g_k[obase + tn * 8 + d0]) = packh(v[tn][0], v[tn][1]);
        }
    };

#pragma unroll
    for (int tm = 0; tm < 2; tm++) {
        const int mA = row0 + warp_m * 32 + tm * 16 + (lane >> 2);
        float vA[8][2], vB[8][2];
#pragma unroll
        for (int tn = 0; tn < 8; tn++) {
            vA[tn][0] = acc[tm][tn][0] + bs[tn][0];
            vA[tn][1] = acc[tm][tn][1] + bs[tn][1];
            vB[tn][0] = acc[tm][tn][2] + bs[tn][0];
            vB[tn][1] = acc[tm][tn][3] + bs[tn][1];
        }
        process_row(vA, mA);
        process_row(vB, mA + 8);
    }
}

// ---------------------------------------------------------------------------
// Generic single-pass fp16 GEMM (proj): out = A.B^T + bias
// ---------------------------------------------------------------------------
__global__ __launch_bounds__(256, 2) void gemm_mma(
    const __half* __restrict__ Ah, const __half* __restrict__ Bh,
    const float* __restrict__ bias, float* __restrict__ out, int ostride)
{
    extern __shared__ char sm[];
    const uint32_t sbase = smem_u32(sm);
    const int tid = threadIdx.x;
    const int lane = tid & 31;
    const int wid = tid >> 5;
    const int warp_m = wid >> 1;
    const int warp_n = wid & 1;
    const int row0 = blockIdx.y * 128;
    const int col0 = blockIdx.x * 128;

    float acc[2][8][4];
#pragma unroll
    for (int a = 0; a < 2; a++)
#pragma unroll
        for (int b = 0; b < 8; b++)
#pragma unroll
            for (int c = 0; c < 4; c++) acc[a][b][c] = 0.0f;

    const __half* srcs[2] = { Ah + (size_t)row0 * 1024, Bh + (size_t)col0 * 1024 };

    auto load_stage = [&](int c, int buf) {
#pragma unroll
        for (int i = 0; i < 4; i++) {
            int lin = tid + i * 256;
            int mat = lin >> 9;
            int rem = lin & 511;
            int row = rem >> 2;
            int ch = rem & 3;
            const __half* s = srcs[mat] + (size_t)row * 1024 + c * 32 + ch * 8;
            uint32_t d = sbase + buf * STAGE_B + mat * 10240 + (uint32_t)(row * 40 + ch * 8) * 2;
            asm volatile("cp.async.cg.shared.global [%0], [%1], 16;" :: "r"(d), "l"(s));
        }
        asm volatile("cp.async.commit_group;");
    };

    load_stage(0, 0);
    for (int c = 0; c < 32; c++) {
        const int buf = c & 1;
        if (c + 1 < 32) { load_stage(c + 1, buf ^ 1); asm volatile("cp.async.wait_group 1;"); }
        else            { asm volatile("cp.async.wait_group 0;"); }
        __syncthreads();
        const uint32_t base = sbase + buf * STAGE_B;
#pragma unroll
        for (int kk = 0; kk < 2; kk++) {
            uint32_t ah[2][4], bh[4][4];
            int arow = warp_m * 32 + (lane & 15);
            int acol = kk * 16 + (lane >> 4) * 8;
            uint32_t aoff = (uint32_t)(arow * 40 + acol) * 2;
            ldsm4(ah[0], base + aoff);
            ldsm4(ah[1], base + aoff + 1280);
            int g = lane >> 3, l7 = lane & 7;
#pragma unroll
            for (int p = 0; p < 4; p++) {
                int brow = warp_n * 64 + (p * 2 + (g >> 1)) * 8 + l7;
                int bcol = kk * 16 + (g & 1) * 8;
                ldsm4(bh[p], base + 10240 + (uint32_t)(brow * 40 + bcol) * 2);
            }
#pragma unroll
            for (int tm = 0; tm < 2; tm++)
#pragma unroll
                for (int tn = 0; tn < 8; tn++)
                    mma16816(acc[tm][tn], ah[tm],
                             bh[tn >> 1][(tn & 1) * 2], bh[tn >> 1][(tn & 1) * 2 + 1]);
        }
        __syncthreads();
    }

#pragma unroll
    for (int tm = 0; tm < 2; tm++) {
        int mb = row0 + warp_m * 32 + tm * 16 + (lane >> 2);
#pragma unroll
        for (int tn = 0; tn < 8; tn++) {
            int col = col0 + warp_n * 64 + tn * 8 + (lane & 3) * 2;
            float b0 = __ldg(&bias[col]), b1 = __ldg(&bias[col + 1]);
            *reinterpret_cast<float2*>(&out[(size_t)mb * ostride + col]) =
                make_float2(acc[tm][tn][0] + b0, acc[tm][tn][1] + b1);
            *reinterpret_cast<float2*>(&out[(size_t)(mb + 8) * ostride + col]) =
                make_float2(acc[tm][tn][2] + b0, acc[tm][tn][3] + b1);
        }
    }
}

// ---------------------------------------------------------------------------
// Flash attention (mma.sync fp16, fully single-pass).
// Q staged through KV buf0 then hoisted; smem 36.9KB, 2 CTAs/SM.
// ---------------------------------------------------------------------------
#define RS   144
#define BUFB 18432                // per KV buffer: K 9216 + V 9216
#define OV   9216
#define ATTN_SMEM (2 * BUFB)      // 36864

__global__ __launch_bounds__(256, 2) void attn_mma()
{
    extern __shared__ char sm[];
    const uint32_t sbase = smem_u32(sm);
    const int tid = threadIdx.x;
    const int lane = tid & 31;
    const int wid = tid >> 5;
    const int q0 = blockIdx.x * 128;
    const int h = blockIdx.y;
    const int b = blockIdx.z;
    const size_t hb = ((size_t)(b * 16 + h)) * 2048 * 64;

    const __half* q_g = g_q + hb + (size_t)q0 * 64;
    const __half* k_g = g_k + hb;
    const __half* v_g = g_v + hb;

    // ---- stage Q through buf0, hoist to registers ----
    {
#pragma unroll
        for (int i = 0; i < 4; i++) {
            int lin = tid + i * 256;          // 0..1023 (128 rows x 8 chunks)
            int row = lin >> 3;
            int ch = lin & 7;
            const __half* s = q_g + (size_t)row * 64 + ch * 8;
            uint32_t d = sbase + (uint32_t)(row * RS + ch * 16);
            asm volatile("cp.async.cg.shared.global [%0], [%1], 16;" :: "r"(d), "l"(s));
        }
        asm volatile("cp.async.commit_group;");
        asm volatile("cp.async.wait_group 0;");
        __syncthreads();
    }

    uint32_t aq[4][4];
    {
        const int arow = wid * 16 + (lane & 15);
        const int acolb = (lane >> 4) * 16;
#pragma unroll
        for (int kc = 0; kc < 4; kc++)
            ldsm4(aq[kc], sbase + (uint32_t)(arow * RS + kc * 32 + acolb));
    }
    __syncthreads();   // all warps hoisted before KV overwrites Q

    auto load_kv = [&](int t, int buf) {
        const uint32_t dbase = sbase + buf * BUFB;
#pragma unroll
        for (int i = 0; i < 4; i++) {
            int lin = tid + i * 256;
            int mat = lin >> 9;
            int rem = lin & 511;
            int row = rem >> 3;
            int ch = rem & 7;
            const __half* s = (mat ? v_g : k_g) + (size_t)t * 64 * 64 + (size_t)row * 64 + ch * 8;
            uint32_t d = dbase + mat * OV + (uint32_t)(row * RS + ch * 16);
            asm volatile("cp.async.cg.shared.global [%0], [%1], 16;" :: "r"(d), "l"(s));
        }
        asm volatile("cp.async.commit_group;");
    };

    load_kv(0, 0);
    load_kv(1, 1);
    asm volatile("cp.async.wait_group 1;");
    __syncthreads();

    float m0 = -1e30f, m1 = -1e30f, l0 = 0.0f, l1 = 0.0f;
    float o[8][4];
#pragma unroll
    for (int nd = 0; nd < 8; nd++)
#pragma unroll
        for (int j = 0; j < 4; j++) o[nd][j] = 0.0f;

    const int g = lane >> 3, l7 = lane & 7;

    for (int t = 0; t < 32; t++) {
        const uint32_t kbuf = sbase + (t & 1) * BUFB;

        // ---- S = Q K^T, logits in log2 domain ----
        float c[8][4];
#pragma unroll
        for (int tn = 0; tn < 8; tn++)
#pragma unroll
            for (int j = 0; j < 4; j++) c[tn][j] = 0.0f;

#pragma unroll
        for (int kc = 0; kc < 4; kc++) {
            uint32_t bh[4][4];
#pragma unroll
            for (int p = 0; p < 4; p++) {
                int brow = (p * 2 + (g >> 1)) * 8 + l7;
                int bcolb = kc * 32 + (g & 1) * 16;
                ldsm4(bh[p], kbuf + (uint32_t)(brow * RS + bcolb));
            }
#pragma unroll
            for (int tn = 0; tn < 8; tn++)
                mma16816(c[tn], aq[kc],
                         bh[tn >> 1][(tn & 1) * 2], bh[tn >> 1][(tn & 1) * 2 + 1]);
        }

        // ---- online softmax (MUFU exp2) ----
        float mx0 = -1e30f, mx1 = -1e30f;
#pragma unroll
        for (int tn = 0; tn < 8; tn++) {
            mx0 = fmaxf(mx0, fmaxf(c[tn][0], c[tn][1]));
            mx1 = fmaxf(mx1, fmaxf(c[tn][2], c[tn][3]));
        }
        mx0 = fmaxf(mx0, __shfl_xor_sync(0xffffffffu, mx0, 1));
        mx0 = fmaxf(mx0, __shfl_xor_sync(0xffffffffu, mx0, 2));
        mx1 = fmaxf(mx1, __shfl_xor_sync(0xffffffffu, mx1, 1));
        mx1 = fmaxf(mx1, __shfl_xor_sync(0xffffffffu, mx1, 2));
        float mn0 = fmaxf(m0, mx0), mn1 = fmaxf(m1, mx1);
        float al0 = fexp2(m0 - mn0), al1 = fexp2(m1 - mn1);
        m0 = mn0; m1 = mn1;

        float s0 = 0.0f, s1 = 0.0f;
#pragma unroll
        for (int tn = 0; tn < 8; tn++) {
            c[tn][0] = fexp2(c[tn][0] - mn0);
            c[tn][1] = fexp2(c[tn][1] - mn0);
            c[tn][2] = fexp2(c[tn][2] - mn1);
            c[tn][3] = fexp2(c[tn][3] - mn1);
            s0 += c[tn][0] + c[tn][1];
            s1 += c[tn][2] + c[tn][3];
        }
        s0 += __shfl_xor_sync(0xffffffffu, s0, 1);
        s0 += __shfl_xor_sync(0xffffffffu, s0, 2);
        s1 += __shfl_xor_sync(0xffffffffu, s1, 1);
        s1 += __shfl_xor_sync(0xffffffffu, s1, 2);
        l0 = l0 * al0 + s0;
        l1 = l1 * al1 + s1;
#pragma unroll
        for (int nd = 0; nd < 8; nd++) {
            o[nd][0] *= al0; o[nd][1] *= al0;
            o[nd][2] *= al1; o[nd][3] *= al1;
        }

        // ---- O += P V ----
#pragma unroll
        for (int kc = 0; kc < 4; kc++) {
            uint32_t phi[4];
            phi[0] = packh(c[2 * kc][0],     c[2 * kc][1]);
            phi[1] = packh(c[2 * kc][2],     c[2 * kc][3]);
            phi[2] = packh(c[2 * kc + 1][0], c[2 * kc + 1][1]);
            phi[3] = packh(c[2 * kc + 1][2], c[2 * kc + 1][3]);
#pragma unroll
            for (int dp = 0; dp < 4; dp++) {
                int vrow = kc * 16 + (g & 1) * 8 + l7;
                int vcolb = dp * 32 + (g >> 1) * 16;
                uint32_t vh[4];
                ldsm4t(vh, kbuf + OV + (uint32_t)(vrow * RS + vcolb));
                mma16816(o[dp * 2],     phi, vh[0], vh[1]);
                mma16816(o[dp * 2 + 1], phi, vh[2], vh[3]);
            }
        }

        __syncthreads();
        if (t + 2 < 32) load_kv(t + 2, t & 1);
        if (t + 1 < 32) {
            if (t + 2 < 32) { asm volatile("cp.async.wait_group 1;"); }
            else            { asm volatile("cp.async.wait_group 0;"); }
            __syncthreads();
        }
    }

    // ---- epilogue: normalize + single fp16 into [M,1024] ----
    const float inv0 = 1.0f / l0, inv1 = 1.0f / l1;
    const int r0 = q0 + wid * 16 + (lane >> 2);
    const size_t m0i = (size_t)(b * 2048) + r0;
    const int colb = h * 64 + (lane & 3) * 2;
#pragma unroll
    for (int nd = 0; nd < 8; nd++) {
        *reinterpret_cast<uint32_t*>(&g_a[m0i * 1024 + colb + nd * 8]) =
            packh(o[nd][0] * inv0, o[nd][1] * inv0);
        *reinterpret_cast<uint32_t*>(&g_a[(m0i + 8) * 1024 + colb + nd * 8]) =
            packh(o[nd][2] * inv1, o[nd][3] * inv1);
    }
}

// ---------------------------------------------------------------------------
// Launch
// ---------------------------------------------------------------------------
extern "C" void kernel_launch(void* const* d_in, const int* in_sizes, int n_in,
                              void* d_out, int out_size)
{
    const float* x      = (const float*)d_in[0];
    const float* qkv_w  = (const float*)d_in[1];
    const float* qkv_b  = (const float*)d_in[2];
    const float* qn_w   = (const float*)d_in[3];
    const float* kn_w   = (const float*)d_in[4];
    const float* proj_w = (const float*)d_in[5];
    const float* proj_b = (const float*)d_in[6];
    float* out = (float*)d_out;

    const int gemm_smem = 2 * STAGE_B;   // 40960
    cudaFuncSetAttribute(gemm_qkv_fused, cudaFuncAttributeMaxDynamicSharedMemorySize, gemm_smem);
    cudaFuncSetAttribute(gemm_mma, cudaFuncAttributeMaxDynamicSharedMemorySize, gemm_smem);
    cudaFuncSetAttribute(attn_mma, cudaFuncAttributeMaxDynamicSharedMemorySize, ATTN_SMEM);

    void *p_xh, *p_w1h, *p_w2h, *p_a;
    cudaGetSymbolAddress(&p_xh, g_xh);
    cudaGetSymbolAddress(&p_w1h, g_w1h);
    cudaGetSymbolAddress(&p_w2h, g_w2h);
    cudaGetSymbolAddress(&p_a, g_a);

    rope_table<<<128, 256>>>();

    cvt_fp16<<<(M_ * C_ / 4 + 255) / 256, 256>>>((const float4*)x, (uint2*)p_xh, M_ * C_ / 4);
    cvt_fp16<<<(K3_ * C_ / 4 + 255) / 256, 256>>>((const float4*)qkv_w, (uint2*)p_w1h, K3_ * C_ / 4);
    cvt_fp16<<<(C_ * C_ / 4 + 255) / 256, 256>>>((const float4*)proj_w, (uint2*)p_w2h, C_ * C_ / 4);

    // 1. QKV projection + fused RMSNorm/RoPE/fp16 emit (head-major q/k/v)
    gemm_qkv_fused<<<dim3(K3_ / 128, M_ / 128), 256, gemm_smem>>>(
        (const __half*)p_xh, (const __half*)p_w1h, qkv_b, qn_w, kn_w);

    // 2. Tensor-core flash attention -> g_a [M,1024]
    attn_mma<<<dim3(N_ / 128, H_, B_), 256, ATTN_SMEM>>>();

    // 3. Output projection -> d_out
    gemm_mma<<<dim3(C_ / 128, M_ / 128), 256, gemm_smem>>>(
        (const __half*)p_a, (const __half*)p_w2h, proj_b, out, C_);
}

// round 11
// speedup vs baseline: 7.0192x; 1.0882x over previous
#include <cuda_runtime.h>
#include <cuda_bf16.h>
#include <cuda_fp16.h>
#include <cstdint>
#include <math.h>

// Problem constants
#define B_  2
#define N_  2048
#define C_  1024
#define H_  16
#define D_  64
#define M_  (B_ * N_)        // 4096
#define K3_ (3 * C_)         // 3072

// ---------------------------------------------------------------------------
// Scratch (device globals)
// ---------------------------------------------------------------------------
__device__ __half g_xh[M_ * C_];                       // x single fp16
__device__ __half g_w1h[K3_ * C_];                     // qkv_w single fp16
__device__ __half g_w2h[C_ * C_];                      // proj_w single fp16
__device__ __half g_a[M_ * C_];                        // attention out single fp16
// head-major [b*16+h][n][64]
__device__ __half g_q[B_*H_*N_*D_];                    // Q single (pre-scaled)
__device__ __half g_k[B_*H_*N_*D_];                    // K single
__device__ __half g_v[B_*H_*N_*D_];                    // V single
__device__ float g_cos[1024 * 32], g_sin[1024 * 32];

// ---------------------------------------------------------------------------
// Helpers
// ---------------------------------------------------------------------------
__device__ __forceinline__ uint32_t smem_u32(const void* p) {
    uint32_t a;
    asm("{ .reg .u64 t; cvta.to.shared.u64 t, %1; cvt.u32.u64 %0, t; }" : "=r"(a) : "l"(p));
    return a;
}
__device__ __forceinline__ void ldsm4(uint32_t* r, uint32_t addr) {
    asm volatile("ldmatrix.sync.aligned.m8n8.x4.shared.b16 {%0,%1,%2,%3}, [%4];"
                 : "=r"(r[0]), "=r"(r[1]), "=r"(r[2]), "=r"(r[3]) : "r"(addr));
}
__device__ __forceinline__ void ldsm4t(uint32_t* r, uint32_t addr) {
    asm volatile("ldmatrix.sync.aligned.m8n8.x4.trans.shared.b16 {%0,%1,%2,%3}, [%4];"
                 : "=r"(r[0]), "=r"(r[1]), "=r"(r[2]), "=r"(r[3]) : "r"(addr));
}
__device__ __forceinline__ void mma16816(float* c, const uint32_t* a, uint32_t b0, uint32_t b1) {
    asm volatile("mma.sync.aligned.m16n8k16.row.col.f32.f16.f16.f32 "
                 "{%0,%1,%2,%3}, {%4,%5,%6,%7}, {%8,%9}, {%0,%1,%2,%3};"
                 : "+f"(c[0]), "+f"(c[1]), "+f"(c[2]), "+f"(c[3])
                 : "r"(a[0]), "r"(a[1]), "r"(a[2]), "r"(a[3]), "r"(b0), "r"(b1));
}
__device__ __forceinline__ uint32_t packh(float a, float b) {
    uint32_t r;
    asm("cvt.rn.f16x2.f32 %0, %1, %2;" : "=r"(r) : "f"(b), "f"(a));
    return r;
}
__device__ __forceinline__ float fexp2(float x) {
    float r;
    asm("ex2.approx.f32 %0, %1;" : "=f"(r) : "f"(x));
    return r;
}
__device__ __forceinline__ uint32_t h2exp2(uint32_t x) {
    uint32_t r;
    asm("ex2.approx.f16x2 %0, %1;" : "=r"(r) : "r"(x));
    return r;
}

#define QSCALE 0.1803368801111137f   // 0.125 * log2(e)
#define ONES_H2 0x3C003C00u          // fp16x2 {1.0, 1.0}

// ---------------------------------------------------------------------------
// Merged fp32 -> fp16 convert for x, qkv_w, proj_w
// ---------------------------------------------------------------------------
#define NX4  (M_ * C_ / 4)
#define NW14 (K3_ * C_ / 4)
#define NW24 (C_ * C_ / 4)

__global__ __launch_bounds__(256) void cvt_all(const float4* __restrict__ x,
                                               const float4* __restrict__ w1,
                                               const float4* __restrict__ w2,
                                               uint2* __restrict__ xh,
                                               uint2* __restrict__ w1h,
                                               uint2* __restrict__ w2h)
{
    int i = blockIdx.x * 256 + threadIdx.x;
    const float4* s;
    uint2* d;
    if (i < NX4)              { s = x + i;                 d = xh + i; }
    else if (i < NX4 + NW14)  { s = w1 + (i - NX4);        d = w1h + (i - NX4); }
    else                      { s = w2 + (i - NX4 - NW14); d = w2h + (i - NX4 - NW14); }
    float4 v = *s;
    *d = make_uint2(packh(v.x, v.y), packh(v.z, v.w));
}

// ---------------------------------------------------------------------------
// RoPE tables
// ---------------------------------------------------------------------------
__global__ __launch_bounds__(256) void rope_table()
{
    int idx = blockIdx.x * 256 + threadIdx.x;          // 32768
    int pos = idx >> 5, lane = idx & 31;
    float e = (float)(2 * lane) * (1.0f / 64.0f);
    float inv = expf(-9.210340371976184f * e);
    float ang = (float)pos * inv;
    g_cos[idx] = cosf(ang);
    g_sin[idx] = sinf(ang);
}

// ---------------------------------------------------------------------------
// Shared GEMM config (block 128x128, K=1024, chunk 32, 8 warps 4x2)
// Stage: 2 matrices (A, B), 20480 B; 3-stage pipeline.
// ---------------------------------------------------------------------------
#define STAGE_B 20480
#define GEMM_SMEM (3 * STAGE_B)   // 61440

// ---------------------------------------------------------------------------
// QKV GEMM (single-pass fp16) with FUSED RMSNorm + RoPE + fp16 emit.
// ---------------------------------------------------------------------------
__global__ __launch_bounds__(256, 2) void gemm_qkv_fused(
    const __half* __restrict__ Ah, const __half* __restrict__ Bh,
    const float* __restrict__ bias,
    const float* __restrict__ qn_w, const float* __restrict__ kn_w)
{
    extern __shared__ char sm[];
    const uint32_t sbase = smem_u32(sm);
    const int tid = threadIdx.x;
    const int lane = tid & 31;
    const int wid = tid >> 5;
    const int warp_m = wid >> 1;
    const int warp_n = wid & 1;
    const int row0 = blockIdx.y * 128;
    const int col0 = blockIdx.x * 128;

    float acc[2][8][4];
#pragma unroll
    for (int a = 0; a < 2; a++)
#pragma unroll
        for (int b = 0; b < 8; b++)
#pragma unroll
            for (int c = 0; c < 4; c++) acc[a][b][c] = 0.0f;

    const __half* srcs[2] = { Ah + (size_t)row0 * 1024, Bh + (size_t)col0 * 1024 };

    auto load_stage = [&](int c, int buf) {
#pragma unroll
        for (int i = 0; i < 4; i++) {
            int lin = tid + i * 256;          // 0..1023
            int mat = lin >> 9;               // 0=A, 1=B
            int rem = lin & 511;
            int row = rem >> 2;
            int ch = rem & 3;
            const __half* s = srcs[mat] + (size_t)row * 1024 + c * 32 + ch * 8;
            uint32_t d = sbase + buf * STAGE_B + mat * 10240 + (uint32_t)(row * 40 + ch * 8) * 2;
            asm volatile("cp.async.cg.shared.global [%0], [%1], 16;" :: "r"(d), "l"(s));
        }
        asm volatile("cp.async.commit_group;");
    };

    load_stage(0, 0);
    load_stage(1, 1);
    for (int c = 0; c < 32; c++) {
        const int buf = c % 3;
        if (c + 2 < 32) { load_stage(c + 2, (c + 2) % 3); asm volatile("cp.async.wait_group 2;"); }
        else if (c + 1 < 32) { asm volatile("cp.async.wait_group 1;"); }
        else { asm volatile("cp.async.wait_group 0;"); }
        __syncthreads();
        const uint32_t base = sbase + buf * STAGE_B;
#pragma unroll
        for (int kk = 0; kk < 2; kk++) {
            uint32_t ah[2][4], bh[4][4];
            int arow = warp_m * 32 + (lane & 15);
            int acol = kk * 16 + (lane >> 4) * 8;
            uint32_t aoff = (uint32_t)(arow * 40 + acol) * 2;
            ldsm4(ah[0], base + aoff);
            ldsm4(ah[1], base + aoff + 1280);
            int g = lane >> 3, l7 = lane & 7;
#pragma unroll
            for (int p = 0; p < 4; p++) {
                int brow = warp_n * 64 + (p * 2 + (g >> 1)) * 8 + l7;
                int bcol = kk * 16 + (g & 1) * 8;
                ldsm4(bh[p], base + 10240 + (uint32_t)(brow * 40 + bcol) * 2);
            }
#pragma unroll
            for (int tm = 0; tm < 2; tm++)
#pragma unroll
                for (int tn = 0; tn < 8; tn++)
                    mma16816(acc[tm][tn], ah[tm],
                             bh[tn >> 1][(tn & 1) * 2], bh[tn >> 1][(tn & 1) * 2 + 1]);
        }
        __syncthreads();
    }

    // ---- fused epilogue ----
    const int sec = col0 >> 10;                         // 0=q, 1=k, 2=v
    const int head = ((col0 & 1023) >> 6) + warp_n;
    const int d0 = (lane & 3) * 2;

    float bs[8][2], wv[8][2];
    const float* w = (sec == 1) ? kn_w : qn_w;
#pragma unroll
    for (int tn = 0; tn < 8; tn++) {
        int d = tn * 8 + d0;
        int col = col0 + warp_n * 64 + d;
        bs[tn][0] = __ldg(&bias[col]);
        bs[tn][1] = __ldg(&bias[col + 1]);
        if (sec < 2) { wv[tn][0] = __ldg(&w[d]); wv[tn][1] = __ldg(&w[d + 1]); }
    }

    auto process_row = [&](float v[8][2], int m) {
        const int n = m & 2047;
        const int bb = m >> 11;
        const size_t obase = (((size_t)(bb * 16 + head)) * 2048 + n) * 64;
        if (sec == 2) {
#pragma unroll
            for (int tn = 0; tn < 8; tn++)
                *reinterpret_cast<uint32_t*>(&g_v[obase + tn * 8 + d0]) = packh(v[tn][0], v[tn][1]);
            return;
        }
        float ss = 0.0f;
#pragma unroll
        for (int tn = 0; tn < 8; tn++) ss += v[tn][0] * v[tn][0] + v[tn][1] * v[tn][1];
        ss += __shfl_xor_sync(0xffffffffu, ss, 1);
        ss += __shfl_xor_sync(0xffffffffu, ss, 2);
        float rs = rsqrtf(ss * (1.0f / 64.0f) + 1e-6f);
#pragma unroll
        for (int tn = 0; tn < 8; tn++) {
            v[tn][0] *= rs * wv[tn][0];
            v[tn][1] *= rs * wv[tn][1];
        }
        int pos = (n < 1024) ? n : ((n < 1536) ? (n - 1024) : -1);
        if (pos >= 0) {
#pragma unroll
            for (int tn = 0; tn < 4; tn++) {
                int idx = pos * 32 + tn * 8 + d0;
#pragma unroll
                for (int j = 0; j < 2; j++) {
                    float cs = g_cos[idx + j], sn = g_sin[idx + j];
                    float t1 = v[tn][j], t2 = v[tn + 4][j];
                    v[tn][j]     = t1 * cs - t2 * sn;
                    v[tn + 4][j] = t2 * cs + t1 * sn;
                }
            }
        }
        if (sec == 0) {
#pragma unroll
            for (int tn = 0; tn < 8; tn++)
                *reinterpret_cast<uint32_t*>(&g_q[obase + tn * 8 + d0]) =
                    packh(v[tn][0] * QSCALE, v[tn][1] * QSCALE);
        } else {
#pragma unroll
            for (int tn = 0; tn < 8; tn++)
                *reinterpret_cast<uint32_t*>(&g_k[obase + tn * 8 + d0]) = packh(v[tn][0], v[tn][1]);
        }
    };

#pragma unroll
    for (int tm = 0; tm < 2; tm++) {
        const int mA = row0 + warp_m * 32 + tm * 16 + (lane >> 2);
        float vA[8][2], vB[8][2];
#pragma unroll
        for (int tn = 0; tn < 8; tn++) {
            vA[tn][0] = acc[tm][tn][0] + bs[tn][0];
            vA[tn][1] = acc[tm][tn][1] + bs[tn][1];
            vB[tn][0] = acc[tm][tn][2] + bs[tn][0];
            vB[tn][1] = acc[tm][tn][3] + bs[tn][1];
        }
        process_row(vA, mA);
        process_row(vB, mA + 8);
    }
}

// ---------------------------------------------------------------------------
// Generic single-pass fp16 GEMM (proj): out = A.B^T + bias
// ---------------------------------------------------------------------------
__global__ __launch_bounds__(256, 2) void gemm_mma(
    const __half* __restrict__ Ah, const __half* __restrict__ Bh,
    const float* __restrict__ bias, float* __restrict__ out, int ostride)
{
    extern __shared__ char sm[];
    const uint32_t sbase = smem_u32(sm);
    const int tid = threadIdx.x;
    const int lane = tid & 31;
    const int wid = tid >> 5;
    const int warp_m = wid >> 1;
    const int warp_n = wid & 1;
    const int row0 = blockIdx.y * 128;
    const int col0 = blockIdx.x * 128;

    float acc[2][8][4];
#pragma unroll
    for (int a = 0; a < 2; a++)
#pragma unroll
        for (int b = 0; b < 8; b++)
#pragma unroll
            for (int c = 0; c < 4; c++) acc[a][b][c] = 0.0f;

    const __half* srcs[2] = { Ah + (size_t)row0 * 1024, Bh + (size_t)col0 * 1024 };

    auto load_stage = [&](int c, int buf) {
#pragma unroll
        for (int i = 0; i < 4; i++) {
            int lin = tid + i * 256;
            int mat = lin >> 9;
            int rem = lin & 511;
            int row = rem >> 2;
            int ch = rem & 3;
            const __half* s = srcs[mat] + (size_t)row * 1024 + c * 32 + ch * 8;
            uint32_t d = sbase + buf * STAGE_B + mat * 10240 + (uint32_t)(row * 40 + ch * 8) * 2;
            asm volatile("cp.async.cg.shared.global [%0], [%1], 16;" :: "r"(d), "l"(s));
        }
        asm volatile("cp.async.commit_group;");
    };

    load_stage(0, 0);
    load_stage(1, 1);
    for (int c = 0; c < 32; c++) {
        const int buf = c % 3;
        if (c + 2 < 32) { load_stage(c + 2, (c + 2) % 3); asm volatile("cp.async.wait_group 2;"); }
        else if (c + 1 < 32) { asm volatile("cp.async.wait_group 1;"); }
        else { asm volatile("cp.async.wait_group 0;"); }
        __syncthreads();
        const uint32_t base = sbase + buf * STAGE_B;
#pragma unroll
        for (int kk = 0; kk < 2; kk++) {
            uint32_t ah[2][4], bh[4][4];
            int arow = warp_m * 32 + (lane & 15);
            int acol = kk * 16 + (lane >> 4) * 8;
            uint32_t aoff = (uint32_t)(arow * 40 + acol) * 2;
            ldsm4(ah[0], base + aoff);
            ldsm4(ah[1], base + aoff + 1280);
            int g = lane >> 3, l7 = lane & 7;
#pragma unroll
            for (int p = 0; p < 4; p++) {
                int brow = warp_n * 64 + (p * 2 + (g >> 1)) * 8 + l7;
                int bcol = kk * 16 + (g & 1) * 8;
                ldsm4(bh[p], base + 10240 + (uint32_t)(brow * 40 + bcol) * 2);
            }
#pragma unroll
            for (int tm = 0; tm < 2; tm++)
#pragma unroll
                for (int tn = 0; tn < 8; tn++)
                    mma16816(acc[tm][tn], ah[tm],
                             bh[tn >> 1][(tn & 1) * 2], bh[tn >> 1][(tn & 1) * 2 + 1]);
        }
        __syncthreads();
    }

#pragma unroll
    for (int tm = 0; tm < 2; tm++) {
        int mb = row0 + warp_m * 32 + tm * 16 + (lane >> 2);
#pragma unroll
        for (int tn = 0; tn < 8; tn++) {
            int col = col0 + warp_n * 64 + tn * 8 + (lane & 3) * 2;
            float b0 = __ldg(&bias[col]), b1 = __ldg(&bias[col + 1]);
            *reinterpret_cast<float2*>(&out[(size_t)mb * ostride + col]) =
                make_float2(acc[tm][tn][0] + b0, acc[tm][tn][1] + b1);
            *reinterpret_cast<float2*>(&out[(size_t)(mb + 8) * ostride + col]) =
                make_float2(acc[tm][tn][2] + b0, acc[tm][tn][3] + b1);
        }
    }
}

// ---------------------------------------------------------------------------
// Flash attention (mma.sync fp16, single-pass). Softmax: f16x2 MUFU exp2,
// row sums via MMA against all-ones B. Q staged through KV buf0; 2 CTAs/SM.
// ---------------------------------------------------------------------------
#define RS   144
#define BUFB 18432                // per KV buffer: K 9216 + V 9216
#define OV   9216
#define ATTN_SMEM (2 * BUFB)      // 36864

__global__ __launch_bounds__(256, 2) void attn_mma()
{
    extern __shared__ char sm[];
    const uint32_t sbase = smem_u32(sm);
    const int tid = threadIdx.x;
    const int lane = tid & 31;
    const int wid = tid >> 5;
    const int q0 = blockIdx.x * 128;
    const int h = blockIdx.y;
    const int b = blockIdx.z;
    const size_t hb = ((size_t)(b * 16 + h)) * 2048 * 64;

    const __half* q_g = g_q + hb + (size_t)q0 * 64;
    const __half* k_g = g_k + hb;
    const __half* v_g = g_v + hb;

    // ---- stage Q through buf0, hoist to registers ----
    {
#pragma unroll
        for (int i = 0; i < 4; i++) {
            int lin = tid + i * 256;          // 0..1023 (128 rows x 8 chunks)
            int row = lin >> 3;
            int ch = lin & 7;
            const __half* s = q_g + (size_t)row * 64 + ch * 8;
            uint32_t d = sbase + (uint32_t)(row * RS + ch * 16);
            asm volatile("cp.async.cg.shared.global [%0], [%1], 16;" :: "r"(d), "l"(s));
        }
        asm volatile("cp.async.commit_group;");
        asm volatile("cp.async.wait_group 0;");
        __syncthreads();
    }

    uint32_t aq[4][4];
    {
        const int arow = wid * 16 + (lane & 15);
        const int acolb = (lane >> 4) * 16;
#pragma unroll
        for (int kc = 0; kc < 4; kc++)
            ldsm4(aq[kc], sbase + (uint32_t)(arow * RS + kc * 32 + acolb));
    }
    __syncthreads();   // all warps hoisted before KV overwrites Q

    auto load_kv = [&](int t, int buf) {
        const uint32_t dbase = sbase + buf * BUFB;
#pragma unroll
        for (int i = 0; i < 4; i++) {
            int lin = tid + i * 256;
            int mat = lin >> 9;
            int rem = lin & 511;
            int row = rem >> 3;
            int ch = rem & 7;
            const __half* s = (mat ? v_g : k_g) + (size_t)t * 64 * 64 + (size_t)row * 64 + ch * 8;
            uint32_t d = dbase + mat * OV + (uint32_t)(row * RS + ch * 16);
            asm volatile("cp.async.cg.shared.global [%0], [%1], 16;" :: "r"(d), "l"(s));
        }
        asm volatile("cp.async.commit_group;");
    };

    load_kv(0, 0);
    load_kv(1, 1);
    asm volatile("cp.async.wait_group 1;");
    __syncthreads();

    float m0 = -1e30f, m1 = -1e30f, l0 = 0.0f, l1 = 0.0f;
    float o[8][4];
#pragma unroll
    for (int nd = 0; nd < 8; nd++)
#pragma unroll
        for (int j = 0; j < 4; j++) o[nd][j] = 0.0f;

    const int g = lane >> 3, l7 = lane & 7;

    for (int t = 0; t < 32; t++) {
        const uint32_t kbuf = sbase + (t & 1) * BUFB;

        // ---- S = Q K^T, logits in log2 domain ----
        float c[8][4];
#pragma unroll
        for (int tn = 0; tn < 8; tn++)
#pragma unroll
            for (int j = 0; j < 4; j++) c[tn][j] = 0.0f;

#pragma unroll
        for (int kc = 0; kc < 4; kc++) {
            uint32_t bh[4][4];
#pragma unroll
            for (int p = 0; p < 4; p++) {
                int brow = (p * 2 + (g >> 1)) * 8 + l7;
                int bcolb = kc * 32 + (g & 1) * 16;
                ldsm4(bh[p], kbuf + (uint32_t)(brow * RS + bcolb));
            }
#pragma unroll
            for (int tn = 0; tn < 8; tn++)
                mma16816(c[tn], aq[kc],
                         bh[tn >> 1][(tn & 1) * 2], bh[tn >> 1][(tn & 1) * 2 + 1]);
        }

        // ---- online softmax: max, then packed-fp16 exp2 + MMA row sums ----
        float mx0 = -1e30f, mx1 = -1e30f;
#pragma unroll
        for (int tn = 0; tn < 8; tn++) {
            mx0 = fmaxf(mx0, fmaxf(c[tn][0], c[tn][1]));
            mx1 = fmaxf(mx1, fmaxf(c[tn][2], c[tn][3]));
        }
        mx0 = fmaxf(mx0, __shfl_xor_sync(0xffffffffu, mx0, 1));
        mx0 = fmaxf(mx0, __shfl_xor_sync(0xffffffffu, mx0, 2));
        mx1 = fmaxf(mx1, __shfl_xor_sync(0xffffffffu, mx1, 1));
        mx1 = fmaxf(mx1, __shfl_xor_sync(0xffffffffu, mx1, 2));
        float mn0 = fmaxf(m0, mx0), mn1 = fmaxf(m1, mx1);
        float al0 = fexp2(m0 - mn0), al1 = fexp2(m1 - mn1);
        m0 = mn0; m1 = mn1;

        // P = exp2(c - mn) packed fp16; row sums via MMA with ones
        uint32_t p[16];
        float sac[4] = {0.0f, 0.0f, 0.0f, 0.0f};
#pragma unroll
        for (int kc = 0; kc < 4; kc++) {
            p[kc * 4 + 0] = h2exp2(packh(c[2 * kc][0] - mn0,     c[2 * kc][1] - mn0));
            p[kc * 4 + 1] = h2exp2(packh(c[2 * kc][2] - mn1,     c[2 * kc][3] - mn1));
            p[kc * 4 + 2] = h2exp2(packh(c[2 * kc + 1][0] - mn0, c[2 * kc + 1][1] - mn0));
            p[kc * 4 + 3] = h2exp2(packh(c[2 * kc + 1][2] - mn1, c[2 * kc + 1][3] - mn1));
            mma16816(sac, &p[kc * 4], ONES_H2, ONES_H2);
        }
        l0 = l0 * al0 + sac[0];
        l1 = l1 * al1 + sac[2];
#pragma unroll
        for (int nd = 0; nd < 8; nd++) {
            o[nd][0] *= al0; o[nd][1] *= al0;
            o[nd][2] *= al1; o[nd][3] *= al1;
        }

        // ---- O += P V ----
#pragma unroll
        for (int kc = 0; kc < 4; kc++) {
#pragma unroll
            for (int dp = 0; dp < 4; dp++) {
                int vrow = kc * 16 + (g & 1) * 8 + l7;
                int vcolb = dp * 32 + (g >> 1) * 16;
                uint32_t vh[4];
                ldsm4t(vh, kbuf + OV + (uint32_t)(vrow * RS + vcolb));
                mma16816(o[dp * 2],     &p[kc * 4], vh[0], vh[1]);
                mma16816(o[dp * 2 + 1], &p[kc * 4], vh[2], vh[3]);
            }
        }

        __syncthreads();
        if (t + 2 < 32) load_kv(t + 2, t & 1);
        if (t + 1 < 32) {
            if (t + 2 < 32) { asm volatile("cp.async.wait_group 1;"); }
            else            { asm volatile("cp.async.wait_group 0;"); }
            __syncthreads();
        }
    }

    // ---- epilogue: normalize + single fp16 into [M,1024] ----
    const float inv0 = 1.0f / l0, inv1 = 1.0f / l1;
    const int r0 = q0 + wid * 16 + (lane >> 2);
    const size_t m0i = (size_t)(b * 2048) + r0;
    const int colb = h * 64 + (lane & 3) * 2;
#pragma unroll
    for (int nd = 0; nd < 8; nd++) {
        *reinterpret_cast<uint32_t*>(&g_a[m0i * 1024 + colb + nd * 8]) =
            packh(o[nd][0] * inv0, o[nd][1] * inv0);
        *reinterpret_cast<uint32_t*>(&g_a[(m0i + 8) * 1024 + colb + nd * 8]) =
            packh(o[nd][2] * inv1, o[nd][3] * inv1);
    }
}

// ---------------------------------------------------------------------------
// Launch
// ---------------------------------------------------------------------------
extern "C" void kernel_launch(void* const* d_in, const int* in_sizes, int n_in,
                              void* d_out, int out_size)
{
    const float* x      = (const float*)d_in[0];
    const float* qkv_w  = (const float*)d_in[1];
    const float* qkv_b  = (const float*)d_in[2];
    const float* qn_w   = (const float*)d_in[3];
    const float* kn_w   = (const float*)d_in[4];
    const float* proj_w = (const float*)d_in[5];
    const float* proj_b = (const float*)d_in[6];
    float* out = (float*)d_out;

    cudaFuncSetAttribute(gemm_qkv_fused, cudaFuncAttributeMaxDynamicSharedMemorySize, GEMM_SMEM);
    cudaFuncSetAttribute(gemm_mma, cudaFuncAttributeMaxDynamicSharedMemorySize, GEMM_SMEM);
    cudaFuncSetAttribute(attn_mma, cudaFuncAttributeMaxDynamicSharedMemorySize, ATTN_SMEM);

    void *p_xh, *p_w1h, *p_w2h, *p_a;
    cudaGetSymbolAddress(&p_xh, g_xh);
    cudaGetSymbolAddress(&p_w1h, g_w1h);
    cudaGetSymbolAddress(&p_w2h, g_w2h);
    cudaGetSymbolAddress(&p_a, g_a);

    rope_table<<<128, 256>>>();

    cvt_all<<<(NX4 + NW14 + NW24 + 255) / 256, 256>>>(
        (const float4*)x, (const float4*)qkv_w, (const float4*)proj_w,
        (uint2*)p_xh, (uint2*)p_w1h, (uint2*)p_w2h);

    // 1. QKV projection + fused RMSNorm/RoPE/fp16 emit (head-major q/k/v)
    gemm_qkv_fused<<<dim3(K3_ / 128, M_ / 128), 256, GEMM_SMEM>>>(
        (const __half*)p_xh, (const __half*)p_w1h, qkv_b, qn_w, kn_w);

    // 2. Tensor-core flash attention -> g_a [M,1024]
    attn_mma<<<dim3(N_ / 128, H_, B_), 256, ATTN_SMEM>>>();

    // 3. Output projection -> d_out
    gemm_mma<<<dim3(C_ / 128, M_ / 128), 256, GEMM_SMEM>>>(
        (const __half*)p_a, (const __half*)p_w2h, proj_b, out, C_);
}

// round 12
// speedup vs baseline: 7.1235x; 1.0149x over previous
#include <cuda_runtime.h>
#include <cuda_bf16.h>
#include <cuda_fp16.h>
#include <cstdint>
#include <math.h>

// Problem constants
#define B_  2
#define N_  2048
#define C_  1024
#define H_  16
#define D_  64
#define M_  (B_ * N_)        // 4096
#define K3_ (3 * C_)         // 3072

// ---------------------------------------------------------------------------
// Scratch (device globals)
// ---------------------------------------------------------------------------
__device__ __half g_xh[M_ * C_];                       // x single fp16
__device__ __half g_w1h[K3_ * C_];                     // qkv_w single fp16
__device__ __half g_w2h[C_ * C_];                      // proj_w single fp16
__device__ __half g_a[M_ * C_];                        // attention out single fp16
// head-major [b*16+h][n][64]
__device__ __half g_q[B_*H_*N_*D_];                    // Q single (pre-scaled)
__device__ __half g_k[B_*H_*N_*D_];                    // K single
__device__ __half g_v[B_*H_*N_*D_];                    // V single
__device__ float g_cos[1024 * 32], g_sin[1024 * 32];

// ---------------------------------------------------------------------------
// Helpers
// ---------------------------------------------------------------------------
__device__ __forceinline__ uint32_t smem_u32(const void* p) {
    uint32_t a;
    asm("{ .reg .u64 t; cvta.to.shared.u64 t, %1; cvt.u32.u64 %0, t; }" : "=r"(a) : "l"(p));
    return a;
}
__device__ __forceinline__ void ldsm4(uint32_t* r, uint32_t addr) {
    asm volatile("ldmatrix.sync.aligned.m8n8.x4.shared.b16 {%0,%1,%2,%3}, [%4];"
                 : "=r"(r[0]), "=r"(r[1]), "=r"(r[2]), "=r"(r[3]) : "r"(addr));
}
__device__ __forceinline__ void ldsm4t(uint32_t* r, uint32_t addr) {
    asm volatile("ldmatrix.sync.aligned.m8n8.x4.trans.shared.b16 {%0,%1,%2,%3}, [%4];"
                 : "=r"(r[0]), "=r"(r[1]), "=r"(r[2]), "=r"(r[3]) : "r"(addr));
}
__device__ __forceinline__ void mma16816(float* c, const uint32_t* a, uint32_t b0, uint32_t b1) {
    asm volatile("mma.sync.aligned.m16n8k16.row.col.f32.f16.f16.f32 "
                 "{%0,%1,%2,%3}, {%4,%5,%6,%7}, {%8,%9}, {%0,%1,%2,%3};"
                 : "+f"(c[0]), "+f"(c[1]), "+f"(c[2]), "+f"(c[3])
                 : "r"(a[0]), "r"(a[1]), "r"(a[2]), "r"(a[3]), "r"(b0), "r"(b1));
}
__device__ __forceinline__ uint32_t packh(float a, float b) {
    uint32_t r;
    asm("cvt.rn.f16x2.f32 %0, %1, %2;" : "=r"(r) : "f"(b), "f"(a));
    return r;
}
__device__ __forceinline__ float fexp2(float x) {
    float r;
    asm("ex2.approx.f32 %0, %1;" : "=f"(r) : "f"(x));
    return r;
}
__device__ __forceinline__ uint32_t h2exp2(uint32_t x) {
    uint32_t r;
    asm("ex2.approx.f16x2 %0, %1;" : "=r"(r) : "r"(x));
    return r;
}

#define QSCALE 0.1803368801111137f   // 0.125 * log2(e)
#define ONES_H2 0x3C003C00u          // fp16x2 {1.0, 1.0}

// ---------------------------------------------------------------------------
// Merged fp32 -> fp16 convert for x, qkv_w, proj_w
// ---------------------------------------------------------------------------
#define NX4  (M_ * C_ / 4)
#define NW14 (K3_ * C_ / 4)
#define NW24 (C_ * C_ / 4)

__global__ __launch_bounds__(256) void cvt_all(const float4* __restrict__ x,
                                               const float4* __restrict__ w1,
                                               const float4* __restrict__ w2,
                                               uint2* __restrict__ xh,
                                               uint2* __restrict__ w1h,
                                               uint2* __restrict__ w2h)
{
    int i = blockIdx.x * 256 + threadIdx.x;
    const float4* s;
    uint2* d;
    if (i < NX4)              { s = x + i;                 d = xh + i; }
    else if (i < NX4 + NW14)  { s = w1 + (i - NX4);        d = w1h + (i - NX4); }
    else                      { s = w2 + (i - NX4 - NW14); d = w2h + (i - NX4 - NW14); }
    float4 v = *s;
    *d = make_uint2(packh(v.x, v.y), packh(v.z, v.w));
}

// ---------------------------------------------------------------------------
// RoPE tables
// ---------------------------------------------------------------------------
__global__ __launch_bounds__(256) void rope_table()
{
    int idx = blockIdx.x * 256 + threadIdx.x;          // 32768
    int pos = idx >> 5, lane = idx & 31;
    float e = (float)(2 * lane) * (1.0f / 64.0f);
    float inv = expf(-9.210340371976184f * e);
    float ang = (float)pos * inv;
    g_cos[idx] = cosf(ang);
    g_sin[idx] = sinf(ang);
}

// ---------------------------------------------------------------------------
// Shared GEMM config (block 128x128, K=1024, chunk 32, 8 warps 4x2)
// Stage: 2 matrices (A, B), 20480 B; 3-stage pipeline.
// ---------------------------------------------------------------------------
#define STAGE_B 20480
#define GEMM_SMEM (3 * STAGE_B)   // 61440

// ---------------------------------------------------------------------------
// QKV GEMM (single-pass fp16) with FUSED RMSNorm + RoPE + fp16 emit.
// ---------------------------------------------------------------------------
__global__ __launch_bounds__(256, 2) void gemm_qkv_fused(
    const __half* __restrict__ Ah, const __half* __restrict__ Bh,
    const float* __restrict__ bias,
    const float* __restrict__ qn_w, const float* __restrict__ kn_w)
{
    extern __shared__ char sm[];
    const uint32_t sbase = smem_u32(sm);
    const int tid = threadIdx.x;
    const int lane = tid & 31;
    const int wid = tid >> 5;
    const int warp_m = wid >> 1;
    const int warp_n = wid & 1;
    const int row0 = blockIdx.y * 128;
    const int col0 = blockIdx.x * 128;

    float acc[2][8][4];
#pragma unroll
    for (int a = 0; a < 2; a++)
#pragma unroll
        for (int b = 0; b < 8; b++)
#pragma unroll
            for (int c = 0; c < 4; c++) acc[a][b][c] = 0.0f;

    const __half* srcs[2] = { Ah + (size_t)row0 * 1024, Bh + (size_t)col0 * 1024 };

    auto load_stage = [&](int c, int buf) {
#pragma unroll
        for (int i = 0; i < 4; i++) {
            int lin = tid + i * 256;
            int mat = lin >> 9;
            int rem = lin & 511;
            int row = rem >> 2;
            int ch = rem & 3;
            const __half* s = srcs[mat] + (size_t)row * 1024 + c * 32 + ch * 8;
            uint32_t d = sbase + buf * STAGE_B + mat * 10240 + (uint32_t)(row * 40 + ch * 8) * 2;
            asm volatile("cp.async.cg.shared.global [%0], [%1], 16;" :: "r"(d), "l"(s));
        }
        asm volatile("cp.async.commit_group;");
    };

    load_stage(0, 0);
    load_stage(1, 1);
    for (int c = 0; c < 32; c++) {
        const int buf = c % 3;
        if (c + 2 < 32) { load_stage(c + 2, (c + 2) % 3); asm volatile("cp.async.wait_group 2;"); }
        else if (c + 1 < 32) { asm volatile("cp.async.wait_group 1;"); }
        else { asm volatile("cp.async.wait_group 0;"); }
        __syncthreads();
        const uint32_t base = sbase + buf * STAGE_B;
#pragma unroll
        for (int kk = 0; kk < 2; kk++) {
            uint32_t ah[2][4], bh[4][4];
            int arow = warp_m * 32 + (lane & 15);
            int acol = kk * 16 + (lane >> 4) * 8;
            uint32_t aoff = (uint32_t)(arow * 40 + acol) * 2;
            ldsm4(ah[0], base + aoff);
            ldsm4(ah[1], base + aoff + 1280);
            int g = lane >> 3, l7 = lane & 7;
#pragma unroll
            for (int p = 0; p < 4; p++) {
                int brow = warp_n * 64 + (p * 2 + (g >> 1)) * 8 + l7;
                int bcol = kk * 16 + (g & 1) * 8;
                ldsm4(bh[p], base + 10240 + (uint32_t)(brow * 40 + bcol) * 2);
            }
#pragma unroll
            for (int tm = 0; tm < 2; tm++)
#pragma unroll
                for (int tn = 0; tn < 8; tn++)
                    mma16816(acc[tm][tn], ah[tm],
                             bh[tn >> 1][(tn & 1) * 2], bh[tn >> 1][(tn & 1) * 2 + 1]);
        }
        __syncthreads();
    }

    // ---- fused epilogue ----
    const int sec = col0 >> 10;                         // 0=q, 1=k, 2=v
    const int head = ((col0 & 1023) >> 6) + warp_n;
    const int d0 = (lane & 3) * 2;

    float bs[8][2], wv[8][2];
    const float* w = (sec == 1) ? kn_w : qn_w;
#pragma unroll
    for (int tn = 0; tn < 8; tn++) {
        int d = tn * 8 + d0;
        int col = col0 + warp_n * 64 + d;
        bs[tn][0] = __ldg(&bias[col]);
        bs[tn][1] = __ldg(&bias[col + 1]);
        if (sec < 2) { wv[tn][0] = __ldg(&w[d]); wv[tn][1] = __ldg(&w[d + 1]); }
    }

    auto process_row = [&](float v[8][2], int m) {
        const int n = m & 2047;
        const int bb = m >> 11;
        const size_t obase = (((size_t)(bb * 16 + head)) * 2048 + n) * 64;
        if (sec == 2) {
#pragma unroll
            for (int tn = 0; tn < 8; tn++)
                *reinterpret_cast<uint32_t*>(&g_v[obase + tn * 8 + d0]) = packh(v[tn][0], v[tn][1]);
            return;
        }
        float ss = 0.0f;
#pragma unroll
        for (int tn = 0; tn < 8; tn++) ss += v[tn][0] * v[tn][0] + v[tn][1] * v[tn][1];
        ss += __shfl_xor_sync(0xffffffffu, ss, 1);
        ss += __shfl_xor_sync(0xffffffffu, ss, 2);
        float rs = rsqrtf(ss * (1.0f / 64.0f) + 1e-6f);
#pragma unroll
        for (int tn = 0; tn < 8; tn++) {
            v[tn][0] *= rs * wv[tn][0];
            v[tn][1] *= rs * wv[tn][1];
        }
        int pos = (n < 1024) ? n : ((n < 1536) ? (n - 1024) : -1);
        if (pos >= 0) {
#pragma unroll
            for (int tn = 0; tn < 4; tn++) {
                int idx = pos * 32 + tn * 8 + d0;
#pragma unroll
                for (int j = 0; j < 2; j++) {
                    float cs = g_cos[idx + j], sn = g_sin[idx + j];
                    float t1 = v[tn][j], t2 = v[tn + 4][j];
                    v[tn][j]     = t1 * cs - t2 * sn;
                    v[tn + 4][j] = t2 * cs + t1 * sn;
                }
            }
        }
        if (sec == 0) {
#pragma unroll
            for (int tn = 0; tn < 8; tn++)
                *reinterpret_cast<uint32_t*>(&g_q[obase + tn * 8 + d0]) =
                    packh(v[tn][0] * QSCALE, v[tn][1] * QSCALE);
        } else {
#pragma unroll
            for (int tn = 0; tn < 8; tn++)
                *reinterpret_cast<uint32_t*>(&g_k[obase + tn * 8 + d0]) = packh(v[tn][0], v[tn][1]);
        }
    };

#pragma unroll
    for (int tm = 0; tm < 2; tm++) {
        const int mA = row0 + warp_m * 32 + tm * 16 + (lane >> 2);
        float vA[8][2], vB[8][2];
#pragma unroll
        for (int tn = 0; tn < 8; tn++) {
            vA[tn][0] = acc[tm][tn][0] + bs[tn][0];
            vA[tn][1] = acc[tm][tn][1] + bs[tn][1];
            vB[tn][0] = acc[tm][tn][2] + bs[tn][0];
            vB[tn][1] = acc[tm][tn][3] + bs[tn][1];
        }
        process_row(vA, mA);
        process_row(vB, mA + 8);
    }
}

// ---------------------------------------------------------------------------
// Generic single-pass fp16 GEMM (proj): out = A.B^T + bias
// ---------------------------------------------------------------------------
__global__ __launch_bounds__(256, 2) void gemm_mma(
    const __half* __restrict__ Ah, const __half* __restrict__ Bh,
    const float* __restrict__ bias, float* __restrict__ out, int ostride)
{
    extern __shared__ char sm[];
    const uint32_t sbase = smem_u32(sm);
    const int tid = threadIdx.x;
    const int lane = tid & 31;
    const int wid = tid >> 5;
    const int warp_m = wid >> 1;
    const int warp_n = wid & 1;
    const int row0 = blockIdx.y * 128;
    const int col0 = blockIdx.x * 128;

    float acc[2][8][4];
#pragma unroll
    for (int a = 0; a < 2; a++)
#pragma unroll
        for (int b = 0; b < 8; b++)
#pragma unroll
            for (int c = 0; c < 4; c++) acc[a][b][c] = 0.0f;

    const __half* srcs[2] = { Ah + (size_t)row0 * 1024, Bh + (size_t)col0 * 1024 };

    auto load_stage = [&](int c, int buf) {
#pragma unroll
        for (int i = 0; i < 4; i++) {
            int lin = tid + i * 256;
            int mat = lin >> 9;
            int rem = lin & 511;
            int row = rem >> 2;
            int ch = rem & 3;
            const __half* s = srcs[mat] + (size_t)row * 1024 + c * 32 + ch * 8;
            uint32_t d = sbase + buf * STAGE_B + mat * 10240 + (uint32_t)(row * 40 + ch * 8) * 2;
            asm volatile("cp.async.cg.shared.global [%0], [%1], 16;" :: "r"(d), "l"(s));
        }
        asm volatile("cp.async.commit_group;");
    };

    load_stage(0, 0);
    load_stage(1, 1);
    for (int c = 0; c < 32; c++) {
        const int buf = c % 3;
        if (c + 2 < 32) { load_stage(c + 2, (c + 2) % 3); asm volatile("cp.async.wait_group 2;"); }
        else if (c + 1 < 32) { asm volatile("cp.async.wait_group 1;"); }
        else { asm volatile("cp.async.wait_group 0;"); }
        __syncthreads();
        const uint32_t base = sbase + buf * STAGE_B;
#pragma unroll
        for (int kk = 0; kk < 2; kk++) {
            uint32_t ah[2][4], bh[4][4];
            int arow = warp_m * 32 + (lane & 15);
            int acol = kk * 16 + (lane >> 4) * 8;
            uint32_t aoff = (uint32_t)(arow * 40 + acol) * 2;
            ldsm4(ah[0], base + aoff);
            ldsm4(ah[1], base + aoff + 1280);
            int g = lane >> 3, l7 = lane & 7;
#pragma unroll
            for (int p = 0; p < 4; p++) {
                int brow = warp_n * 64 + (p * 2 + (g >> 1)) * 8 + l7;
                int bcol = kk * 16 + (g & 1) * 8;
                ldsm4(bh[p], base + 10240 + (uint32_t)(brow * 40 + bcol) * 2);
            }
#pragma unroll
            for (int tm = 0; tm < 2; tm++)
#pragma unroll
                for (int tn = 0; tn < 8; tn++)
                    mma16816(acc[tm][tn], ah[tm],
                             bh[tn >> 1][(tn & 1) * 2], bh[tn >> 1][(tn & 1) * 2 + 1]);
        }
        __syncthreads();
    }

#pragma unroll
    for (int tm = 0; tm < 2; tm++) {
        int mb = row0 + warp_m * 32 + tm * 16 + (lane >> 2);
#pragma unroll
        for (int tn = 0; tn < 8; tn++) {
            int col = col0 + warp_n * 64 + tn * 8 + (lane & 3) * 2;
            float b0 = __ldg(&bias[col]), b1 = __ldg(&bias[col + 1]);
            *reinterpret_cast<float2*>(&out[(size_t)mb * ostride + col]) =
                make_float2(acc[tm][tn][0] + b0, acc[tm][tn][1] + b1);
            *reinterpret_cast<float2*>(&out[(size_t)(mb + 8) * ostride + col]) =
                make_float2(acc[tm][tn][2] + b0, acc[tm][tn][3] + b1);
        }
    }
}

// ---------------------------------------------------------------------------
// Flash attention: 256 queries/CTA, warp = 32 rows (2 x 16-row blocks
// sharing every K/V fragment) -> smem crossbar traffic per row halved.
// 1 CTA/SM (regs ~190). Q staged through both KV buffers, hoisted.
// ---------------------------------------------------------------------------
#define RS   144
#define BUFB 18432                // per KV buffer: K 9216 + V 9216
#define OV   9216
#define ATTN_SMEM (2 * BUFB)      // 36864

__global__ __launch_bounds__(256, 1) void attn_mma()
{
    extern __shared__ char sm[];
    const uint32_t sbase = smem_u32(sm);
    const int tid = threadIdx.x;
    const int lane = tid & 31;
    const int wid = tid >> 5;
    const int q0 = blockIdx.x * 256;
    const int h = blockIdx.y;
    const int b = blockIdx.z;
    const size_t hb = ((size_t)(b * 16 + h)) * 2048 * 64;

    const __half* q_g = g_q + hb + (size_t)q0 * 64;
    const __half* k_g = g_k + hb;
    const __half* v_g = g_v + hb;

    // ---- stage Q (256 rows, 32KB) through BOTH KV buffers, hoist ----
    {
#pragma unroll
        for (int i = 0; i < 8; i++) {
            int lin = tid + i * 256;          // 0..2047 (256 rows x 8 chunks)
            int row = lin >> 3;
            int ch = lin & 7;
            const __half* s = q_g + (size_t)row * 64 + ch * 8;
            uint32_t d = sbase + (uint32_t)(row * RS + ch * 16);
            asm volatile("cp.async.cg.shared.global [%0], [%1], 16;" :: "r"(d), "l"(s));
        }
        asm volatile("cp.async.commit_group;");
        asm volatile("cp.async.wait_group 0;");
        __syncthreads();
    }

    uint32_t aq[2][4][4];
    {
        const int acolb = (lane >> 4) * 16;
#pragma unroll
        for (int blk = 0; blk < 2; blk++) {
            const int arow = wid * 32 + blk * 16 + (lane & 15);
#pragma unroll
            for (int kc = 0; kc < 4; kc++)
                ldsm4(aq[blk][kc], sbase + (uint32_t)(arow * RS + kc * 32 + acolb));
        }
    }
    __syncthreads();   // all warps hoisted before KV overwrites Q

    auto load_kv = [&](int t, int buf) {
        const uint32_t dbase = sbase + buf * BUFB;
#pragma unroll
        for (int i = 0; i < 4; i++) {
            int lin = tid + i * 256;
            int mat = lin >> 9;
            int rem = lin & 511;
            int row = rem >> 3;
            int ch = rem & 7;
            const __half* s = (mat ? v_g : k_g) + (size_t)t * 64 * 64 + (size_t)row * 64 + ch * 8;
            uint32_t d = dbase + mat * OV + (uint32_t)(row * RS + ch * 16);
            asm volatile("cp.async.cg.shared.global [%0], [%1], 16;" :: "r"(d), "l"(s));
        }
        asm volatile("cp.async.commit_group;");
    };

    load_kv(0, 0);
    load_kv(1, 1);
    asm volatile("cp.async.wait_group 1;");
    __syncthreads();

    float mrow[2][2], lrow[2][2];
    float o[2][8][4];
#pragma unroll
    for (int blk = 0; blk < 2; blk++) {
        mrow[blk][0] = -1e30f; mrow[blk][1] = -1e30f;
        lrow[blk][0] = 0.0f;   lrow[blk][1] = 0.0f;
#pragma unroll
        for (int nd = 0; nd < 8; nd++)
#pragma unroll
            for (int j = 0; j < 4; j++) o[blk][nd][j] = 0.0f;
    }

    const int g = lane >> 3, l7 = lane & 7;

    for (int t = 0; t < 32; t++) {
        const uint32_t kbuf = sbase + (t & 1) * BUFB;

        // ---- S = Q K^T (K frags shared across both row blocks) ----
        float c[2][8][4];
#pragma unroll
        for (int blk = 0; blk < 2; blk++)
#pragma unroll
            for (int tn = 0; tn < 8; tn++)
#pragma unroll
                for (int j = 0; j < 4; j++) c[blk][tn][j] = 0.0f;

#pragma unroll
        for (int kc = 0; kc < 4; kc++) {
            uint32_t bh[4][4];
#pragma unroll
            for (int p = 0; p < 4; p++) {
                int brow = (p * 2 + (g >> 1)) * 8 + l7;
                int bcolb = kc * 32 + (g & 1) * 16;
                ldsm4(bh[p], kbuf + (uint32_t)(brow * RS + bcolb));
            }
#pragma unroll
            for (int blk = 0; blk < 2; blk++)
#pragma unroll
                for (int tn = 0; tn < 8; tn++)
                    mma16816(c[blk][tn], aq[blk][kc],
                             bh[tn >> 1][(tn & 1) * 2], bh[tn >> 1][(tn & 1) * 2 + 1]);
        }

        // ---- online softmax (per row block) + packed exp2 + MMA row sums ----
        uint32_t p[2][16];
        float al[2][2];
#pragma unroll
        for (int blk = 0; blk < 2; blk++) {
            float mx0 = -1e30f, mx1 = -1e30f;
#pragma unroll
            for (int tn = 0; tn < 8; tn++) {
                mx0 = fmaxf(mx0, fmaxf(c[blk][tn][0], c[blk][tn][1]));
                mx1 = fmaxf(mx1, fmaxf(c[blk][tn][2], c[blk][tn][3]));
            }
            mx0 = fmaxf(mx0, __shfl_xor_sync(0xffffffffu, mx0, 1));
            mx0 = fmaxf(mx0, __shfl_xor_sync(0xffffffffu, mx0, 2));
            mx1 = fmaxf(mx1, __shfl_xor_sync(0xffffffffu, mx1, 1));
            mx1 = fmaxf(mx1, __shfl_xor_sync(0xffffffffu, mx1, 2));
            float mn0 = fmaxf(mrow[blk][0], mx0), mn1 = fmaxf(mrow[blk][1], mx1);
            al[blk][0] = fexp2(mrow[blk][0] - mn0);
            al[blk][1] = fexp2(mrow[blk][1] - mn1);
            mrow[blk][0] = mn0; mrow[blk][1] = mn1;

            float sac[4] = {0.0f, 0.0f, 0.0f, 0.0f};
#pragma unroll
            for (int kc = 0; kc < 4; kc++) {
                p[blk][kc * 4 + 0] = h2exp2(packh(c[blk][2 * kc][0] - mn0,     c[blk][2 * kc][1] - mn0));
                p[blk][kc * 4 + 1] = h2exp2(packh(c[blk][2 * kc][2] - mn1,     c[blk][2 * kc][3] - mn1));
                p[blk][kc * 4 + 2] = h2exp2(packh(c[blk][2 * kc + 1][0] - mn0, c[blk][2 * kc + 1][1] - mn0));
                p[blk][kc * 4 + 3] = h2exp2(packh(c[blk][2 * kc + 1][2] - mn1, c[blk][2 * kc + 1][3] - mn1));
                mma16816(sac, &p[blk][kc * 4], ONES_H2, ONES_H2);
            }
            lrow[blk][0] = lrow[blk][0] * al[blk][0] + sac[0];
            lrow[blk][1] = lrow[blk][1] * al[blk][1] + sac[2];
#pragma unroll
            for (int nd = 0; nd < 8; nd++) {
                o[blk][nd][0] *= al[blk][0]; o[blk][nd][1] *= al[blk][0];
                o[blk][nd][2] *= al[blk][1]; o[blk][nd][3] *= al[blk][1];
            }
        }

        // ---- O += P V (V frags shared across both row blocks) ----
#pragma unroll
        for (int kc = 0; kc < 4; kc++) {
#pragma unroll
            for (int dp = 0; dp < 4; dp++) {
                int vrow = kc * 16 + (g & 1) * 8 + l7;
                int vcolb = dp * 32 + (g >> 1) * 16;
                uint32_t vh[4];
                ldsm4t(vh, kbuf + OV + (uint32_t)(vrow * RS + vcolb));
#pragma unroll
                for (int blk = 0; blk < 2; blk++) {
                    mma16816(o[blk][dp * 2],     &p[blk][kc * 4], vh[0], vh[1]);
                    mma16816(o[blk][dp * 2 + 1], &p[blk][kc * 4], vh[2], vh[3]);
                }
            }
        }

        __syncthreads();
        if (t + 2 < 32) load_kv(t + 2, t & 1);
        if (t + 1 < 32) {
            if (t + 2 < 32) { asm volatile("cp.async.wait_group 1;"); }
            else            { asm volatile("cp.async.wait_group 0;"); }
            __syncthreads();
        }
    }

    // ---- epilogue: normalize + single fp16 into [M,1024] ----
    const int colb = h * 64 + (lane & 3) * 2;
#pragma unroll
    for (int blk = 0; blk < 2; blk++) {
        const float inv0 = 1.0f / lrow[blk][0], inv1 = 1.0f / lrow[blk][1];
        const int r0 = q0 + wid * 32 + blk * 16 + (lane >> 2);
        const size_t m0i = (size_t)(b * 2048) + r0;
#pragma unroll
        for (int nd = 0; nd < 8; nd++) {
            *reinterpret_cast<uint32_t*>(&g_a[m0i * 1024 + colb + nd * 8]) =
                packh(o[blk][nd][0] * inv0, o[blk][nd][1] * inv0);
            *reinterpret_cast<uint32_t*>(&g_a[(m0i + 8) * 1024 + colb + nd * 8]) =
                packh(o[blk][nd][2] * inv1, o[blk][nd][3] * inv1);
        }
    }
}

// ---------------------------------------------------------------------------
// Launch
// ---------------------------------------------------------------------------
extern "C" void kernel_launch(void* const* d_in, const int* in_sizes, int n_in,
                              void* d_out, int out_size)
{
    const float* x      = (const float*)d_in[0];
    const float* qkv_w  = (const float*)d_in[1];
    const float* qkv_b  = (const float*)d_in[2];
    const float* qn_w   = (const float*)d_in[3];
    const float* kn_w   = (const float*)d_in[4];
    const float* proj_w = (const float*)d_in[5];
    const float* proj_b = (const float*)d_in[6];
    float* out = (float*)d_out;

    cudaFuncSetAttribute(gemm_qkv_fused, cudaFuncAttributeMaxDynamicSharedMemorySize, GEMM_SMEM);
    cudaFuncSetAttribute(gemm_mma, cudaFuncAttributeMaxDynamicSharedMemorySize, GEMM_SMEM);
    cudaFuncSetAttribute(attn_mma, cudaFuncAttributeMaxDynamicSharedMemorySize, ATTN_SMEM);

    void *p_xh, *p_w1h, *p_w2h, *p_a;
    cudaGetSymbolAddress(&p_xh, g_xh);
    cudaGetSymbolAddress(&p_w1h, g_w1h);
    cudaGetSymbolAddress(&p_w2h, g_w2h);
    cudaGetSymbolAddress(&p_a, g_a);

    rope_table<<<128, 256>>>();

    cvt_all<<<(NX4 + NW14 + NW24 + 255) / 256, 256>>>(
        (const float4*)x, (const float4*)qkv_w, (const float4*)proj_w,
        (uint2*)p_xh, (uint2*)p_w1h, (uint2*)p_w2h);

    // 1. QKV projection + fused RMSNorm/RoPE/fp16 emit (head-major q/k/v)
    gemm_qkv_fused<<<dim3(K3_ / 128, M_ / 128), 256, GEMM_SMEM>>>(
        (const __half*)p_xh, (const __half*)p_w1h, qkv_b, qn_w, kn_w);

    // 2. Tensor-core flash attention (256 q/CTA) -> g_a [M,1024]
    attn_mma<<<dim3(N_ / 256, H_, B_), 256, ATTN_SMEM>>>();

    // 3. Output projection -> d_out
    gemm_mma<<<dim3(C_ / 128, M_ / 128), 256, GEMM_SMEM>>>(
        (const __half*)p_a, (const __half*)p_w2h, proj_b, out, C_);
}

// round 13
// speedup vs baseline: 7.1297x; 1.0009x over previous
#include <cuda_runtime.h>
#include <cuda_bf16.h>
#include <cuda_fp16.h>
#include <cstdint>
#include <math.h>

// Problem constants
#define B_  2
#define N_  2048
#define C_  1024
#define H_  16
#define D_  64
#define M_  (B_ * N_)        // 4096
#define K3_ (3 * C_)         // 3072

// ---------------------------------------------------------------------------
// Scratch (device globals)
// ---------------------------------------------------------------------------
__device__ __half g_xh[M_ * C_];                       // x single fp16
__device__ __half g_w1h[K3_ * C_];                     // qkv_w single fp16
__device__ __half g_w2h[C_ * C_];                      // proj_w single fp16
__device__ __half g_a[M_ * C_];                        // attention out single fp16
// head-major [b*16+h][n][64]
__device__ __half g_q[B_*H_*N_*D_];                    // Q single (pre-scaled)
__device__ __half g_k[B_*H_*N_*D_];                    // K single
__device__ __half g_v[B_*H_*N_*D_];                    // V single
__device__ float g_cos[1024 * 32], g_sin[1024 * 32];

// ---------------------------------------------------------------------------
// Helpers
// ---------------------------------------------------------------------------
__device__ __forceinline__ uint32_t smem_u32(const void* p) {
    uint32_t a;
    asm("{ .reg .u64 t; cvta.to.shared.u64 t, %1; cvt.u32.u64 %0, t; }" : "=r"(a) : "l"(p));
    return a;
}
__device__ __forceinline__ void ldsm4(uint32_t* r, uint32_t addr) {
    asm volatile("ldmatrix.sync.aligned.m8n8.x4.shared.b16 {%0,%1,%2,%3}, [%4];"
                 : "=r"(r[0]), "=r"(r[1]), "=r"(r[2]), "=r"(r[3]) : "r"(addr));
}
__device__ __forceinline__ void ldsm4t(uint32_t* r, uint32_t addr) {
    asm volatile("ldmatrix.sync.aligned.m8n8.x4.trans.shared.b16 {%0,%1,%2,%3}, [%4];"
                 : "=r"(r[0]), "=r"(r[1]), "=r"(r[2]), "=r"(r[3]) : "r"(addr));
}
__device__ __forceinline__ void mma16816(float* c, const uint32_t* a, uint32_t b0, uint32_t b1) {
    asm volatile("mma.sync.aligned.m16n8k16.row.col.f32.f16.f16.f32 "
                 "{%0,%1,%2,%3}, {%4,%5,%6,%7}, {%8,%9}, {%0,%1,%2,%3};"
                 : "+f"(c[0]), "+f"(c[1]), "+f"(c[2]), "+f"(c[3])
                 : "r"(a[0]), "r"(a[1]), "r"(a[2]), "r"(a[3]), "r"(b0), "r"(b1));
}
__device__ __forceinline__ uint32_t packh(float a, float b) {
    uint32_t r;
    asm("cvt.rn.f16x2.f32 %0, %1, %2;" : "=r"(r) : "f"(b), "f"(a));
    return r;
}
__device__ __forceinline__ float fexp2(float x) {
    float r;
    asm("ex2.approx.f32 %0, %1;" : "=f"(r) : "f"(x));
    return r;
}
__device__ __forceinline__ uint32_t h2exp2(uint32_t x) {
    uint32_t r;
    asm("ex2.approx.f16x2 %0, %1;" : "=r"(r) : "r"(x));
    return r;
}

#define QSCALE 0.1803368801111137f   // 0.125 * log2(e)
#define ONES_H2 0x3C003C00u          // fp16x2 {1.0, 1.0}

// ---------------------------------------------------------------------------
// Merged fp32 -> fp16 convert for x, qkv_w, proj_w
// ---------------------------------------------------------------------------
#define NX4  (M_ * C_ / 4)
#define NW14 (K3_ * C_ / 4)
#define NW24 (C_ * C_ / 4)

__global__ __launch_bounds__(256) void cvt_all(const float4* __restrict__ x,
                                               const float4* __restrict__ w1,
                                               const float4* __restrict__ w2,
                                               uint2* __restrict__ xh,
                                               uint2* __restrict__ w1h,
                                               uint2* __restrict__ w2h)
{
    int i = blockIdx.x * 256 + threadIdx.x;
    const float4* s;
    uint2* d;
    if (i < NX4)              { s = x + i;                 d = xh + i; }
    else if (i < NX4 + NW14)  { s = w1 + (i - NX4);        d = w1h + (i - NX4); }
    else                      { s = w2 + (i - NX4 - NW14); d = w2h + (i - NX4 - NW14); }
    float4 v = *s;
    *d = make_uint2(packh(v.x, v.y), packh(v.z, v.w));
}

// ---------------------------------------------------------------------------
// RoPE tables
// ---------------------------------------------------------------------------
__global__ __launch_bounds__(256) void rope_table()
{
    int idx = blockIdx.x * 256 + threadIdx.x;          // 32768
    int pos = idx >> 5, lane = idx & 31;
    float e = (float)(2 * lane) * (1.0f / 64.0f);
    float inv = expf(-9.210340371976184f * e);
    float ang = (float)pos * inv;
    g_cos[idx] = cosf(ang);
    g_sin[idx] = sinf(ang);
}

// ---------------------------------------------------------------------------
// Shared GEMM config (block 128x128, K=1024, chunk 32, 8 warps 4x2)
// ---------------------------------------------------------------------------
#define STAGE_B 20480
#define GEMM_SMEM (3 * STAGE_B)   // 61440

// ---------------------------------------------------------------------------
// QKV GEMM (single-pass fp16) with FUSED RMSNorm + RoPE + fp16 emit.
// ---------------------------------------------------------------------------
__global__ __launch_bounds__(256, 2) void gemm_qkv_fused(
    const __half* __restrict__ Ah, const __half* __restrict__ Bh,
    const float* __restrict__ bias,
    const float* __restrict__ qn_w, const float* __restrict__ kn_w)
{
    extern __shared__ char sm[];
    const uint32_t sbase = smem_u32(sm);
    const int tid = threadIdx.x;
    const int lane = tid & 31;
    const int wid = tid >> 5;
    const int warp_m = wid >> 1;
    const int warp_n = wid & 1;
    const int row0 = blockIdx.y * 128;
    const int col0 = blockIdx.x * 128;

    float acc[2][8][4];
#pragma unroll
    for (int a = 0; a < 2; a++)
#pragma unroll
        for (int b = 0; b < 8; b++)
#pragma unroll
            for (int c = 0; c < 4; c++) acc[a][b][c] = 0.0f;

    const __half* srcs[2] = { Ah + (size_t)row0 * 1024, Bh + (size_t)col0 * 1024 };

    auto load_stage = [&](int c, int buf) {
#pragma unroll
        for (int i = 0; i < 4; i++) {
            int lin = tid + i * 256;
            int mat = lin >> 9;
            int rem = lin & 511;
            int row = rem >> 2;
            int ch = rem & 3;
            const __half* s = srcs[mat] + (size_t)row * 1024 + c * 32 + ch * 8;
            uint32_t d = sbase + buf * STAGE_B + mat * 10240 + (uint32_t)(row * 40 + ch * 8) * 2;
            asm volatile("cp.async.cg.shared.global [%0], [%1], 16;" :: "r"(d), "l"(s));
        }
        asm volatile("cp.async.commit_group;");
    };

    load_stage(0, 0);
    load_stage(1, 1);
    for (int c = 0; c < 32; c++) {
        const int buf = c % 3;
        if (c + 2 < 32) { load_stage(c + 2, (c + 2) % 3); asm volatile("cp.async.wait_group 2;"); }
        else if (c + 1 < 32) { asm volatile("cp.async.wait_group 1;"); }
        else { asm volatile("cp.async.wait_group 0;"); }
        __syncthreads();
        const uint32_t base = sbase + buf * STAGE_B;
#pragma unroll
        for (int kk = 0; kk < 2; kk++) {
            uint32_t ah[2][4], bh[4][4];
            int arow = warp_m * 32 + (lane & 15);
            int acol = kk * 16 + (lane >> 4) * 8;
            uint32_t aoff = (uint32_t)(arow * 40 + acol) * 2;
            ldsm4(ah[0], base + aoff);
            ldsm4(ah[1], base + aoff + 1280);
            int g = lane >> 3, l7 = lane & 7;
#pragma unroll
            for (int p = 0; p < 4; p++) {
                int brow = warp_n * 64 + (p * 2 + (g >> 1)) * 8 + l7;
                int bcol = kk * 16 + (g & 1) * 8;
                ldsm4(bh[p], base + 10240 + (uint32_t)(brow * 40 + bcol) * 2);
            }
#pragma unroll
            for (int tm = 0; tm < 2; tm++)
#pragma unroll
                for (int tn = 0; tn < 8; tn++)
                    mma16816(acc[tm][tn], ah[tm],
                             bh[tn >> 1][(tn & 1) * 2], bh[tn >> 1][(tn & 1) * 2 + 1]);
        }
        __syncthreads();
    }

    // ---- fused epilogue ----
    const int sec = col0 >> 10;                         // 0=q, 1=k, 2=v
    const int head = ((col0 & 1023) >> 6) + warp_n;
    const int d0 = (lane & 3) * 2;

    float bs[8][2], wv[8][2];
    const float* w = (sec == 1) ? kn_w : qn_w;
#pragma unroll
    for (int tn = 0; tn < 8; tn++) {
        int d = tn * 8 + d0;
        int col = col0 + warp_n * 64 + d;
        bs[tn][0] = __ldg(&bias[col]);
        bs[tn][1] = __ldg(&bias[col + 1]);
        if (sec < 2) { wv[tn][0] = __ldg(&w[d]); wv[tn][1] = __ldg(&w[d + 1]); }
    }

    auto process_row = [&](float v[8][2], int m) {
        const int n = m & 2047;
        const int bb = m >> 11;
        const size_t obase = (((size_t)(bb * 16 + head)) * 2048 + n) * 64;
        if (sec == 2) {
#pragma unroll
            for (int tn = 0; tn < 8; tn++)
                *reinterpret_cast<uint32_t*>(&g_v[obase + tn * 8 + d0]) = packh(v[tn][0], v[tn][1]);
            return;
        }
        float ss = 0.0f;
#pragma unroll
        for (int tn = 0; tn < 8; tn++) ss += v[tn][0] * v[tn][0] + v[tn][1] * v[tn][1];
        ss += __shfl_xor_sync(0xffffffffu, ss, 1);
        ss += __shfl_xor_sync(0xffffffffu, ss, 2);
        float rs = rsqrtf(ss * (1.0f / 64.0f) + 1e-6f);
#pragma unroll
        for (int tn = 0; tn < 8; tn++) {
            v[tn][0] *= rs * wv[tn][0];
            v[tn][1] *= rs * wv[tn][1];
        }
        int pos = (n < 1024) ? n : ((n < 1536) ? (n - 1024) : -1);
        if (pos >= 0) {
#pragma unroll
            for (int tn = 0; tn < 4; tn++) {
                int idx = pos * 32 + tn * 8 + d0;
#pragma unroll
                for (int j = 0; j < 2; j++) {
                    float cs = g_cos[idx + j], sn = g_sin[idx + j];
                    float t1 = v[tn][j], t2 = v[tn + 4][j];
                    v[tn][j]     = t1 * cs - t2 * sn;
                    v[tn + 4][j] = t2 * cs + t1 * sn;
                }
            }
        }
        if (sec == 0) {
#pragma unroll
            for (int tn = 0; tn < 8; tn++)
                *reinterpret_cast<uint32_t*>(&g_q[obase + tn * 8 + d0]) =
                    packh(v[tn][0] * QSCALE, v[tn][1] * QSCALE);
        } else {
#pragma unroll
            for (int tn = 0; tn < 8; tn++)
                *reinterpret_cast<uint32_t*>(&g_k[obase + tn * 8 + d0]) = packh(v[tn][0], v[tn][1]);
        }
    };

#pragma unroll
    for (int tm = 0; tm < 2; tm++) {
        const int mA = row0 + warp_m * 32 + tm * 16 + (lane >> 2);
        float vA[8][2], vB[8][2];
#pragma unroll
        for (int tn = 0; tn < 8; tn++) {
            vA[tn][0] = acc[tm][tn][0] + bs[tn][0];
            vA[tn][1] = acc[tm][tn][1] + bs[tn][1];
            vB[tn][0] = acc[tm][tn][2] + bs[tn][0];
            vB[tn][1] = acc[tm][tn][3] + bs[tn][1];
        }
        process_row(vA, mA);
        process_row(vB, mA + 8);
    }
}

// ---------------------------------------------------------------------------
// Generic single-pass fp16 GEMM (proj): out = A.B^T + bias
// ---------------------------------------------------------------------------
__global__ __launch_bounds__(256, 2) void gemm_mma(
    const __half* __restrict__ Ah, const __half* __restrict__ Bh,
    const float* __restrict__ bias, float* __restrict__ out, int ostride)
{
    extern __shared__ char sm[];
    const uint32_t sbase = smem_u32(sm);
    const int tid = threadIdx.x;
    const int lane = tid & 31;
    const int wid = tid >> 5;
    const int warp_m = wid >> 1;
    const int warp_n = wid & 1;
    const int row0 = blockIdx.y * 128;
    const int col0 = blockIdx.x * 128;

    float acc[2][8][4];
#pragma unroll
    for (int a = 0; a < 2; a++)
#pragma unroll
        for (int b = 0; b < 8; b++)
#pragma unroll
            for (int c = 0; c < 4; c++) acc[a][b][c] = 0.0f;

    const __half* srcs[2] = { Ah + (size_t)row0 * 1024, Bh + (size_t)col0 * 1024 };

    auto load_stage = [&](int c, int buf) {
#pragma unroll
        for (int i = 0; i < 4; i++) {
            int lin = tid + i * 256;
            int mat = lin >> 9;
            int rem = lin & 511;
            int row = rem >> 2;
            int ch = rem & 3;
            const __half* s = srcs[mat] + (size_t)row * 1024 + c * 32 + ch * 8;
            uint32_t d = sbase + buf * STAGE_B + mat * 10240 + (uint32_t)(row * 40 + ch * 8) * 2;
            asm volatile("cp.async.cg.shared.global [%0], [%1], 16;" :: "r"(d), "l"(s));
        }
        asm volatile("cp.async.commit_group;");
    };

    load_stage(0, 0);
    load_stage(1, 1);
    for (int c = 0; c < 32; c++) {
        const int buf = c % 3;
        if (c + 2 < 32) { load_stage(c + 2, (c + 2) % 3); asm volatile("cp.async.wait_group 2;"); }
        else if (c + 1 < 32) { asm volatile("cp.async.wait_group 1;"); }
        else { asm volatile("cp.async.wait_group 0;"); }
        __syncthreads();
        const uint32_t base = sbase + buf * STAGE_B;
#pragma unroll
        for (int kk = 0; kk < 2; kk++) {
            uint32_t ah[2][4], bh[4][4];
            int arow = warp_m * 32 + (lane & 15);
            int acol = kk * 16 + (lane >> 4) * 8;
            uint32_t aoff = (uint32_t)(arow * 40 + acol) * 2;
            ldsm4(ah[0], base + aoff);
            ldsm4(ah[1], base + aoff + 1280);
            int g = lane >> 3, l7 = lane & 7;
#pragma unroll
            for (int p = 0; p < 4; p++) {
                int brow = warp_n * 64 + (p * 2 + (g >> 1)) * 8 + l7;
                int bcol = kk * 16 + (g & 1) * 8;
                ldsm4(bh[p], base + 10240 + (uint32_t)(brow * 40 + bcol) * 2);
            }
#pragma unroll
            for (int tm = 0; tm < 2; tm++)
#pragma unroll
                for (int tn = 0; tn < 8; tn++)
                    mma16816(acc[tm][tn], ah[tm],
                             bh[tn >> 1][(tn & 1) * 2], bh[tn >> 1][(tn & 1) * 2 + 1]);
        }
        __syncthreads();
    }

#pragma unroll
    for (int tm = 0; tm < 2; tm++) {
        int mb = row0 + warp_m * 32 + tm * 16 + (lane >> 2);
#pragma unroll
        for (int tn = 0; tn < 8; tn++) {
            int col = col0 + warp_n * 64 + tn * 8 + (lane & 3) * 2;
            float b0 = __ldg(&bias[col]), b1 = __ldg(&bias[col + 1]);
            *reinterpret_cast<float2*>(&out[(size_t)mb * ostride + col]) =
                make_float2(acc[tm][tn][0] + b0, acc[tm][tn][1] + b1);
            *reinterpret_cast<float2*>(&out[(size_t)(mb + 8) * ostride + col]) =
                make_float2(acc[tm][tn][2] + b0, acc[tm][tn][3] + b1);
        }
    }
}

// ---------------------------------------------------------------------------
// Flash attention: 256 q/CTA, warp = 32 rows; 128-key KV tiles processed as
// two 64-key sub-tiles (half the barriers); alpha-skip fast path;
// kc-interleaved exp2/rowsum/PV. 1 CTA/SM.
// ---------------------------------------------------------------------------
#define RS   144
#define KVB  36864                // per buffer: K 128x144 + V 128x144
#define OVV  18432                // V offset within buffer
#define ATTN_SMEM (2 * KVB)       // 73728

__global__ __launch_bounds__(256, 1) void attn_mma()
{
    extern __shared__ char sm[];
    const uint32_t sbase = smem_u32(sm);
    const int tid = threadIdx.x;
    const int lane = tid & 31;
    const int wid = tid >> 5;
    const int q0 = blockIdx.x * 256;
    const int h = blockIdx.y;
    const int b = blockIdx.z;
    const size_t hb = ((size_t)(b * 16 + h)) * 2048 * 64;

    const __half* q_g = g_q + hb + (size_t)q0 * 64;
    const __half* k_g = g_k + hb;
    const __half* v_g = g_v + hb;

    // ---- stage Q (256 rows) through buffer region, hoist ----
    {
#pragma unroll
        for (int i = 0; i < 8; i++) {
            int lin = tid + i * 256;          // 0..2047 (256 rows x 8 chunks)
            int row = lin >> 3;
            int ch = lin & 7;
            const __half* s = q_g + (size_t)row * 64 + ch * 8;
            uint32_t d = sbase + (uint32_t)(row * RS + ch * 16);
            asm volatile("cp.async.cg.shared.global [%0], [%1], 16;" :: "r"(d), "l"(s));
        }
        asm volatile("cp.async.commit_group;");
        asm volatile("cp.async.wait_group 0;");
        __syncthreads();
    }

    uint32_t aq[2][4][4];
    {
        const int acolb = (lane >> 4) * 16;
#pragma unroll
        for (int blk = 0; blk < 2; blk++) {
            const int arow = wid * 32 + blk * 16 + (lane & 15);
#pragma unroll
            for (int kc = 0; kc < 4; kc++)
                ldsm4(aq[blk][kc], sbase + (uint32_t)(arow * RS + kc * 32 + acolb));
        }
    }
    __syncthreads();   // all warps hoisted before KV overwrites Q

    // loads a 128-key tile (K 128 rows + V 128 rows)
    auto load_kv = [&](int t, int buf) {
        const uint32_t dbase = sbase + buf * KVB;
#pragma unroll
        for (int i = 0; i < 8; i++) {
            int lin = tid + i * 256;          // 0..2047
            int mat = lin >> 10;              // 0=K, 1=V
            int rem = lin & 1023;
            int row = rem >> 3;
            int ch = rem & 7;
            const __half* s = (mat ? v_g : k_g) + (size_t)t * 128 * 64 + (size_t)row * 64 + ch * 8;
            uint32_t d = dbase + mat * OVV + (uint32_t)(row * RS + ch * 16);
            asm volatile("cp.async.cg.shared.global [%0], [%1], 16;" :: "r"(d), "l"(s));
        }
        asm volatile("cp.async.commit_group;");
    };

    load_kv(0, 0);
    load_kv(1, 1);
    asm volatile("cp.async.wait_group 1;");
    __syncthreads();

    float mrow[2][2], lrow[2][2];
    float o[2][8][4];
#pragma unroll
    for (int blk = 0; blk < 2; blk++) {
        mrow[blk][0] = -1e30f; mrow[blk][1] = -1e30f;
        lrow[blk][0] = 0.0f;   lrow[blk][1] = 0.0f;
#pragma unroll
        for (int nd = 0; nd < 8; nd++)
#pragma unroll
            for (int j = 0; j < 4; j++) o[blk][nd][j] = 0.0f;
    }

    const int g = lane >> 3, l7 = lane & 7;

    for (int t = 0; t < 16; t++) {
        const uint32_t kbuf = sbase + (t & 1) * KVB;

#pragma unroll
        for (int sub = 0; sub < 2; sub++) {
            const uint32_t koff = kbuf + (uint32_t)(sub * 64 * RS);
            const uint32_t voff = kbuf + OVV + (uint32_t)(sub * 64 * RS);

            // ---- S = Q K^T ----
            float c[2][8][4];
#pragma unroll
            for (int blk = 0; blk < 2; blk++)
#pragma unroll
                for (int tn = 0; tn < 8; tn++)
#pragma unroll
                    for (int j = 0; j < 4; j++) c[blk][tn][j] = 0.0f;

#pragma unroll
            for (int kc = 0; kc < 4; kc++) {
                uint32_t bh[4][4];
#pragma unroll
                for (int p = 0; p < 4; p++) {
                    int brow = (p * 2 + (g >> 1)) * 8 + l7;
                    int bcolb = kc * 32 + (g & 1) * 16;
                    ldsm4(bh[p], koff + (uint32_t)(brow * RS + bcolb));
                }
#pragma unroll
                for (int blk = 0; blk < 2; blk++)
#pragma unroll
                    for (int tn = 0; tn < 8; tn++)
                        mma16816(c[blk][tn], aq[blk][kc],
                                 bh[tn >> 1][(tn & 1) * 2], bh[tn >> 1][(tn & 1) * 2 + 1]);
            }

            // ---- online softmax: max + alpha (with skip fast path) ----
            float al[2][2];
            float mn[2][2];
#pragma unroll
            for (int blk = 0; blk < 2; blk++) {
                float mx0 = -1e30f, mx1 = -1e30f;
#pragma unroll
                for (int tn = 0; tn < 8; tn++) {
                    mx0 = fmaxf(mx0, fmaxf(c[blk][tn][0], c[blk][tn][1]));
                    mx1 = fmaxf(mx1, fmaxf(c[blk][tn][2], c[blk][tn][3]));
                }
                mx0 = fmaxf(mx0, __shfl_xor_sync(0xffffffffu, mx0, 1));
                mx0 = fmaxf(mx0, __shfl_xor_sync(0xffffffffu, mx0, 2));
                mx1 = fmaxf(mx1, __shfl_xor_sync(0xffffffffu, mx1, 1));
                mx1 = fmaxf(mx1, __shfl_xor_sync(0xffffffffu, mx1, 2));
                mn[blk][0] = fmaxf(mrow[blk][0], mx0);
                mn[blk][1] = fmaxf(mrow[blk][1], mx1);
                al[blk][0] = fexp2(mrow[blk][0] - mn[blk][0]);
                al[blk][1] = fexp2(mrow[blk][1] - mn[blk][1]);
                mrow[blk][0] = mn[blk][0];
                mrow[blk][1] = mn[blk][1];
            }
            bool noup = (al[0][0] == 1.0f) & (al[0][1] == 1.0f) &
                        (al[1][0] == 1.0f) & (al[1][1] == 1.0f);
            if (!__all_sync(0xffffffffu, noup)) {
#pragma unroll
                for (int blk = 0; blk < 2; blk++)
#pragma unroll
                    for (int nd = 0; nd < 8; nd++) {
                        o[blk][nd][0] *= al[blk][0]; o[blk][nd][1] *= al[blk][0];
                        o[blk][nd][2] *= al[blk][1]; o[blk][nd][3] *= al[blk][1];
                    }
            }

            // ---- per-kc: exp2/pack P, rowsum MMA, PV MMA ----
            float sac[2][4] = {{0.0f, 0.0f, 0.0f, 0.0f}, {0.0f, 0.0f, 0.0f, 0.0f}};
#pragma unroll
            for (int kc = 0; kc < 4; kc++) {
                uint32_t p[2][4];
#pragma unroll
                for (int blk = 0; blk < 2; blk++) {
                    p[blk][0] = h2exp2(packh(c[blk][2 * kc][0] - mn[blk][0],     c[blk][2 * kc][1] - mn[blk][0]));
                    p[blk][1] = h2exp2(packh(c[blk][2 * kc][2] - mn[blk][1],     c[blk][2 * kc][3] - mn[blk][1]));
                    p[blk][2] = h2exp2(packh(c[blk][2 * kc + 1][0] - mn[blk][0], c[blk][2 * kc + 1][1] - mn[blk][0]));
                    p[blk][3] = h2exp2(packh(c[blk][2 * kc + 1][2] - mn[blk][1], c[blk][2 * kc + 1][3] - mn[blk][1]));
                    mma16816(sac[blk], p[blk], ONES_H2, ONES_H2);
                }
#pragma unroll
                for (int dp = 0; dp < 4; dp++) {
                    int vrow = kc * 16 + (g & 1) * 8 + l7;
                    int vcolb = dp * 32 + (g >> 1) * 16;
                    uint32_t vh[4];
                    ldsm4t(vh, voff + (uint32_t)(vrow * RS + vcolb));
#pragma unroll
                    for (int blk = 0; blk < 2; blk++) {
                        mma16816(o[blk][dp * 2],     p[blk], vh[0], vh[1]);
                        mma16816(o[blk][dp * 2 + 1], p[blk], vh[2], vh[3]);
                    }
                }
            }
#pragma unroll
            for (int blk = 0; blk < 2; blk++) {
                lrow[blk][0] = lrow[blk][0] * al[blk][0] + sac[blk][0];
                lrow[blk][1] = lrow[blk][1] * al[blk][1] + sac[blk][2];
            }
        }

        __syncthreads();
        if (t + 2 < 16) load_kv(t + 2, t & 1);
        if (t + 1 < 16) {
            if (t + 2 < 16) { asm volatile("cp.async.wait_group 1;"); }
            else            { asm volatile("cp.async.wait_group 0;"); }
            __syncthreads();
        }
    }

    // ---- epilogue: normalize + single fp16 into [M,1024] ----
    const int colb = h * 64 + (lane & 3) * 2;
#pragma unroll
    for (int blk = 0; blk < 2; blk++) {
        const float inv0 = 1.0f / lrow[blk][0], inv1 = 1.0f / lrow[blk][1];
        const int r0 = q0 + wid * 32 + blk * 16 + (lane >> 2);
        const size_t m0i = (size_t)(b * 2048) + r0;
#pragma unroll
        for (int nd = 0; nd < 8; nd++) {
            *reinterpret_cast<uint32_t*>(&g_a[m0i * 1024 + colb + nd * 8]) =
                packh(o[blk][nd][0] * inv0, o[blk][nd][1] * inv0);
            *reinterpret_cast<uint32_t*>(&g_a[(m0i + 8) * 1024 + colb + nd * 8]) =
                packh(o[blk][nd][2] * inv1, o[blk][nd][3] * inv1);
        }
    }
}

// ---------------------------------------------------------------------------
// Launch
// ---------------------------------------------------------------------------
extern "C" void kernel_launch(void* const* d_in, const int* in_sizes, int n_in,
                              void* d_out, int out_size)
{
    const float* x      = (const float*)d_in[0];
    const float* qkv_w  = (const float*)d_in[1];
    const float* qkv_b  = (const float*)d_in[2];
    const float* qn_w   = (const float*)d_in[3];
    const float* kn_w   = (const float*)d_in[4];
    const float* proj_w = (const float*)d_in[5];
    const float* proj_b = (const float*)d_in[6];
    float* out = (float*)d_out;

    cudaFuncSetAttribute(gemm_qkv_fused, cudaFuncAttributeMaxDynamicSharedMemorySize, GEMM_SMEM);
    cudaFuncSetAttribute(gemm_mma, cudaFuncAttributeMaxDynamicSharedMemorySize, GEMM_SMEM);
    cudaFuncSetAttribute(attn_mma, cudaFuncAttributeMaxDynamicSharedMemorySize, ATTN_SMEM);

    void *p_xh, *p_w1h, *p_w2h, *p_a;
    cudaGetSymbolAddress(&p_xh, g_xh);
    cudaGetSymbolAddress(&p_w1h, g_w1h);
    cudaGetSymbolAddress(&p_w2h, g_w2h);
    cudaGetSymbolAddress(&p_a, g_a);

    rope_table<<<128, 256>>>();

    cvt_all<<<(NX4 + NW14 + NW24 + 255) / 256, 256>>>(
        (const float4*)x, (const float4*)qkv_w, (const float4*)proj_w,
        (uint2*)p_xh, (uint2*)p_w1h, (uint2*)p_w2h);

    // 1. QKV projection + fused RMSNorm/RoPE/fp16 emit (head-major q/k/v)
    gemm_qkv_fused<<<dim3(K3_ / 128, M_ / 128), 256, GEMM_SMEM>>>(
        (const __half*)p_xh, (const __half*)p_w1h, qkv_b, qn_w, kn_w);

    // 2. Tensor-core flash attention (256 q/CTA, 128-key tiles) -> g_a
    attn_mma<<<dim3(N_ / 256, H_, B_), 256, ATTN_SMEM>>>();

    // 3. Output projection -> d_out
    gemm_mma<<<dim3(C_ / 128, M_ / 128), 256, GEMM_SMEM>>>(
        (const __half*)p_a, (const __half*)p_w2h, proj_b, out, C_);
}

// round 14
// speedup vs baseline: 7.1306x; 1.0001x over previous
#include <cuda_runtime.h>
#include <cuda_bf16.h>
#include <cuda_fp16.h>
#include <cstdint>
#include <math.h>

// Problem constants
#define B_  2
#define N_  2048
#define C_  1024
#define H_  16
#define D_  64
#define M_  (B_ * N_)        // 4096
#define K3_ (3 * C_)         // 3072

// ---------------------------------------------------------------------------
// Scratch (device globals)
// ---------------------------------------------------------------------------
__device__ __half g_xh[M_ * C_];                       // x single fp16
__device__ __half g_w1h[K3_ * C_];                     // qkv_w single fp16
__device__ __half g_w2h[C_ * C_];                      // proj_w single fp16
__device__ __half g_a[M_ * C_];                        // attention out single fp16
// head-major [b*16+h][n][64]
__device__ __half g_q[B_*H_*N_*D_];                    // Q single (pre-scaled)
__device__ __half g_k[B_*H_*N_*D_];                    // K single
__device__ __half g_v[B_*H_*N_*D_];                    // V single
__device__ float g_cos[1024 * 32], g_sin[1024 * 32];

// ---------------------------------------------------------------------------
// Helpers
// ---------------------------------------------------------------------------
__device__ __forceinline__ uint32_t smem_u32(const void* p) {
    uint32_t a;
    asm("{ .reg .u64 t; cvta.to.shared.u64 t, %1; cvt.u32.u64 %0, t; }" : "=r"(a) : "l"(p));
    return a;
}
__device__ __forceinline__ void ldsm4(uint32_t* r, uint32_t addr) {
    asm volatile("ldmatrix.sync.aligned.m8n8.x4.shared.b16 {%0,%1,%2,%3}, [%4];"
                 : "=r"(r[0]), "=r"(r[1]), "=r"(r[2]), "=r"(r[3]) : "r"(addr));
}
__device__ __forceinline__ void ldsm4t(uint32_t* r, uint32_t addr) {
    asm volatile("ldmatrix.sync.aligned.m8n8.x4.trans.shared.b16 {%0,%1,%2,%3}, [%4];"
                 : "=r"(r[0]), "=r"(r[1]), "=r"(r[2]), "=r"(r[3]) : "r"(addr));
}
__device__ __forceinline__ void mma16816(float* c, const uint32_t* a, uint32_t b0, uint32_t b1) {
    asm volatile("mma.sync.aligned.m16n8k16.row.col.f32.f16.f16.f32 "
                 "{%0,%1,%2,%3}, {%4,%5,%6,%7}, {%8,%9}, {%0,%1,%2,%3};"
                 : "+f"(c[0]), "+f"(c[1]), "+f"(c[2]), "+f"(c[3])
                 : "r"(a[0]), "r"(a[1]), "r"(a[2]), "r"(a[3]), "r"(b0), "r"(b1));
}
__device__ __forceinline__ uint32_t packh(float a, float b) {
    uint32_t r;
    asm("cvt.rn.f16x2.f32 %0, %1, %2;" : "=r"(r) : "f"(b), "f"(a));
    return r;
}
__device__ __forceinline__ float fexp2(float x) {
    float r;
    asm("ex2.approx.f32 %0, %1;" : "=f"(r) : "f"(x));
    return r;
}
__device__ __forceinline__ uint32_t h2exp2(uint32_t x) {
    uint32_t r;
    asm("ex2.approx.f16x2 %0, %1;" : "=r"(r) : "r"(x));
    return r;
}

#define QSCALE 0.1803368801111137f   // 0.125 * log2(e)
#define ONES_H2 0x3C003C00u          // fp16x2 {1.0, 1.0}

// ---------------------------------------------------------------------------
// Merged fp32 -> fp16 convert for x, qkv_w, proj_w
// ---------------------------------------------------------------------------
#define NX4  (M_ * C_ / 4)
#define NW14 (K3_ * C_ / 4)
#define NW24 (C_ * C_ / 4)

__global__ __launch_bounds__(256) void cvt_all(const float4* __restrict__ x,
                                               const float4* __restrict__ w1,
                                               const float4* __restrict__ w2,
                                               uint2* __restrict__ xh,
                                               uint2* __restrict__ w1h,
                                               uint2* __restrict__ w2h)
{
    int i = blockIdx.x * 256 + threadIdx.x;
    const float4* s;
    uint2* d;
    if (i < NX4)              { s = x + i;                 d = xh + i; }
    else if (i < NX4 + NW14)  { s = w1 + (i - NX4);        d = w1h + (i - NX4); }
    else                      { s = w2 + (i - NX4 - NW14); d = w2h + (i - NX4 - NW14); }
    float4 v = *s;
    *d = make_uint2(packh(v.x, v.y), packh(v.z, v.w));
}

// ---------------------------------------------------------------------------
// RoPE tables
// ---------------------------------------------------------------------------
__global__ __launch_bounds__(256) void rope_table()
{
    int idx = blockIdx.x * 256 + threadIdx.x;          // 32768
    int pos = idx >> 5, lane = idx & 31;
    float e = (float)(2 * lane) * (1.0f / 64.0f);
    float inv = expf(-9.210340371976184f * e);
    float ang = (float)pos * inv;
    g_cos[idx] = cosf(ang);
    g_sin[idx] = sinf(ang);
}

// ---------------------------------------------------------------------------
// Shared GEMM config (block 128x128, K=1024, chunk 32, 8 warps 4x2)
// ---------------------------------------------------------------------------
#define STAGE_B 20480
#define GEMM_SMEM (3 * STAGE_B)   // 61440

// ---------------------------------------------------------------------------
// QKV GEMM (single-pass fp16) with FUSED RMSNorm + RoPE + fp16 emit.
// ---------------------------------------------------------------------------
__global__ __launch_bounds__(256, 2) void gemm_qkv_fused(
    const __half* __restrict__ Ah, const __half* __restrict__ Bh,
    const float* __restrict__ bias,
    const float* __restrict__ qn_w, const float* __restrict__ kn_w)
{
    extern __shared__ char sm[];
    const uint32_t sbase = smem_u32(sm);
    const int tid = threadIdx.x;
    const int lane = tid & 31;
    const int wid = tid >> 5;
    const int warp_m = wid >> 1;
    const int warp_n = wid & 1;
    const int row0 = blockIdx.y * 128;
    const int col0 = blockIdx.x * 128;

    float acc[2][8][4];
#pragma unroll
    for (int a = 0; a < 2; a++)
#pragma unroll
        for (int b = 0; b < 8; b++)
#pragma unroll
            for (int c = 0; c < 4; c++) acc[a][b][c] = 0.0f;

    const __half* srcs[2] = { Ah + (size_t)row0 * 1024, Bh + (size_t)col0 * 1024 };

    auto load_stage = [&](int c, int buf) {
#pragma unroll
        for (int i = 0; i < 4; i++) {
            int lin = tid + i * 256;
            int mat = lin >> 9;
            int rem = lin & 511;
            int row = rem >> 2;
            int ch = rem & 3;
            const __half* s = srcs[mat] + (size_t)row * 1024 + c * 32 + ch * 8;
            uint32_t d = sbase + buf * STAGE_B + mat * 10240 + (uint32_t)(row * 40 + ch * 8) * 2;
            asm volatile("cp.async.cg.shared.global [%0], [%1], 16;" :: "r"(d), "l"(s));
        }
        asm volatile("cp.async.commit_group;");
    };

    load_stage(0, 0);
    load_stage(1, 1);
    for (int c = 0; c < 32; c++) {
        const int buf = c % 3;
        if (c + 2 < 32) { load_stage(c + 2, (c + 2) % 3); asm volatile("cp.async.wait_group 2;"); }
        else if (c + 1 < 32) { asm volatile("cp.async.wait_group 1;"); }
        else { asm volatile("cp.async.wait_group 0;"); }
        __syncthreads();
        const uint32_t base = sbase + buf * STAGE_B;
#pragma unroll
        for (int kk = 0; kk < 2; kk++) {
            uint32_t ah[2][4], bh[4][4];
            int arow = warp_m * 32 + (lane & 15);
            int acol = kk * 16 + (lane >> 4) * 8;
            uint32_t aoff = (uint32_t)(arow * 40 + acol) * 2;
            ldsm4(ah[0], base + aoff);
            ldsm4(ah[1], base + aoff + 1280);
            int g = lane >> 3, l7 = lane & 7;
#pragma unroll
            for (int p = 0; p < 4; p++) {
                int brow = warp_n * 64 + (p * 2 + (g >> 1)) * 8 + l7;
                int bcol = kk * 16 + (g & 1) * 8;
                ldsm4(bh[p], base + 10240 + (uint32_t)(brow * 40 + bcol) * 2);
            }
#pragma unroll
            for (int tm = 0; tm < 2; tm++)
#pragma unroll
                for (int tn = 0; tn < 8; tn++)
                    mma16816(acc[tm][tn], ah[tm],
                             bh[tn >> 1][(tn & 1) * 2], bh[tn >> 1][(tn & 1) * 2 + 1]);
        }
        __syncthreads();
    }

    // ---- fused epilogue ----
    const int sec = col0 >> 10;                         // 0=q, 1=k, 2=v
    const int head = ((col0 & 1023) >> 6) + warp_n;
    const int d0 = (lane & 3) * 2;

    float bs[8][2], wv[8][2];
    const float* w = (sec == 1) ? kn_w : qn_w;
#pragma unroll
    for (int tn = 0; tn < 8; tn++) {
        int d = tn * 8 + d0;
        int col = col0 + warp_n * 64 + d;
        bs[tn][0] = __ldg(&bias[col]);
        bs[tn][1] = __ldg(&bias[col + 1]);
        if (sec < 2) { wv[tn][0] = __ldg(&w[d]); wv[tn][1] = __ldg(&w[d + 1]); }
    }

    auto process_row = [&](float v[8][2], int m) {
        const int n = m & 2047;
        const int bb = m >> 11;
        const size_t obase = (((size_t)(bb * 16 + head)) * 2048 + n) * 64;
        if (sec == 2) {
#pragma unroll
            for (int tn = 0; tn < 8; tn++)
                *reinterpret_cast<uint32_t*>(&g_v[obase + tn * 8 + d0]) = packh(v[tn][0], v[tn][1]);
            return;
        }
        float ss = 0.0f;
#pragma unroll
        for (int tn = 0; tn < 8; tn++) ss += v[tn][0] * v[tn][0] + v[tn][1] * v[tn][1];
        ss += __shfl_xor_sync(0xffffffffu, ss, 1);
        ss += __shfl_xor_sync(0xffffffffu, ss, 2);
        float rs = rsqrtf(ss * (1.0f / 64.0f) + 1e-6f);
#pragma unroll
        for (int tn = 0; tn < 8; tn++) {
            v[tn][0] *= rs * wv[tn][0];
            v[tn][1] *= rs * wv[tn][1];
        }
        int pos = (n < 1024) ? n : ((n < 1536) ? (n - 1024) : -1);
        if (pos >= 0) {
#pragma unroll
            for (int tn = 0; tn < 4; tn++) {
                int idx = pos * 32 + tn * 8 + d0;
#pragma unroll
                for (int j = 0; j < 2; j++) {
                    float cs = g_cos[idx + j], sn = g_sin[idx + j];
                    float t1 = v[tn][j], t2 = v[tn + 4][j];
                    v[tn][j]     = t1 * cs - t2 * sn;
                    v[tn + 4][j] = t2 * cs + t1 * sn;
                }
            }
        }
        if (sec == 0) {
#pragma unroll
            for (int tn = 0; tn < 8; tn++)
                *reinterpret_cast<uint32_t*>(&g_q[obase + tn * 8 + d0]) =
                    packh(v[tn][0] * QSCALE, v[tn][1] * QSCALE);
        } else {
#pragma unroll
            for (int tn = 0; tn < 8; tn++)
                *reinterpret_cast<uint32_t*>(&g_k[obase + tn * 8 + d0]) = packh(v[tn][0], v[tn][1]);
        }
    };

#pragma unroll
    for (int tm = 0; tm < 2; tm++) {
        const int mA = row0 + warp_m * 32 + tm * 16 + (lane >> 2);
        float vA[8][2], vB[8][2];
#pragma unroll
        for (int tn = 0; tn < 8; tn++) {
            vA[tn][0] = acc[tm][tn][0] + bs[tn][0];
            vA[tn][1] = acc[tm][tn][1] + bs[tn][1];
            vB[tn][0] = acc[tm][tn][2] + bs[tn][0];
            vB[tn][1] = acc[tm][tn][3] + bs[tn][1];
        }
        process_row(vA, mA);
        process_row(vB, mA + 8);
    }
}

// ---------------------------------------------------------------------------
// Generic single-pass fp16 GEMM (proj): out = A.B^T + bias
// ---------------------------------------------------------------------------
__global__ __launch_bounds__(256, 2) void gemm_mma(
    const __half* __restrict__ Ah, const __half* __restrict__ Bh,
    const float* __restrict__ bias, float* __restrict__ out, int ostride)
{
    extern __shared__ char sm[];
    const uint32_t sbase = smem_u32(sm);
    const int tid = threadIdx.x;
    const int lane = tid & 31;
    const int wid = tid >> 5;
    const int warp_m = wid >> 1;
    const int warp_n = wid & 1;
    const int row0 = blockIdx.y * 128;
    const int col0 = blockIdx.x * 128;

    float acc[2][8][4];
#pragma unroll
    for (int a = 0; a < 2; a++)
#pragma unroll
        for (int b = 0; b < 8; b++)
#pragma unroll
            for (int c = 0; c < 4; c++) acc[a][b][c] = 0.0f;

    const __half* srcs[2] = { Ah + (size_t)row0 * 1024, Bh + (size_t)col0 * 1024 };

    auto load_stage = [&](int c, int buf) {
#pragma unroll
        for (int i = 0; i < 4; i++) {
            int lin = tid + i * 256;
            int mat = lin >> 9;
            int rem = lin & 511;
            int row = rem >> 2;
            int ch = rem & 3;
            const __half* s = srcs[mat] + (size_t)row * 1024 + c * 32 + ch * 8;
            uint32_t d = sbase + buf * STAGE_B + mat * 10240 + (uint32_t)(row * 40 + ch * 8) * 2;
            asm volatile("cp.async.cg.shared.global [%0], [%1], 16;" :: "r"(d), "l"(s));
        }
        asm volatile("cp.async.commit_group;");
    };

    load_stage(0, 0);
    load_stage(1, 1);
    for (int c = 0; c < 32; c++) {
        const int buf = c % 3;
        if (c + 2 < 32) { load_stage(c + 2, (c + 2) % 3); asm volatile("cp.async.wait_group 2;"); }
        else if (c + 1 < 32) { asm volatile("cp.async.wait_group 1;"); }
        else { asm volatile("cp.async.wait_group 0;"); }
        __syncthreads();
        const uint32_t base = sbase + buf * STAGE_B;
#pragma unroll
        for (int kk = 0; kk < 2; kk++) {
            uint32_t ah[2][4], bh[4][4];
            int arow = warp_m * 32 + (lane & 15);
            int acol = kk * 16 + (lane >> 4) * 8;
            uint32_t aoff = (uint32_t)(arow * 40 + acol) * 2;
            ldsm4(ah[0], base + aoff);
            ldsm4(ah[1], base + aoff + 1280);
            int g = lane >> 3, l7 = lane & 7;
#pragma unroll
            for (int p = 0; p < 4; p++) {
                int brow = warp_n * 64 + (p * 2 + (g >> 1)) * 8 + l7;
                int bcol = kk * 16 + (g & 1) * 8;
                ldsm4(bh[p], base + 10240 + (uint32_t)(brow * 40 + bcol) * 2);
            }
#pragma unroll
            for (int tm = 0; tm < 2; tm++)
#pragma unroll
                for (int tn = 0; tn < 8; tn++)
                    mma16816(acc[tm][tn], ah[tm],
                             bh[tn >> 1][(tn & 1) * 2], bh[tn >> 1][(tn & 1) * 2 + 1]);
        }
        __syncthreads();
    }

#pragma unroll
    for (int tm = 0; tm < 2; tm++) {
        int mb = row0 + warp_m * 32 + tm * 16 + (lane >> 2);
#pragma unroll
        for (int tn = 0; tn < 8; tn++) {
            int col = col0 + warp_n * 64 + tn * 8 + (lane & 3) * 2;
            float b0 = __ldg(&bias[col]), b1 = __ldg(&bias[col + 1]);
            *reinterpret_cast<float2*>(&out[(size_t)mb * ostride + col]) =
                make_float2(acc[tm][tn][0] + b0, acc[tm][tn][1] + b1);
            *reinterpret_cast<float2*>(&out[(size_t)(mb + 8) * ostride + col]) =
                make_float2(acc[tm][tn][2] + b0, acc[tm][tn][3] + b1);
        }
    }
}

// ---------------------------------------------------------------------------
// Flash attention: 256 q/CTA, warp = 32 rows; 128-key KV tiles as two 64-key
// sub-tiles. PHASE STAGGER: warps 0-3 process sub-tiles (0,1), warps 4-7
// process (1,0) so each SMSP overlaps one warp's softmax with the other's MMA.
// ---------------------------------------------------------------------------
#define RS   144
#define KVB  36864                // per buffer: K 128x144 + V 128x144
#define OVV  18432                // V offset within buffer
#define ATTN_SMEM (2 * KVB)       // 73728

__global__ __launch_bounds__(256, 1) void attn_mma()
{
    extern __shared__ char sm[];
    const uint32_t sbase = smem_u32(sm);
    const int tid = threadIdx.x;
    const int lane = tid & 31;
    const int wid = tid >> 5;
    const int q0 = blockIdx.x * 256;
    const int h = blockIdx.y;
    const int b = blockIdx.z;
    const size_t hb = ((size_t)(b * 16 + h)) * 2048 * 64;

    const __half* q_g = g_q + hb + (size_t)q0 * 64;
    const __half* k_g = g_k + hb;
    const __half* v_g = g_v + hb;

    // ---- stage Q (256 rows) through buffer region, hoist ----
    {
#pragma unroll
        for (int i = 0; i < 8; i++) {
            int lin = tid + i * 256;          // 0..2047 (256 rows x 8 chunks)
            int row = lin >> 3;
            int ch = lin & 7;
            const __half* s = q_g + (size_t)row * 64 + ch * 8;
            uint32_t d = sbase + (uint32_t)(row * RS + ch * 16);
            asm volatile("cp.async.cg.shared.global [%0], [%1], 16;" :: "r"(d), "l"(s));
        }
        asm volatile("cp.async.commit_group;");
        asm volatile("cp.async.wait_group 0;");
        __syncthreads();
    }

    uint32_t aq[2][4][4];
    {
        const int acolb = (lane >> 4) * 16;
#pragma unroll
        for (int blk = 0; blk < 2; blk++) {
            const int arow = wid * 32 + blk * 16 + (lane & 15);
#pragma unroll
            for (int kc = 0; kc < 4; kc++)
                ldsm4(aq[blk][kc], sbase + (uint32_t)(arow * RS + kc * 32 + acolb));
        }
    }
    __syncthreads();   // all warps hoisted before KV overwrites Q

    // loads a 128-key tile (K 128 rows + V 128 rows)
    auto load_kv = [&](int t, int buf) {
        const uint32_t dbase = sbase + buf * KVB;
#pragma unroll
        for (int i = 0; i < 8; i++) {
            int lin = tid + i * 256;          // 0..2047
            int mat = lin >> 10;              // 0=K, 1=V
            int rem = lin & 1023;
            int row = rem >> 3;
            int ch = rem & 7;
            const __half* s = (mat ? v_g : k_g) + (size_t)t * 128 * 64 + (size_t)row * 64 + ch * 8;
            uint32_t d = dbase + mat * OVV + (uint32_t)(row * RS + ch * 16);
            asm volatile("cp.async.cg.shared.global [%0], [%1], 16;" :: "r"(d), "l"(s));
        }
        asm volatile("cp.async.commit_group;");
    };

    load_kv(0, 0);
    load_kv(1, 1);
    asm volatile("cp.async.wait_group 1;");
    __syncthreads();

    float mrow[2][2], lrow[2][2];
    float o[2][8][4];
#pragma unroll
    for (int blk = 0; blk < 2; blk++) {
        mrow[blk][0] = -1e30f; mrow[blk][1] = -1e30f;
        lrow[blk][0] = 0.0f;   lrow[blk][1] = 0.0f;
#pragma unroll
        for (int nd = 0; nd < 8; nd++)
#pragma unroll
            for (int j = 0; j < 4; j++) o[blk][nd][j] = 0.0f;
    }

    const int g = lane >> 3, l7 = lane & 7;
    const int sflip = (wid >> 2) & 1;     // warps 4-7 process sub-tiles reversed

    for (int t = 0; t < 16; t++) {
        const uint32_t kbuf = sbase + (t & 1) * KVB;

#pragma unroll
        for (int s = 0; s < 2; s++) {
            const int sub = s ^ sflip;
            const uint32_t koff = kbuf + (uint32_t)(sub * 64 * RS);
            const uint32_t voff = kbuf + OVV + (uint32_t)(sub * 64 * RS);

            // ---- S = Q K^T ----
            float c[2][8][4];
#pragma unroll
            for (int blk = 0; blk < 2; blk++)
#pragma unroll
                for (int tn = 0; tn < 8; tn++)
#pragma unroll
                    for (int j = 0; j < 4; j++) c[blk][tn][j] = 0.0f;

#pragma unroll
            for (int kc = 0; kc < 4; kc++) {
                uint32_t bh[4][4];
#pragma unroll
                for (int p = 0; p < 4; p++) {
                    int brow = (p * 2 + (g >> 1)) * 8 + l7;
                    int bcolb = kc * 32 + (g & 1) * 16;
                    ldsm4(bh[p], koff + (uint32_t)(brow * RS + bcolb));
                }
#pragma unroll
                for (int blk = 0; blk < 2; blk++)
#pragma unroll
                    for (int tn = 0; tn < 8; tn++)
                        mma16816(c[blk][tn], aq[blk][kc],
                                 bh[tn >> 1][(tn & 1) * 2], bh[tn >> 1][(tn & 1) * 2 + 1]);
            }

            // ---- online softmax: max + alpha (with skip fast path) ----
            float al[2][2];
            float mn[2][2];
#pragma unroll
            for (int blk = 0; blk < 2; blk++) {
                float mx0 = -1e30f, mx1 = -1e30f;
#pragma unroll
                for (int tn = 0; tn < 8; tn++) {
                    mx0 = fmaxf(mx0, fmaxf(c[blk][tn][0], c[blk][tn][1]));
                    mx1 = fmaxf(mx1, fmaxf(c[blk][tn][2], c[blk][tn][3]));
                }
                mx0 = fmaxf(mx0, __shfl_xor_sync(0xffffffffu, mx0, 1));
                mx0 = fmaxf(mx0, __shfl_xor_sync(0xffffffffu, mx0, 2));
                mx1 = fmaxf(mx1, __shfl_xor_sync(0xffffffffu, mx1, 1));
                mx1 = fmaxf(mx1, __shfl_xor_sync(0xffffffffu, mx1, 2));
                mn[blk][0] = fmaxf(mrow[blk][0], mx0);
                mn[blk][1] = fmaxf(mrow[blk][1], mx1);
                al[blk][0] = fexp2(mrow[blk][0] - mn[blk][0]);
                al[blk][1] = fexp2(mrow[blk][1] - mn[blk][1]);
                mrow[blk][0] = mn[blk][0];
                mrow[blk][1] = mn[blk][1];
            }
            bool noup = (al[0][0] == 1.0f) & (al[0][1] == 1.0f) &
                        (al[1][0] == 1.0f) & (al[1][1] == 1.0f);
            if (!__all_sync(0xffffffffu, noup)) {
#pragma unroll
                for (int blk = 0; blk < 2; blk++)
#pragma unroll
                    for (int nd = 0; nd < 8; nd++) {
                        o[blk][nd][0] *= al[blk][0]; o[blk][nd][1] *= al[blk][0];
                        o[blk][nd][2] *= al[blk][1]; o[blk][nd][3] *= al[blk][1];
                    }
            }

            // ---- per-kc: exp2/pack P, rowsum MMA, PV MMA ----
            float sac[2][4] = {{0.0f, 0.0f, 0.0f, 0.0f}, {0.0f, 0.0f, 0.0f, 0.0f}};
#pragma unroll
            for (int kc = 0; kc < 4; kc++) {
                uint32_t p[2][4];
#pragma unroll
                for (int blk = 0; blk < 2; blk++) {
                    p[blk][0] = h2exp2(packh(c[blk][2 * kc][0] - mn[blk][0],     c[blk][2 * kc][1] - mn[blk][0]));
                    p[blk][1] = h2exp2(packh(c[blk][2 * kc][2] - mn[blk][1],     c[blk][2 * kc][3] - mn[blk][1]));
                    p[blk][2] = h2exp2(packh(c[blk][2 * kc + 1][0] - mn[blk][0], c[blk][2 * kc + 1][1] - mn[blk][0]));
                    p[blk][3] = h2exp2(packh(c[blk][2 * kc + 1][2] - mn[blk][1], c[blk][2 * kc + 1][3] - mn[blk][1]));
                    mma16816(sac[blk], p[blk], ONES_H2, ONES_H2);
                }
#pragma unroll
                for (int dp = 0; dp < 4; dp++) {
                    int vrow = kc * 16 + (g & 1) * 8 + l7;
                    int vcolb = dp * 32 + (g >> 1) * 16;
                    uint32_t vh[4];
                    ldsm4t(vh, voff + (uint32_t)(vrow * RS + vcolb));
#pragma unroll
                    for (int blk = 0; blk < 2; blk++) {
                        mma16816(o[blk][dp * 2],     p[blk], vh[0], vh[1]);
                        mma16816(o[blk][dp * 2 + 1], p[blk], vh[2], vh[3]);
                    }
                }
            }
#pragma unroll
            for (int blk = 0; blk < 2; blk++) {
                lrow[blk][0] = lrow[blk][0] * al[blk][0] + sac[blk][0];
                lrow[blk][1] = lrow[blk][1] * al[blk][1] + sac[blk][2];
            }
        }

        __syncthreads();
        if (t + 2 < 16) load_kv(t + 2, t & 1);
        if (t + 1 < 16) {
            if (t + 2 < 16) { asm volatile("cp.async.wait_group 1;"); }
            else            { asm volatile("cp.async.wait_group 0;"); }
            __syncthreads();
        }
    }

    // ---- epilogue: normalize + single fp16 into [M,1024] ----
    const int colb = h * 64 + (lane & 3) * 2;
#pragma unroll
    for (int blk = 0; blk < 2; blk++) {
        const float inv0 = 1.0f / lrow[blk][0], inv1 = 1.0f / lrow[blk][1];
        const int r0 = q0 + wid * 32 + blk * 16 + (lane >> 2);
        const size_t m0i = (size_t)(b * 2048) + r0;
#pragma unroll
        for (int nd = 0; nd < 8; nd++) {
            *reinterpret_cast<uint32_t*>(&g_a[m0i * 1024 + colb + nd * 8]) =
                packh(o[blk][nd][0] * inv0, o[blk][nd][1] * inv0);
            *reinterpret_cast<uint32_t*>(&g_a[(m0i + 8) * 1024 + colb + nd * 8]) =
                packh(o[blk][nd][2] * inv1, o[blk][nd][3] * inv1);
        }
    }
}

// ---------------------------------------------------------------------------
// Launch
// ---------------------------------------------------------------------------
extern "C" void kernel_launch(void* const* d_in, const int* in_sizes, int n_in,
                              void* d_out, int out_size)
{
    const float* x      = (const float*)d_in[0];
    const float* qkv_w  = (const float*)d_in[1];
    const float* qkv_b  = (const float*)d_in[2];
    const float* qn_w   = (const float*)d_in[3];
    const float* kn_w   = (const float*)d_in[4];
    const float* proj_w = (const float*)d_in[5];
    const float* proj_b = (const float*)d_in[6];
    float* out = (float*)d_out;

    cudaFuncSetAttribute(gemm_qkv_fused, cudaFuncAttributeMaxDynamicSharedMemorySize, GEMM_SMEM);
    cudaFuncSetAttribute(gemm_mma, cudaFuncAttributeMaxDynamicSharedMemorySize, GEMM_SMEM);
    cudaFuncSetAttribute(attn_mma, cudaFuncAttributeMaxDynamicSharedMemorySize, ATTN_SMEM);

    void *p_xh, *p_w1h, *p_w2h, *p_a;
    cudaGetSymbolAddress(&p_xh, g_xh);
    cudaGetSymbolAddress(&p_w1h, g_w1h);
    cudaGetSymbolAddress(&p_w2h, g_w2h);
    cudaGetSymbolAddress(&p_a, g_a);

    rope_table<<<128, 256>>>();

    cvt_all<<<(NX4 + NW14 + NW24 + 255) / 256, 256>>>(
        (const float4*)x, (const float4*)qkv_w, (const float4*)proj_w,
        (uint2*)p_xh, (uint2*)p_w1h, (uint2*)p_w2h);

    // 1. QKV projection + fused RMSNorm/RoPE/fp16 emit (head-major q/k/v)
    gemm_qkv_fused<<<dim3(K3_ / 128, M_ / 128), 256, GEMM_SMEM>>>(
        (const __half*)p_xh, (const __half*)p_w1h, qkv_b, qn_w, kn_w);

    // 2. Tensor-core flash attention (256 q/CTA, phase-staggered) -> g_a
    attn_mma<<<dim3(N_ / 256, H_, B_), 256, ATTN_SMEM>>>();

    // 3. Output projection -> d_out
    gemm_mma<<<dim3(C_ / 128, M_ / 128), 256, GEMM_SMEM>>>(
        (const __half*)p_a, (const __half*)p_w2h, proj_b, out, C_);
}

// round 15
// speedup vs baseline: 7.3078x; 1.0248x over previous
#include <cuda_runtime.h>
#include <cuda_bf16.h>
#include <cuda_fp16.h>
#include <cstdint>
#include <math.h>

// Problem constants
#define B_  2
#define N_  2048
#define C_  1024
#define H_  16
#define D_  64
#define M_  (B_ * N_)        // 4096
#define K3_ (3 * C_)         // 3072

// ---------------------------------------------------------------------------
// Scratch (device globals)
// ---------------------------------------------------------------------------
__device__ __half g_xh[M_ * C_];                       // x single fp16
__device__ __half g_w1h[K3_ * C_];                     // qkv_w single fp16
__device__ __half g_w2h[C_ * C_];                      // proj_w single fp16
__device__ __half g_a[M_ * C_];                        // attention out single fp16
// head-major [b*16+h][n][64]
__device__ __half g_q[B_*H_*N_*D_];                    // Q single (pre-scaled)
__device__ __half g_k[B_*H_*N_*D_];                    // K single
__device__ __half g_v[B_*H_*N_*D_];                    // V single
__device__ float g_cos[1024 * 32], g_sin[1024 * 32];

// ---------------------------------------------------------------------------
// Helpers
// ---------------------------------------------------------------------------
__device__ __forceinline__ uint32_t smem_u32(const void* p) {
    uint32_t a;
    asm("{ .reg .u64 t; cvta.to.shared.u64 t, %1; cvt.u32.u64 %0, t; }" : "=r"(a) : "l"(p));
    return a;
}
__device__ __forceinline__ void ldsm4(uint32_t* r, uint32_t addr) {
    asm volatile("ldmatrix.sync.aligned.m8n8.x4.shared.b16 {%0,%1,%2,%3}, [%4];"
                 : "=r"(r[0]), "=r"(r[1]), "=r"(r[2]), "=r"(r[3]) : "r"(addr));
}
__device__ __forceinline__ void ldsm4t(uint32_t* r, uint32_t addr) {
    asm volatile("ldmatrix.sync.aligned.m8n8.x4.trans.shared.b16 {%0,%1,%2,%3}, [%4];"
                 : "=r"(r[0]), "=r"(r[1]), "=r"(r[2]), "=r"(r[3]) : "r"(addr));
}
// fp32-accumulator HMMA
__device__ __forceinline__ void mma16816(float* c, const uint32_t* a, uint32_t b0, uint32_t b1) {
    asm volatile("mma.sync.aligned.m16n8k16.row.col.f32.f16.f16.f32 "
                 "{%0,%1,%2,%3}, {%4,%5,%6,%7}, {%8,%9}, {%0,%1,%2,%3};"
                 : "+f"(c[0]), "+f"(c[1]), "+f"(c[2]), "+f"(c[3])
                 : "r"(a[0]), "r"(a[1]), "r"(a[2]), "r"(a[3]), "r"(b0), "r"(b1));
}
// fp16-accumulator HMMA (D = 2 regs: d0 = row r cols {2j,2j+1}, d1 = row r+8)
__device__ __forceinline__ void mma16816h(uint32_t* d, const uint32_t* a, uint32_t b0, uint32_t b1) {
    asm volatile("mma.sync.aligned.m16n8k16.row.col.f16.f16.f16.f16 "
                 "{%0,%1}, {%2,%3,%4,%5}, {%6,%7}, {%0,%1};"
                 : "+r"(d[0]), "+r"(d[1])
                 : "r"(a[0]), "r"(a[1]), "r"(a[2]), "r"(a[3]), "r"(b0), "r"(b1));
}
__device__ __forceinline__ uint32_t packh(float a, float b) {
    uint32_t r;
    asm("cvt.rn.f16x2.f32 %0, %1, %2;" : "=r"(r) : "f"(b), "f"(a));
    return r;
}
__device__ __forceinline__ float fexp2(float x) {
    float r;
    asm("ex2.approx.f32 %0, %1;" : "=f"(r) : "f"(x));
    return r;
}
__device__ __forceinline__ uint32_t h2exp2(uint32_t x) {
    uint32_t r;
    asm("ex2.approx.f16x2 %0, %1;" : "=r"(r) : "r"(x));
    return r;
}
__device__ __forceinline__ uint32_t h2max(uint32_t a, uint32_t b) {
    uint32_t r;
    asm("max.f16x2 %0, %1, %2;" : "=r"(r) : "r"(a), "r"(b));
    return r;
}
__device__ __forceinline__ uint32_t h2sub(uint32_t a, uint32_t b) {
    uint32_t r;
    asm("sub.f16x2 %0, %1, %2;" : "=r"(r) : "r"(a), "r"(b));
    return r;
}

#define QSCALE 0.1803368801111137f   // 0.125 * log2(e)
#define ONES_H2 0x3C003C00u          // fp16x2 {1.0, 1.0}

// ---------------------------------------------------------------------------
// Merged fp32 -> fp16 convert for x, qkv_w, proj_w
// ---------------------------------------------------------------------------
#define NX4  (M_ * C_ / 4)
#define NW14 (K3_ * C_ / 4)
#define NW24 (C_ * C_ / 4)

__global__ __launch_bounds__(256) void cvt_all(const float4* __restrict__ x,
                                               const float4* __restrict__ w1,
                                               const float4* __restrict__ w2,
                                               uint2* __restrict__ xh,
                                               uint2* __restrict__ w1h,
                                               uint2* __restrict__ w2h)
{
    int i = blockIdx.x * 256 + threadIdx.x;
    const float4* s;
    uint2* d;
    if (i < NX4)              { s = x + i;                 d = xh + i; }
    else if (i < NX4 + NW14)  { s = w1 + (i - NX4);        d = w1h + (i - NX4); }
    else                      { s = w2 + (i - NX4 - NW14); d = w2h + (i - NX4 - NW14); }
    float4 v = *s;
    *d = make_uint2(packh(v.x, v.y), packh(v.z, v.w));
}

// ---------------------------------------------------------------------------
// RoPE tables
// ---------------------------------------------------------------------------
__global__ __launch_bounds__(256) void rope_table()
{
    int idx = blockIdx.x * 256 + threadIdx.x;          // 32768
    int pos = idx >> 5, lane = idx & 31;
    float e = (float)(2 * lane) * (1.0f / 64.0f);
    float inv = expf(-9.210340371976184f * e);
    float ang = (float)pos * inv;
    g_cos[idx] = cosf(ang);
    g_sin[idx] = sinf(ang);
}

// ---------------------------------------------------------------------------
// Shared GEMM config (block 128x128, K=1024, chunk 32, 8 warps 4x2)
// ---------------------------------------------------------------------------
#define STAGE_B 20480
#define GEMM_SMEM (3 * STAGE_B)   // 61440

// ---------------------------------------------------------------------------
// QKV GEMM (single-pass fp16) with FUSED RMSNorm + RoPE + fp16 emit.
// ---------------------------------------------------------------------------
__global__ __launch_bounds__(256, 2) void gemm_qkv_fused(
    const __half* __restrict__ Ah, const __half* __restrict__ Bh,
    const float* __restrict__ bias,
    const float* __restrict__ qn_w, const float* __restrict__ kn_w)
{
    extern __shared__ char sm[];
    const uint32_t sbase = smem_u32(sm);
    const int tid = threadIdx.x;
    const int lane = tid & 31;
    const int wid = tid >> 5;
    const int warp_m = wid >> 1;
    const int warp_n = wid & 1;
    const int row0 = blockIdx.y * 128;
    const int col0 = blockIdx.x * 128;

    float acc[2][8][4];
#pragma unroll
    for (int a = 0; a < 2; a++)
#pragma unroll
        for (int b = 0; b < 8; b++)
#pragma unroll
            for (int c = 0; c < 4; c++) acc[a][b][c] = 0.0f;

    const __half* srcs[2] = { Ah + (size_t)row0 * 1024, Bh + (size_t)col0 * 1024 };

    auto load_stage = [&](int c, int buf) {
#pragma unroll
        for (int i = 0; i < 4; i++) {
            int lin = tid + i * 256;
            int mat = lin >> 9;
            int rem = lin & 511;
            int row = rem >> 2;
            int ch = rem & 3;
            const __half* s = srcs[mat] + (size_t)row * 1024 + c * 32 + ch * 8;
            uint32_t d = sbase + buf * STAGE_B + mat * 10240 + (uint32_t)(row * 40 + ch * 8) * 2;
            asm volatile("cp.async.cg.shared.global [%0], [%1], 16;" :: "r"(d), "l"(s));
        }
        asm volatile("cp.async.commit_group;");
    };

    load_stage(0, 0);
    load_stage(1, 1);
    for (int c = 0; c < 32; c++) {
        const int buf = c % 3;
        if (c + 2 < 32) { load_stage(c + 2, (c + 2) % 3); asm volatile("cp.async.wait_group 2;"); }
        else if (c + 1 < 32) { asm volatile("cp.async.wait_group 1;"); }
        else { asm volatile("cp.async.wait_group 0;"); }
        __syncthreads();
        const uint32_t base = sbase + buf * STAGE_B;
#pragma unroll
        for (int kk = 0; kk < 2; kk++) {
            uint32_t ah[2][4], bh[4][4];
            int arow = warp_m * 32 + (lane & 15);
            int acol = kk * 16 + (lane >> 4) * 8;
            uint32_t aoff = (uint32_t)(arow * 40 + acol) * 2;
            ldsm4(ah[0], base + aoff);
            ldsm4(ah[1], base + aoff + 1280);
            int g = lane >> 3, l7 = lane & 7;
#pragma unroll
            for (int p = 0; p < 4; p++) {
                int brow = warp_n * 64 + (p * 2 + (g >> 1)) * 8 + l7;
                int bcol = kk * 16 + (g & 1) * 8;
                ldsm4(bh[p], base + 10240 + (uint32_t)(brow * 40 + bcol) * 2);
            }
#pragma unroll
            for (int tm = 0; tm < 2; tm++)
#pragma unroll
                for (int tn = 0; tn < 8; tn++)
                    mma16816(acc[tm][tn], ah[tm],
                             bh[tn >> 1][(tn & 1) * 2], bh[tn >> 1][(tn & 1) * 2 + 1]);
        }
        __syncthreads();
    }

    // ---- fused epilogue ----
    const int sec = col0 >> 10;                         // 0=q, 1=k, 2=v
    const int head = ((col0 & 1023) >> 6) + warp_n;
    const int d0 = (lane & 3) * 2;

    float bs[8][2], wv[8][2];
    const float* w = (sec == 1) ? kn_w : qn_w;
#pragma unroll
    for (int tn = 0; tn < 8; tn++) {
        int d = tn * 8 + d0;
        int col = col0 + warp_n * 64 + d;
        bs[tn][0] = __ldg(&bias[col]);
        bs[tn][1] = __ldg(&bias[col + 1]);
        if (sec < 2) { wv[tn][0] = __ldg(&w[d]); wv[tn][1] = __ldg(&w[d + 1]); }
    }

    auto process_row = [&](float v[8][2], int m) {
        const int n = m & 2047;
        const int bb = m >> 11;
        const size_t obase = (((size_t)(bb * 16 + head)) * 2048 + n) * 64;
        if (sec == 2) {
#pragma unroll
            for (int tn = 0; tn < 8; tn++)
                *reinterpret_cast<uint32_t*>(&g_v[obase + tn * 8 + d0]) = packh(v[tn][0], v[tn][1]);
            return;
        }
        float ss = 0.0f;
#pragma unroll
        for (int tn = 0; tn < 8; tn++) ss += v[tn][0] * v[tn][0] + v[tn][1] * v[tn][1];
        ss += __shfl_xor_sync(0xffffffffu, ss, 1);
        ss += __shfl_xor_sync(0xffffffffu, ss, 2);
        float rs = rsqrtf(ss * (1.0f / 64.0f) + 1e-6f);
#pragma unroll
        for (int tn = 0; tn < 8; tn++) {
            v[tn][0] *= rs * wv[tn][0];
            v[tn][1] *= rs * wv[tn][1];
        }
        int pos = (n < 1024) ? n : ((n < 1536) ? (n - 1024) : -1);
        if (pos >= 0) {
#pragma unroll
            for (int tn = 0; tn < 4; tn++) {
                int idx = pos * 32 + tn * 8 + d0;
#pragma unroll
                for (int j = 0; j < 2; j++) {
                    float cs = g_cos[idx + j], sn = g_sin[idx + j];
                    float t1 = v[tn][j], t2 = v[tn + 4][j];
                    v[tn][j]     = t1 * cs - t2 * sn;
                    v[tn + 4][j] = t2 * cs + t1 * sn;
                }
            }
        }
        if (sec == 0) {
#pragma unroll
            for (int tn = 0; tn < 8; tn++)
                *reinterpret_cast<uint32_t*>(&g_q[obase + tn * 8 + d0]) =
                    packh(v[tn][0] * QSCALE, v[tn][1] * QSCALE);
        } else {
#pragma unroll
            for (int tn = 0; tn < 8; tn++)
                *reinterpret_cast<uint32_t*>(&g_k[obase + tn * 8 + d0]) = packh(v[tn][0], v[tn][1]);
        }
    };

#pragma unroll
    for (int tm = 0; tm < 2; tm++) {
        const int mA = row0 + warp_m * 32 + tm * 16 + (lane >> 2);
        float vA[8][2], vB[8][2];
#pragma unroll
        for (int tn = 0; tn < 8; tn++) {
            vA[tn][0] = acc[tm][tn][0] + bs[tn][0];
            vA[tn][1] = acc[tm][tn][1] + bs[tn][1];
            vB[tn][0] = acc[tm][tn][2] + bs[tn][0];
            vB[tn][1] = acc[tm][tn][3] + bs[tn][1];
        }
        process_row(vA, mA);
        process_row(vB, mA + 8);
    }
}

// ---------------------------------------------------------------------------
// Generic single-pass fp16 GEMM (proj): out = A.B^T + bias
// ---------------------------------------------------------------------------
__global__ __launch_bounds__(256, 2) void gemm_mma(
    const __half* __restrict__ Ah, const __half* __restrict__ Bh,
    const float* __restrict__ bias, float* __restrict__ out, int ostride)
{
    extern __shared__ char sm[];
    const uint32_t sbase = smem_u32(sm);
    const int tid = threadIdx.x;
    const int lane = tid & 31;
    const int wid = tid >> 5;
    const int warp_m = wid >> 1;
    const int warp_n = wid & 1;
    const int row0 = blockIdx.y * 128;
    const int col0 = blockIdx.x * 128;

    float acc[2][8][4];
#pragma unroll
    for (int a = 0; a < 2; a++)
#pragma unroll
        for (int b = 0; b < 8; b++)
#pragma unroll
            for (int c = 0; c < 4; c++) acc[a][b][c] = 0.0f;

    const __half* srcs[2] = { Ah + (size_t)row0 * 1024, Bh + (size_t)col0 * 1024 };

    auto load_stage = [&](int c, int buf) {
#pragma unroll
        for (int i = 0; i < 4; i++) {
            int lin = tid + i * 256;
            int mat = lin >> 9;
            int rem = lin & 511;
            int row = rem >> 2;
            int ch = rem & 3;
            const __half* s = srcs[mat] + (size_t)row * 1024 + c * 32 + ch * 8;
            uint32_t d = sbase + buf * STAGE_B + mat * 10240 + (uint32_t)(row * 40 + ch * 8) * 2;
            asm volatile("cp.async.cg.shared.global [%0], [%1], 16;" :: "r"(d), "l"(s));
        }
        asm volatile("cp.async.commit_group;");
    };

    load_stage(0, 0);
    load_stage(1, 1);
    for (int c = 0; c < 32; c++) {
        const int buf = c % 3;
        if (c + 2 < 32) { load_stage(c + 2, (c + 2) % 3); asm volatile("cp.async.wait_group 2;"); }
        else if (c + 1 < 32) { asm volatile("cp.async.wait_group 1;"); }
        else { asm volatile("cp.async.wait_group 0;"); }
        __syncthreads();
        const uint32_t base = sbase + buf * STAGE_B;
#pragma unroll
        for (int kk = 0; kk < 2; kk++) {
            uint32_t ah[2][4], bh[4][4];
            int arow = warp_m * 32 + (lane & 15);
            int acol = kk * 16 + (lane >> 4) * 8;
            uint32_t aoff = (uint32_t)(arow * 40 + acol) * 2;
            ldsm4(ah[0], base + aoff);
            ldsm4(ah[1], base + aoff + 1280);
            int g = lane >> 3, l7 = lane & 7;
#pragma unroll
            for (int p = 0; p < 4; p++) {
                int brow = warp_n * 64 + (p * 2 + (g >> 1)) * 8 + l7;
                int bcol = kk * 16 + (g & 1) * 8;
                ldsm4(bh[p], base + 10240 + (uint32_t)(brow * 40 + bcol) * 2);
            }
#pragma unroll
            for (int tm = 0; tm < 2; tm++)
#pragma unroll
                for (int tn = 0; tn < 8; tn++)
                    mma16816(acc[tm][tn], ah[tm],
                             bh[tn >> 1][(tn & 1) * 2], bh[tn >> 1][(tn & 1) * 2 + 1]);
        }
        __syncthreads();
    }

#pragma unroll
    for (int tm = 0; tm < 2; tm++) {
        int mb = row0 + warp_m * 32 + tm * 16 + (lane >> 2);
#pragma unroll
        for (int tn = 0; tn < 8; tn++) {
            int col = col0 + warp_n * 64 + tn * 8 + (lane & 3) * 2;
            float b0 = __ldg(&bias[col]), b1 = __ldg(&bias[col + 1]);
            *reinterpret_cast<float2*>(&out[(size_t)mb * ostride + col]) =
                make_float2(acc[tm][tn][0] + b0, acc[tm][tn][1] + b1);
            *reinterpret_cast<float2*>(&out[(size_t)(mb + 8) * ostride + col]) =
                make_float2(acc[tm][tn][2] + b0, acc[tm][tn][3] + b1);
        }
    }
}

// ---------------------------------------------------------------------------
// Flash attention: 256 q/CTA, warp = 32 rows; 128-key tiles as two 64-key
// sub-tiles. QK^T uses fp16 accumulators (2x HMMA rate if f32-acc is
// half-rate); softmax entirely in f16x2 (max/sub/ex2); PV + rowsum f32-acc.
// ---------------------------------------------------------------------------
#define RS   144
#define KVB  36864                // per buffer: K 128x144 + V 128x144
#define OVV  18432                // V offset within buffer
#define ATTN_SMEM (2 * KVB)       // 73728

__global__ __launch_bounds__(256, 1) void attn_mma()
{
    extern __shared__ char sm[];
    const uint32_t sbase = smem_u32(sm);
    const int tid = threadIdx.x;
    const int lane = tid & 31;
    const int wid = tid >> 5;
    const int q0 = blockIdx.x * 256;
    const int h = blockIdx.y;
    const int b = blockIdx.z;
    const size_t hb = ((size_t)(b * 16 + h)) * 2048 * 64;

    const __half* q_g = g_q + hb + (size_t)q0 * 64;
    const __half* k_g = g_k + hb;
    const __half* v_g = g_v + hb;

    // ---- stage Q (256 rows) through buffer region, hoist ----
    {
#pragma unroll
        for (int i = 0; i < 8; i++) {
            int lin = tid + i * 256;          // 0..2047 (256 rows x 8 chunks)
            int row = lin >> 3;
            int ch = lin & 7;
            const __half* s = q_g + (size_t)row * 64 + ch * 8;
            uint32_t d = sbase + (uint32_t)(row * RS + ch * 16);
            asm volatile("cp.async.cg.shared.global [%0], [%1], 16;" :: "r"(d), "l"(s));
        }
        asm volatile("cp.async.commit_group;");
        asm volatile("cp.async.wait_group 0;");
        __syncthreads();
    }

    uint32_t aq[2][4][4];
    {
        const int acolb = (lane >> 4) * 16;
#pragma unroll
        for (int blk = 0; blk < 2; blk++) {
            const int arow = wid * 32 + blk * 16 + (lane & 15);
#pragma unroll
            for (int kc = 0; kc < 4; kc++)
                ldsm4(aq[blk][kc], sbase + (uint32_t)(arow * RS + kc * 32 + acolb));
        }
    }
    __syncthreads();   // all warps hoisted before KV overwrites Q

    // loads a 128-key tile (K 128 rows + V 128 rows)
    auto load_kv = [&](int t, int buf) {
        const uint32_t dbase = sbase + buf * KVB;
#pragma unroll
        for (int i = 0; i < 8; i++) {
            int lin = tid + i * 256;          // 0..2047
            int mat = lin >> 10;              // 0=K, 1=V
            int rem = lin & 1023;
            int row = rem >> 3;
            int ch = rem & 7;
            const __half* s = (mat ? v_g : k_g) + (size_t)t * 128 * 64 + (size_t)row * 64 + ch * 8;
            uint32_t d = dbase + mat * OVV + (uint32_t)(row * RS + ch * 16);
            asm volatile("cp.async.cg.shared.global [%0], [%1], 16;" :: "r"(d), "l"(s));
        }
        asm volatile("cp.async.commit_group;");
    };

    load_kv(0, 0);
    load_kv(1, 1);
    asm volatile("cp.async.wait_group 1;");
    __syncthreads();

    float mrow[2][2], lrow[2][2];
    float o[2][8][4];
#pragma unroll
    for (int blk = 0; blk < 2; blk++) {
        mrow[blk][0] = -30000.0f; mrow[blk][1] = -30000.0f;
        lrow[blk][0] = 0.0f;      lrow[blk][1] = 0.0f;
#pragma unroll
        for (int nd = 0; nd < 8; nd++)
#pragma unroll
            for (int j = 0; j < 4; j++) o[blk][nd][j] = 0.0f;
    }

    const int g = lane >> 3, l7 = lane & 7;

    for (int t = 0; t < 16; t++) {
        const uint32_t kbuf = sbase + (t & 1) * KVB;

#pragma unroll
        for (int sub = 0; sub < 2; sub++) {
            const uint32_t koff = kbuf + (uint32_t)(sub * 64 * RS);
            const uint32_t voff = kbuf + OVV + (uint32_t)(sub * 64 * RS);

            // ---- S = Q K^T in fp16 accumulators ----
            // d[blk][tn][0] = row r cols {2j,2j+1}; d[blk][tn][1] = row r+8
            uint32_t d[2][8][2];
#pragma unroll
            for (int blk = 0; blk < 2; blk++)
#pragma unroll
                for (int tn = 0; tn < 8; tn++) { d[blk][tn][0] = 0u; d[blk][tn][1] = 0u; }

#pragma unroll
            for (int kc = 0; kc < 4; kc++) {
                uint32_t bh[4][4];
#pragma unroll
                for (int p = 0; p < 4; p++) {
                    int brow = (p * 2 + (g >> 1)) * 8 + l7;
                    int bcolb = kc * 32 + (g & 1) * 16;
                    ldsm4(bh[p], koff + (uint32_t)(brow * RS + bcolb));
                }
#pragma unroll
                for (int blk = 0; blk < 2; blk++)
#pragma unroll
                    for (int tn = 0; tn < 8; tn++)
                        mma16816h(d[blk][tn], aq[blk][kc],
                                  bh[tn >> 1][(tn & 1) * 2], bh[tn >> 1][(tn & 1) * 2 + 1]);
            }

            // ---- online softmax in f16x2 domain ----
            float al[2][2];
            uint32_t mn2[2][2];
#pragma unroll
            for (int blk = 0; blk < 2; blk++) {
                uint32_t m20 = d[blk][0][0], m21 = d[blk][0][1];
#pragma unroll
                for (int tn = 1; tn < 8; tn++) {
                    m20 = h2max(m20, d[blk][tn][0]);
                    m21 = h2max(m21, d[blk][tn][1]);
                }
                m20 = h2max(m20, __shfl_xor_sync(0xffffffffu, m20, 1));
                m20 = h2max(m20, __shfl_xor_sync(0xffffffffu, m20, 2));
                m21 = h2max(m21, __shfl_xor_sync(0xffffffffu, m21, 1));
                m21 = h2max(m21, __shfl_xor_sync(0xffffffffu, m21, 2));
                __half2 h0 = *reinterpret_cast<__half2*>(&m20);
                __half2 h1 = *reinterpret_cast<__half2*>(&m21);
                float mx0 = fmaxf(__low2float(h0), __high2float(h0));
                float mx1 = fmaxf(__low2float(h1), __high2float(h1));
                float mn0 = fmaxf(mrow[blk][0], mx0);
                float mn1 = fmaxf(mrow[blk][1], mx1);
                al[blk][0] = fexp2(mrow[blk][0] - mn0);
                al[blk][1] = fexp2(mrow[blk][1] - mn1);
                mrow[blk][0] = mn0; mrow[blk][1] = mn1;
                mn2[blk][0] = packh(mn0, mn0);
                mn2[blk][1] = packh(mn1, mn1);
#pragma unroll
                for (int nd = 0; nd < 8; nd++) {
                    o[blk][nd][0] *= al[blk][0]; o[blk][nd][1] *= al[blk][0];
                    o[blk][nd][2] *= al[blk][1]; o[blk][nd][3] *= al[blk][1];
                }
            }

            // ---- per-kc: exp2 (f16x2) -> P frags, rowsum MMA, PV MMA ----
            float sac[2][4] = {{0.0f, 0.0f, 0.0f, 0.0f}, {0.0f, 0.0f, 0.0f, 0.0f}};
#pragma unroll
            for (int kc = 0; kc < 4; kc++) {
                uint32_t p[2][4];
#pragma unroll
                for (int blk = 0; blk < 2; blk++) {
                    p[blk][0] = h2exp2(h2sub(d[blk][2 * kc][0],     mn2[blk][0]));
                    p[blk][1] = h2exp2(h2sub(d[blk][2 * kc][1],     mn2[blk][1]));
                    p[blk][2] = h2exp2(h2sub(d[blk][2 * kc + 1][0], mn2[blk][0]));
                    p[blk][3] = h2exp2(h2sub(d[blk][2 * kc + 1][1], mn2[blk][1]));
                    mma16816(sac[blk], p[blk], ONES_H2, ONES_H2);
                }
#pragma unroll
                for (int dp = 0; dp < 4; dp++) {
                    int vrow = kc * 16 + (g & 1) * 8 + l7;
                    int vcolb = dp * 32 + (g >> 1) * 16;
                    uint32_t vh[4];
                    ldsm4t(vh, voff + (uint32_t)(vrow * RS + vcolb));
#pragma unroll
                    for (int blk = 0; blk < 2; blk++) {
                        mma16816(o[blk][dp * 2],     p[blk], vh[0], vh[1]);
                        mma16816(o[blk][dp * 2 + 1], p[blk], vh[2], vh[3]);
                    }
                }
            }
#pragma unroll
            for (int blk = 0; blk < 2; blk++) {
                lrow[blk][0] = lrow[blk][0] * al[blk][0] + sac[blk][0];
                lrow[blk][1] = lrow[blk][1] * al[blk][1] + sac[blk][2];
            }
        }

        __syncthreads();
        if (t + 2 < 16) load_kv(t + 2, t & 1);
        if (t + 1 < 16) {
            if (t + 2 < 16) { asm volatile("cp.async.wait_group 1;"); }
            else            { asm volatile("cp.async.wait_group 0;"); }
            __syncthreads();
        }
    }

    // ---- epilogue: normalize + single fp16 into [M,1024] ----
    const int colb = h * 64 + (lane & 3) * 2;
#pragma unroll
    for (int blk = 0; blk < 2; blk++) {
        const float inv0 = 1.0f / lrow[blk][0], inv1 = 1.0f / lrow[blk][1];
        const int r0 = q0 + wid * 32 + blk * 16 + (lane >> 2);
        const size_t m0i = (size_t)(b * 2048) + r0;
#pragma unroll
        for (int nd = 0; nd < 8; nd++) {
            *reinterpret_cast<uint32_t*>(&g_a[m0i * 1024 + colb + nd * 8]) =
                packh(o[blk][nd][0] * inv0, o[blk][nd][1] * inv0);
            *reinterpret_cast<uint32_t*>(&g_a[(m0i + 8) * 1024 + colb + nd * 8]) =
                packh(o[blk][nd][2] * inv1, o[blk][nd][3] * inv1);
        }
    }
}

// ---------------------------------------------------------------------------
// Launch
// ---------------------------------------------------------------------------
extern "C" void kernel_launch(void* const* d_in, const int* in_sizes, int n_in,
                              void* d_out, int out_size)
{
    const float* x      = (const float*)d_in[0];
    const float* qkv_w  = (const float*)d_in[1];
    const float* qkv_b  = (const float*)d_in[2];
    const float* qn_w   = (const float*)d_in[3];
    const float* kn_w   = (const float*)d_in[4];
    const float* proj_w = (const float*)d_in[5];
    const float* proj_b = (const float*)d_in[6];
    float* out = (float*)d_out;

    cudaFuncSetAttribute(gemm_qkv_fused, cudaFuncAttributeMaxDynamicSharedMemorySize, GEMM_SMEM);
    cudaFuncSetAttribute(gemm_mma, cudaFuncAttributeMaxDynamicSharedMemorySize, GEMM_SMEM);
    cudaFuncSetAttribute(attn_mma, cudaFuncAttributeMaxDynamicSharedMemorySize, ATTN_SMEM);

    void *p_xh, *p_w1h, *p_w2h, *p_a;
    cudaGetSymbolAddress(&p_xh, g_xh);
    cudaGetSymbolAddress(&p_w1h, g_w1h);
    cudaGetSymbolAddress(&p_w2h, g_w2h);
    cudaGetSymbolAddress(&p_a, g_a);

    rope_table<<<128, 256>>>();

    cvt_all<<<(NX4 + NW14 + NW24 + 255) / 256, 256>>>(
        (const float4*)x, (const float4*)qkv_w, (const float4*)proj_w,
        (uint2*)p_xh, (uint2*)p_w1h, (uint2*)p_w2h);

    // 1. QKV projection + fused RMSNorm/RoPE/fp16 emit (head-major q/k/v)
    gemm_qkv_fused<<<dim3(K3_ / 128, M_ / 128), 256, GEMM_SMEM>>>(
        (const __half*)p_xh, (const __half*)p_w1h, qkv_b, qn_w, kn_w);

    // 2. Tensor-core flash attention (fp16-acc QK^T) -> g_a
    attn_mma<<<dim3(N_ / 256, H_, B_), 256, ATTN_SMEM>>>();

    // 3. Output projection -> d_out
    gemm_mma<<<dim3(C_ / 128, M_ / 128), 256, GEMM_SMEM>>>(
        (const __half*)p_a, (const __half*)p_w2h, proj_b, out, C_);
}